// round 2
// baseline (speedup 1.0000x reference)
#include <cuda_runtime.h>

#define B_   16
#define CH_  64
#define H_   128
#define W_   128
#define TOK  16384           // H_*W_
#define CNT  (16.0f*16384.0f) // B_*TOK (batchnorm count)

// ---------------- device scratch (static globals: allocation-free) -------------
__device__ float g_XT[B_*TOK*CH_];      // residual stream, BHWC
__device__ float g_V [B_*TOK*CH_];      // v projection / reused post-transformer
__device__ float g_P [B_*TOK*CH_];      // depthwise conv output
__device__ float g_C    [B_*64*64];     // per-batch gram of XT
__device__ float g_Weff [B_*64*64];     // attn folded into proj
__device__ float g_stats[256];          // [sum1|sumsq1|sum2|sumsq2] per channel
__device__ float g_pooled[B_*64*64];    // 8x8 pooled sums per (b,c)
__device__ float g_minmax[2];
__device__ float g_gate[B_*64];

__device__ __forceinline__ float leaky(float x){ return x >= 0.f ? x : 0.2f*x; }

// acc[64] += xc * wrow[0..63]  (wrow smem, 16B aligned)
__device__ __forceinline__ void mm_acc(float* acc, float xc, const float* wrow){
  const float4* w4 = (const float4*)wrow;
#pragma unroll
  for (int o4 = 0; o4 < 16; o4++){
    float4 w = w4[o4];
    acc[4*o4+0] = fmaf(xc, w.x, acc[4*o4+0]);
    acc[4*o4+1] = fmaf(xc, w.y, acc[4*o4+1]);
    acc[4*o4+2] = fmaf(xc, w.z, acc[4*o4+2]);
    acc[4*o4+3] = fmaf(xc, w.w, acc[4*o4+3]);
  }
}

// ---------------- kernel: NCHW -> BHWC transpose of input ----------------------
__global__ void k_transpose_in(const float* __restrict__ x){
  int b = blockIdx.x, n0 = blockIdx.y * 64;
  __shared__ float s[64*65];
  const float* xb = x + (size_t)b*CH_*TOK;
  for (int idx = threadIdx.x; idx < 4096; idx += 256){
    int c = idx >> 6, j = idx & 63;
    s[c*65 + j] = xb[(size_t)c*TOK + n0 + j];
  }
  __syncthreads();
  float* xt = g_XT + ((size_t)b*TOK + n0)*CH_;
  for (int idx = threadIdx.x; idx < 4096; idx += 256){
    int j = idx >> 6, c = idx & 63;
    xt[j*CH_ + c] = s[c*65 + j];
  }
}

// ---------------- kernel: V = XT @ wv, plus partial gram C = XT^T XT -----------
__global__ void k_v_gram(const float* __restrict__ wv){
  extern __shared__ float sm[];
  float* xs = sm;          // 256*65
  float* ws = sm + 16640;  // 4096
  int b = blockIdx.x, n0 = blockIdx.y * 256;
  const float* xt = g_XT + ((size_t)b*TOK + n0)*CH_;
  for (int idx = threadIdx.x; idx < 16384; idx += 256){
    int t = idx >> 6, c = idx & 63;
    xs[t*65 + c] = xt[idx];
  }
  for (int idx = threadIdx.x; idx < 4096; idx += 256) ws[idx] = wv[idx];
  __syncthreads();

  // V: one token per thread
  int t = threadIdx.x;
  float acc[64];
#pragma unroll
  for (int o = 0; o < 64; o++) acc[o] = 0.f;
  const float* row = &xs[t*65];
#pragma unroll 4
  for (int c = 0; c < 64; c++) mm_acc(acc, row[c], &ws[c*64]);
  float4* vout = (float4*)(g_V + ((size_t)b*TOK + n0 + t)*CH_);
#pragma unroll
  for (int o4 = 0; o4 < 16; o4++)
    vout[o4] = make_float4(acc[4*o4], acc[4*o4+1], acc[4*o4+2], acc[4*o4+3]);

  // partial gram: thread -> 4x4 tile of C (stride-16 layout)
  int a = threadIdx.x >> 4, bb = threadIdx.x & 15;
  float g[16];
#pragma unroll
  for (int i = 0; i < 16; i++) g[i] = 0.f;
  for (int tt = 0; tt < 256; tt++){
    const float* r = &xs[tt*65];
    float x1[4], x2[4];
#pragma unroll
    for (int k = 0; k < 4; k++){ x1[k] = r[a + 16*k]; x2[k] = r[bb + 16*k]; }
#pragma unroll
    for (int i = 0; i < 4; i++)
#pragma unroll
      for (int j = 0; j < 4; j++) g[i*4+j] = fmaf(x1[i], x2[j], g[i*4+j]);
  }
  float* Cb = g_C + b*4096;
#pragma unroll
  for (int i = 0; i < 4; i++)
#pragma unroll
    for (int j = 0; j < 4; j++)
      atomicAdd(&Cb[(a + 16*i)*64 + (bb + 16*j)], g[i*4+j]);
}

// ------- kernel: per-batch attention stats + fold into Weff (tiny, 16 blocks) ---
__global__ void k_attn_weff(const float* __restrict__ wq, const float* __restrict__ wk,
                            const float* __restrict__ wproj){
  extern __shared__ float sm[];
  float* Cs  = sm;            // 4096
  float* wqs = sm + 4096;
  float* wks = sm + 8192;
  float* wps = sm + 12288;
  float* T1  = sm + 16384;    // C @ wq
  float* T2  = sm + 20480;    // C @ wk
  __shared__ float attn_s[512];  // [h*8+dd][e]
  __shared__ float qq[64], kk[64];
  int b = blockIdx.x;
  for (int i = threadIdx.x; i < 4096; i += 256){
    Cs[i]  = g_C[b*4096 + i];
    wqs[i] = wq[i]; wks[i] = wk[i]; wps[i] = wproj[i];
  }
  __syncthreads();
  for (int i = threadIdx.x; i < 4096; i += 256){
    int r = i >> 6, e = i & 63; float s1 = 0.f, s2 = 0.f;
    for (int c = 0; c < 64; c++){
      float cv = Cs[r*64 + c];
      s1 = fmaf(cv, wqs[c*64 + e], s1);
      s2 = fmaf(cv, wks[c*64 + e], s2);
    }
    T1[i] = s1; T2[i] = s2;
  }
  __syncthreads();
  if (threadIdx.x < 64){
    int e = threadIdx.x; float s1 = 0.f, s2 = 0.f;
    for (int c = 0; c < 64; c++){
      s1 = fmaf(wqs[c*64 + e], T1[c*64 + e], s1);
      s2 = fmaf(wks[c*64 + e], T2[c*64 + e], s2);
    }
    qq[e] = s1; kk[e] = s2;
  }
  __syncthreads();
  if (threadIdx.x < 64){
    int h = threadIdx.x >> 3, dd = threadIdx.x & 7;
    float nk = fmaxf(sqrtf(kk[h*8 + dd]), 1e-12f);
    float lo[8]; float mx = -3.4e38f;
#pragma unroll
    for (int e = 0; e < 8; e++){
      float gg = 0.f;
      for (int c = 0; c < 64; c++)
        gg = fmaf(wks[c*64 + h*8 + dd], T1[c*64 + h*8 + e], gg);
      float nq = fmaxf(sqrtf(qq[h*8 + e]), 1e-12f);
      lo[e] = gg / (nk * nq);
      mx = fmaxf(mx, lo[e]);
    }
    float sum = 0.f;
#pragma unroll
    for (int e = 0; e < 8; e++){ lo[e] = expf(lo[e] - mx); sum += lo[e]; }
    float inv = 1.f / sum;
#pragma unroll
    for (int e = 0; e < 8; e++) attn_s[(h*8 + dd)*8 + e] = lo[e] * inv;
  }
  __syncthreads();
  // Weff[h*8+e][oc] = sum_dd attn[h,dd,e] * wproj[h*8+dd][oc]
  for (int i = threadIdx.x; i < 4096; i += 256){
    int cin = i >> 6, oc = i & 63;
    int h = cin >> 3, e = cin & 7;
    float s = 0.f;
#pragma unroll
    for (int dd = 0; dd < 8; dd++)
      s = fmaf(attn_s[(h*8 + dd)*8 + e], wps[(h*8 + dd)*64 + oc], s);
    g_Weff[b*4096 + i] = s;
  }
}

// ---------------- kernel: depthwise 3x3 on V -> P (BHWC) -----------------------
__global__ void k_dwconv(const float* __restrict__ wpos){
  int bh = blockIdx.x; int b = bh >> 7; int y = bh & 127;
  int cg = threadIdx.x & 15;
  int x  = blockIdx.y * 16 + (threadIdx.x >> 4);
  __shared__ float wp[576];
  for (int i = threadIdx.x; i < 576; i += 256) wp[i] = wpos[i];
  __syncthreads();
  float a0 = 0.f, a1 = 0.f, a2 = 0.f, a3 = 0.f;
  const float* Vb = g_V + (size_t)b*TOK*CH_;
#pragma unroll
  for (int ky = 0; ky < 3; ky++){
    int yy = y + ky - 1; if (yy < 0 || yy > 127) continue;
#pragma unroll
    for (int kx = 0; kx < 3; kx++){
      int xx = x + kx - 1; if (xx < 0 || xx > 127) continue;
      float4 v = *(const float4*)&Vb[((size_t)yy*128 + xx)*64 + cg*4];
      int wi = ky*3 + kx;
      a0 = fmaf(v.x, wp[(cg*4+0)*9 + wi], a0);
      a1 = fmaf(v.y, wp[(cg*4+1)*9 + wi], a1);
      a2 = fmaf(v.z, wp[(cg*4+2)*9 + wi], a2);
      a3 = fmaf(v.w, wp[(cg*4+3)*9 + wi], a3);
    }
  }
  *(float4*)&g_P[((size_t)b*TOK + y*128 + x)*64 + cg*4] = make_float4(a0,a1,a2,a3);
}

// ---------------- kernel: epilogue  XT += (V @ Weff_b + bproj) * P --------------
__global__ void k_epilogue(const float* __restrict__ bproj){
  extern __shared__ float sm[];
  float* xs = sm;           // 256*65
  float* ws = sm + 16640;   // 4096
  float* bp = ws + 4096;    // 64
  int b = blockIdx.x, n0 = blockIdx.y * 256;
  const float* V = g_V + ((size_t)b*TOK + n0)*CH_;
  for (int idx = threadIdx.x; idx < 16384; idx += 256){
    int t = idx >> 6, c = idx & 63;
    xs[t*65 + c] = V[idx];
  }
  for (int idx = threadIdx.x; idx < 4096; idx += 256) ws[idx] = g_Weff[b*4096 + idx];
  if (threadIdx.x < 64) bp[threadIdx.x] = bproj[threadIdx.x];
  __syncthreads();
  int t = threadIdx.x;
  float acc[64];
#pragma unroll
  for (int o = 0; o < 64; o++) acc[o] = bp[o];
  const float* row = &xs[t*65];
#pragma unroll 4
  for (int c = 0; c < 64; c++) mm_acc(acc, row[c], &ws[c*64]);
  __syncthreads();
  float* orow = &xs[t*65];
#pragma unroll
  for (int o = 0; o < 64; o++) orow[o] = acc[o];
  __syncthreads();
  float* XT = g_XT + ((size_t)b*TOK + n0)*CH_;
  const float* P = g_P + ((size_t)b*TOK + n0)*CH_;
  for (int idx = threadIdx.x; idx < 16384; idx += 256)
    XT[idx] += xs[(idx >> 6)*65 + (idx & 63)] * P[idx];
}

// ---------------- kernel: XT += LayerNorm(XT) @ wff ----------------------------
__global__ void k_lnff(const float* __restrict__ wff, const float* __restrict__ lng,
                       const float* __restrict__ lnb){
  extern __shared__ float sm[];
  float* xs = sm;
  float* ws = sm + 16640;
  float* gs = ws + 4096;
  float* bs = gs + 64;
  int b = blockIdx.x, n0 = blockIdx.y * 256;
  float* XT = g_XT + ((size_t)b*TOK + n0)*CH_;
  for (int idx = threadIdx.x; idx < 16384; idx += 256){
    int t = idx >> 6, c = idx & 63;
    xs[t*65 + c] = XT[idx];
  }
  for (int idx = threadIdx.x; idx < 4096; idx += 256) ws[idx] = wff[idx];
  if (threadIdx.x < 64){ gs[threadIdx.x] = lng[threadIdx.x]; bs[threadIdx.x] = lnb[threadIdx.x]; }
  __syncthreads();
  int t = threadIdx.x;
  const float* row = &xs[t*65];
  float m = 0.f, v = 0.f;
#pragma unroll 4
  for (int c = 0; c < 64; c++){ float xv = row[c]; m += xv; v = fmaf(xv, xv, v); }
  m *= (1.f/64.f);
  v = v*(1.f/64.f) - m*m;
  float rstd = rsqrtf(v + 1e-5f);
  float acc[64];
#pragma unroll
  for (int o = 0; o < 64; o++) acc[o] = 0.f;
#pragma unroll 4
  for (int c = 0; c < 64; c++){
    float yn = (row[c] - m) * rstd * gs[c] + bs[c];
    mm_acc(acc, yn, &ws[c*64]);
  }
  __syncthreads();
  float* orow = &xs[t*65];
#pragma unroll
  for (int o = 0; o < 64; o++) orow[o] = acc[o];
  __syncthreads();
  for (int idx = threadIdx.x; idx < 16384; idx += 256)
    XT[idx] += xs[(idx >> 6)*65 + (idx & 63)];
}

// ------------- kernel: per-channel stats of leaky(XT) (BN1) --------------------
__global__ void k_bnstats(){
  size_t base = (size_t)blockIdx.x * 16384;
  float s = 0.f, ss = 0.f;
  for (int k = 0; k < 64; k++){
    float x = g_XT[base + k*256 + threadIdx.x];
    x = leaky(x);
    s += x; ss = fmaf(x, x, ss);
  }
  __shared__ float red[512];
  red[threadIdx.x] = s; red[256 + threadIdx.x] = ss;
  __syncthreads();
  if (threadIdx.x < 64){
    float a  = red[threadIdx.x] + red[threadIdx.x+64] + red[threadIdx.x+128] + red[threadIdx.x+192];
    float a2 = red[256+threadIdx.x] + red[320+threadIdx.x] + red[384+threadIdx.x] + red[448+threadIdx.x];
    atomicAdd(&g_stats[threadIdx.x], a);
    atomicAdd(&g_stats[64 + threadIdx.x], a2);
  }
}

// ------ kernel: r3 = BN1(leaky(XT)) @ wd -> g_V, plus stats of leaky(r3) --------
__global__ void k_bn_conv(const float* __restrict__ wd, const float* __restrict__ g1,
                          const float* __restrict__ b1){
  extern __shared__ float sm[];
  float* xs = sm;
  float* ws = sm + 16640;
  float* scale = ws + 4096;
  float* shift = scale + 64;
  __shared__ float red[512];
  int b = blockIdx.x, n0 = blockIdx.y * 256;
  if (threadIdx.x < 64){
    int c = threadIdx.x;
    float m   = g_stats[c]      * (1.f/CNT);
    float var = g_stats[64 + c] * (1.f/CNT) - m*m;
    float sc  = g1[c] * rsqrtf(var + 1e-4f);
    scale[c] = sc; shift[c] = b1[c] - m*sc;
  }
  const float* XT = g_XT + ((size_t)b*TOK + n0)*CH_;
  for (int idx = threadIdx.x; idx < 16384; idx += 256){
    int t = idx >> 6, c = idx & 63;
    xs[t*65 + c] = XT[idx];
  }
  for (int idx = threadIdx.x; idx < 4096; idx += 256) ws[idx] = wd[idx];
  __syncthreads();
  int t = threadIdx.x;
  float acc[64];
#pragma unroll
  for (int o = 0; o < 64; o++) acc[o] = 0.f;
  const float* row = &xs[t*65];
#pragma unroll 4
  for (int c = 0; c < 64; c++){
    float xv = leaky(row[c]) * scale[c] + shift[c];
    mm_acc(acc, xv, &ws[c*64]);
  }
  __syncthreads();
  float* orow = &xs[t*65];
#pragma unroll
  for (int o = 0; o < 64; o++) orow[o] = acc[o];
  __syncthreads();
  float* Vo = g_V + ((size_t)b*TOK + n0)*CH_;
  float s = 0.f, ss = 0.f;
  for (int idx = threadIdx.x; idx < 16384; idx += 256){
    float f = xs[(idx >> 6)*65 + (idx & 63)];
    Vo[idx] = f;
    float lf = leaky(f);
    s += lf; ss = fmaf(lf, lf, ss);
  }
  red[threadIdx.x] = s; red[256 + threadIdx.x] = ss;
  __syncthreads();
  if (threadIdx.x < 64){
    float a  = red[threadIdx.x] + red[threadIdx.x+64] + red[threadIdx.x+128] + red[threadIdx.x+192];
    float a2 = red[256+threadIdx.x] + red[320+threadIdx.x] + red[384+threadIdx.x] + red[448+threadIdx.x];
    atomicAdd(&g_stats[128 + threadIdx.x], a);
    atomicAdd(&g_stats[192 + threadIdx.x], a2);
  }
}

// ---- kernel: s = BN2(leaky(r3)) + x_orig -> d_out (NCHW) + pooled sums ---------
__global__ void k_bn2_add_pool(const float* __restrict__ x_orig, float* __restrict__ out,
                               const float* __restrict__ g2, const float* __restrict__ b2){
  int b = blockIdx.x, n0 = blockIdx.y * 64;
  __shared__ float s[64*65];
  __shared__ float scale[64], shift[64];
  if (threadIdx.x < 64){
    int c = threadIdx.x;
    float m   = g_stats[128 + c] * (1.f/CNT);
    float var = g_stats[192 + c] * (1.f/CNT) - m*m;
    float sc  = g2[c] * rsqrtf(var + 1e-4f);
    scale[c] = sc; shift[c] = b2[c] - m*sc;
  }
  const float* R = g_V + ((size_t)b*TOK + n0)*CH_;
  for (int idx = threadIdx.x; idx < 4096; idx += 256){
    int t = idx >> 6, c = idx & 63;
    s[t*65 + c] = R[idx];
  }
  __syncthreads();
  int y = n0 >> 7, x0 = n0 & 127;
  int iblk = y >> 4, jbase = x0 >> 4;
  const float* xb = x_orig + (size_t)b*CH_*TOK;
  float* ob = out + (size_t)b*CH_*TOK;
  for (int idx = threadIdx.x; idx < 4096; idx += 256){
    int c = idx >> 6, j = idx & 63;
    float f = leaky(s[j*65 + c]) * scale[c] + shift[c];
    size_t off = (size_t)c*TOK + n0 + j;
    float sval = f + xb[off];
    ob[off] = sval;
    // reduce groups of 16 lanes (same c, same 16-wide pooling block)
    float r = sval;
    r += __shfl_down_sync(0xffffffffu, r, 8, 16);
    r += __shfl_down_sync(0xffffffffu, r, 4, 16);
    r += __shfl_down_sync(0xffffffffu, r, 2, 16);
    r += __shfl_down_sync(0xffffffffu, r, 1, 16);
    if ((threadIdx.x & 15) == 0){
      int jblk = jbase + (j >> 4);
      atomicAdd(&g_pooled[(b*64 + c)*64 + iblk*8 + jblk], r);
    }
  }
}

// ---------------- kernel: global min/max over pooled means ---------------------
__global__ void k_minmax(){
  float mn = 3.4e38f, mx = -3.4e38f;
  for (int i = threadIdx.x; i < B_*4096; i += 1024){
    float v = g_pooled[i] * (1.f/256.f);
    mn = fminf(mn, v); mx = fmaxf(mx, v);
  }
#pragma unroll
  for (int o = 16; o > 0; o >>= 1){
    mn = fminf(mn, __shfl_xor_sync(0xffffffffu, mn, o));
    mx = fmaxf(mx, __shfl_xor_sync(0xffffffffu, mx, o));
  }
  __shared__ float smn[32], smx[32];
  if ((threadIdx.x & 31) == 0){ smn[threadIdx.x >> 5] = mn; smx[threadIdx.x >> 5] = mx; }
  __syncthreads();
  if (threadIdx.x < 32){
    mn = smn[threadIdx.x]; mx = smx[threadIdx.x];
#pragma unroll
    for (int o = 16; o > 0; o >>= 1){
      mn = fminf(mn, __shfl_xor_sync(0xffffffffu, mn, o));
      mx = fmaxf(mx, __shfl_xor_sync(0xffffffffu, mx, o));
    }
    if (threadIdx.x == 0){ g_minmax[0] = mn; g_minmax[1] = mx; }
  }
}

// ---------------- kernel: SAA correlation + SE gate (per batch) ----------------
__global__ void k_gate(const float* __restrict__ w1, const float* __restrict__ w2){
  int b = blockIdx.x;
  __shared__ float y[4096];
  __shared__ float S[64];
  __shared__ float g0[64];
  __shared__ float hid[4];
  float mn = g_minmax[0];
  float inv = 1.f / (g_minmax[1] - mn);
  for (int i = threadIdx.x; i < 4096; i += 64)
    y[i] = (g_pooled[b*4096 + i] * (1.f/256.f) - mn) * inv;
  __syncthreads();
  {
    int i = threadIdx.x; float s = 0.f;
    for (int c = 0; c < 64; c++) s += y[c*64 + i];
    S[i] = s;
  }
  __syncthreads();
  {
    int c = threadIdx.x; float s = 0.f, sm2 = 0.f;
    for (int i = 0; i < 64; i++){
      s = fmaf(y[c*64 + i], S[i], s);
      sm2 += g_pooled[b*4096 + c*64 + i];
    }
    g0[c] = (s * (1.f/64.f)) * (sm2 * (1.f/16384.f));
  }
  __syncthreads();
  if (threadIdx.x < 4){
    int j = threadIdx.x; float h = 0.f;
    for (int c = 0; c < 64; c++) h = fmaf(g0[c], w1[c*4 + j], h);
    hid[j] = leaky(h);
  }
  __syncthreads();
  {
    int c = threadIdx.x; float o = 0.f;
#pragma unroll
    for (int j = 0; j < 4; j++) o = fmaf(hid[j], w2[j*64 + c], o);
    g_gate[b*64 + c] = 1.f / (1.f + expf(-o));
  }
}

// ---------------- kernel: d_out *= gate[b,c] (NCHW) ----------------------------
__global__ void k_scale(float* __restrict__ out){
  size_t i = (size_t)blockIdx.x * 256 + threadIdx.x;
  out[i] *= g_gate[i >> 14];
}

// ================================ launch ========================================
extern "C" void kernel_launch(void* const* d_in, const int* in_sizes, int n_in,
                              void* d_out, int out_size){
  const float* x     = (const float*)d_in[0];
  const float* wq    = (const float*)d_in[1];
  const float* wk    = (const float*)d_in[2];
  const float* wv    = (const float*)d_in[3];
  const float* wproj = (const float*)d_in[4];
  const float* bproj = (const float*)d_in[5];
  const float* wpos  = (const float*)d_in[6];
  const float* ln_g  = (const float*)d_in[7];
  const float* ln_b  = (const float*)d_in[8];
  const float* wff   = (const float*)d_in[9];
  const float* bn1_g = (const float*)d_in[10];
  const float* bn1_b = (const float*)d_in[11];
  const float* wd    = (const float*)d_in[12];
  const float* bn2_g = (const float*)d_in[13];
  const float* bn2_b = (const float*)d_in[14];
  const float* sw1   = (const float*)d_in[15];
  const float* sw2   = (const float*)d_in[16];
  float* out = (float*)d_out;

  cudaFuncSetAttribute(k_v_gram,    cudaFuncAttributeMaxDynamicSharedMemorySize, 96*1024);
  cudaFuncSetAttribute(k_attn_weff, cudaFuncAttributeMaxDynamicSharedMemorySize, 100*1024);
  cudaFuncSetAttribute(k_epilogue,  cudaFuncAttributeMaxDynamicSharedMemorySize, 96*1024);
  cudaFuncSetAttribute(k_lnff,      cudaFuncAttributeMaxDynamicSharedMemorySize, 96*1024);
  cudaFuncSetAttribute(k_bn_conv,   cudaFuncAttributeMaxDynamicSharedMemorySize, 96*1024);

  void *pC = nullptr, *pStats = nullptr, *pPooled = nullptr;
  cudaGetSymbolAddress(&pC, g_C);
  cudaGetSymbolAddress(&pStats, g_stats);
  cudaGetSymbolAddress(&pPooled, g_pooled);

  const size_t smA = (16640 + 4096) * sizeof(float);

  k_transpose_in<<<dim3(16, 256), 256>>>(x);
  for (int l = 0; l < 2; l++){
    cudaMemsetAsync(pC, 0, 16*4096*sizeof(float));
    k_v_gram<<<dim3(16, 64), 256, smA>>>(wv + l*4096);
    k_attn_weff<<<16, 256, 6*4096*sizeof(float)>>>(wq + l*4096, wk + l*4096, wproj + l*4096);
    k_dwconv<<<dim3(16*128, 8), 256>>>(wpos + l*576);
    k_epilogue<<<dim3(16, 64), 256, (16640 + 4096 + 64)*sizeof(float)>>>(bproj + l*64);
    k_lnff<<<dim3(16, 64), 256, (16640 + 4096 + 128)*sizeof(float)>>>(wff + l*4096, ln_g + l*64, ln_b + l*64);
  }
  cudaMemsetAsync(pStats, 0, 256*sizeof(float));
  k_bnstats<<<1024, 256>>>();
  k_bn_conv<<<dim3(16, 64), 256, (16640 + 4096 + 128)*sizeof(float)>>>(wd, bn1_g, bn1_b);
  cudaMemsetAsync(pPooled, 0, 16*4096*sizeof(float));
  k_bn2_add_pool<<<dim3(16, 256), 256>>>(x, out, bn2_g, bn2_b);
  k_minmax<<<1, 1024>>>();
  k_gate<<<16, 64>>>(sw1, sw2);
  k_scale<<<65536, 256>>>(out);
}

// round 6
// speedup vs baseline: 1.4198x; 1.4198x over previous
#include <cuda_runtime.h>
#include <cuda_bf16.h>
#include <mma.h>
#include <cstdint>

using namespace nvcuda;

#define B_   16
#define CH_  64
#define TOK  16384
#define CNT  (16.0f*16384.0f)

__device__ float g_XT[B_*TOK*CH_];
__device__ float g_V [B_*TOK*CH_];
__device__ float g_P [B_*TOK*CH_];
__device__ float g_C    [B_*64*64];
__device__ float g_Weff [B_*64*64];
__device__ float g_stats[256];
__device__ float g_pooled[B_*64*64];
__device__ float g_minmax[2];
__device__ float g_gate[B_*64];

__device__ __forceinline__ float leaky(float x){ return x >= 0.f ? x : 0.2f*x; }

__device__ __forceinline__ void split_bf16(float f, __nv_bfloat16& h, __nv_bfloat16& l){
  h = __float2bfloat16_rn(f);
  l = __float2bfloat16_rn(f - __bfloat162float(h));
}

// ---------------- NCHW -> BHWC transpose ----------------
__global__ void k_transpose_in(const float* __restrict__ x){
  int b = blockIdx.x, n0 = blockIdx.y * 64;
  __shared__ float s[64*65];
  const float* xb = x + (size_t)b*CH_*TOK;
  for (int idx = threadIdx.x; idx < 4096; idx += 256){
    int c = idx >> 6, j = idx & 63;
    s[c*65 + j] = xb[(size_t)c*TOK + n0 + j];
  }
  __syncthreads();
  float* xt = g_XT + ((size_t)b*TOK + n0)*CH_;
  for (int idx = threadIdx.x; idx < 4096; idx += 256){
    int j = idx >> 6, c = idx & 63;
    xt[j*CH_ + c] = s[c*65 + j];
  }
}

// =============== wmma GEMM, fused pre/post ===============
// MODE 0: V = XT @ W
// MODE 1: XT += (V @ Weff_b + bproj) * P
// MODE 2: XT += LN(XT) @ W   (STATS=1: also accumulate leaky stats of new XT -> g_stats[0..127])
// MODE 3: V = BN1(leaky(XT)) @ W ; leaky stats of result -> g_stats[128..255]
// dynamic smem layout (bytes):
//  xs   float [128][68]        @ 0       (34816)
//  Ah   bf16  [128][72]        @ 34816   (18432)
//  Al   bf16  [128][72]        @ 53248   (18432)
//  Bh   bf16  [64][72]         @ 71680   (9216)
//  Bl   bf16  [64][72]         @ 80896   (9216)   total 90112
#define SM_GEMM_BYTES 90112
template<int MODE, int STATS>
__global__ __launch_bounds__(128)
void k_gemm(const float* __restrict__ W, const float* __restrict__ aux0,
            const float* __restrict__ aux1){
  extern __shared__ unsigned char smraw[];
  float* xs = (float*)smraw;
  __nv_bfloat16* Ah = (__nv_bfloat16*)(smraw + 34816);
  __nv_bfloat16* Al = (__nv_bfloat16*)(smraw + 53248);
  __nv_bfloat16* Bh = (__nv_bfloat16*)(smraw + 71680);
  __nv_bfloat16* Bl = (__nv_bfloat16*)(smraw + 80896);
  __shared__ float s_a[64], s_b[64];
  __shared__ float red[256];

  int tid = threadIdx.x, wid = tid >> 5;
  int b = blockIdx.x, n0 = blockIdx.y * 128;

  // aux preload
  if (MODE == 1 && tid < 64) s_a[tid] = aux0[tid];
  if (MODE == 2 && tid < 64){ s_a[tid] = aux0[tid]; s_b[tid] = aux1[tid]; }
  if (MODE == 3 && tid < 64){
    float m   = g_stats[tid]      * (1.f/CNT);
    float var = g_stats[64 + tid] * (1.f/CNT) - m*m;
    float sc  = aux0[tid] * rsqrtf(var + 1e-4f);
    s_a[tid] = sc; s_b[tid] = aux1[tid] - m*sc;
  }

  // stage W -> Bh/Bl  (W layout [cin][out], exactly wmma row-major B [k][n])
  const float* Wb = (MODE == 1) ? (g_Weff + b*4096) : W;
  for (int idx = tid; idx < 4096; idx += 128){
    int k = idx >> 6, n = idx & 63;
    __nv_bfloat16 h, l; split_bf16(Wb[idx], h, l);
    Bh[k*72 + n] = h; Bl[k*72 + n] = l;
  }
  __syncthreads();  // s_a/s_b ready (needed by MODE 3 staging)

  // stage input -> Ah/Al (elementwise pre-op fused; MODE 2 needs row stats first)
  const float* IN = (MODE == 1 ? g_V : g_XT) + ((size_t)b*TOK + n0)*CH_;
  if (MODE == 2){
    for (int idx = tid; idx < 8192; idx += 128)
      xs[(idx >> 6)*68 + (idx & 63)] = IN[idx];
    __syncthreads();
    const float* row = &xs[tid*68];
    float s = 0.f, ss = 0.f;
#pragma unroll
    for (int c = 0; c < 64; c++){ float xv = row[c]; s += xv; ss = fmaf(xv, xv, ss); }
    float mean = s * (1.f/64.f);
    float rstd = rsqrtf(ss*(1.f/64.f) - mean*mean + 1e-5f);
#pragma unroll
    for (int c = 0; c < 64; c++){
      float f = (row[c] - mean) * rstd * s_a[c] + s_b[c];
      __nv_bfloat16 h, l; split_bf16(f, h, l);
      Ah[tid*72 + c] = h; Al[tid*72 + c] = l;
    }
  } else {
    for (int idx = tid; idx < 8192; idx += 128){
      int t = idx >> 6, c = idx & 63;
      float f = IN[idx];
      if (MODE == 3) f = leaky(f)*s_a[c] + s_b[c];
      __nv_bfloat16 h, l; split_bf16(f, h, l);
      Ah[t*72 + c] = h; Al[t*72 + c] = l;
    }
  }
  __syncthreads();

  // wmma: each warp does 32 token rows (2 m-frags) x 64 out (4 n-frags)
  {
    wmma::fragment<wmma::accumulator,16,16,16,float> acc[2][4];
#pragma unroll
    for (int i = 0; i < 2; i++)
#pragma unroll
      for (int j = 0; j < 4; j++) wmma::fill_fragment(acc[i][j], 0.f);
    int m0 = wid * 32;
#pragma unroll
    for (int k = 0; k < 4; k++){
      wmma::fragment<wmma::matrix_a,16,16,16,__nv_bfloat16,wmma::row_major> ah[2], al[2];
#pragma unroll
      for (int i = 0; i < 2; i++){
        wmma::load_matrix_sync(ah[i], Ah + (m0 + i*16)*72 + k*16, 72);
        wmma::load_matrix_sync(al[i], Al + (m0 + i*16)*72 + k*16, 72);
      }
#pragma unroll
      for (int j = 0; j < 4; j++){
        wmma::fragment<wmma::matrix_b,16,16,16,__nv_bfloat16,wmma::row_major> bh, bl;
        wmma::load_matrix_sync(bh, Bh + (k*16)*72 + j*16, 72);
        wmma::load_matrix_sync(bl, Bl + (k*16)*72 + j*16, 72);
#pragma unroll
        for (int i = 0; i < 2; i++){
          wmma::mma_sync(acc[i][j], ah[i], bh, acc[i][j]);
          wmma::mma_sync(acc[i][j], ah[i], bl, acc[i][j]);
          wmma::mma_sync(acc[i][j], al[i], bh, acc[i][j]);
        }
      }
    }
    __syncthreads();  // xs free for output
#pragma unroll
    for (int i = 0; i < 2; i++)
#pragma unroll
      for (int j = 0; j < 4; j++)
        wmma::store_matrix_sync(xs + (m0 + i*16)*68 + j*16, acc[i][j], 68, wmma::mem_row_major);
  }
  __syncthreads();

  // epilogue
  float s = 0.f, ss = 0.f;
  if (MODE == 0){
    float* O = g_V + ((size_t)b*TOK + n0)*CH_;
    for (int idx = tid; idx < 8192; idx += 128)
      O[idx] = xs[(idx>>6)*68 + (idx&63)];
  } else if (MODE == 1){
    float* XT = g_XT + ((size_t)b*TOK + n0)*CH_;
    const float* P = g_P + ((size_t)b*TOK + n0)*CH_;
    for (int idx = tid; idx < 8192; idx += 128){
      int c = idx & 63;
      XT[idx] += (xs[(idx>>6)*68 + c] + s_a[c]) * P[idx];
    }
  } else if (MODE == 2){
    float* XT = g_XT + ((size_t)b*TOK + n0)*CH_;
    for (int idx = tid; idx < 8192; idx += 128){
      float nv = XT[idx] + xs[(idx>>6)*68 + (idx&63)];
      XT[idx] = nv;
      if (STATS){ float lf = leaky(nv); s += lf; ss = fmaf(lf, lf, ss); }
    }
  } else {
    float* O = g_V + ((size_t)b*TOK + n0)*CH_;
    for (int idx = tid; idx < 8192; idx += 128){
      float f = xs[(idx>>6)*68 + (idx&63)];
      O[idx] = f;
      float lf = leaky(f);
      s += lf; ss = fmaf(lf, lf, ss);
    }
  }
  if (STATS || MODE == 3){
    red[tid] = s; red[128 + tid] = ss;
    __syncthreads();
    int base = (MODE == 3) ? 128 : 0;
    if (tid < 64){
      atomicAdd(&g_stats[base + tid],      red[tid] + red[tid + 64]);
      atomicAdd(&g_stats[base + 64 + tid], red[128 + tid] + red[192 + tid]);
    }
  }
}

// =============== wmma gram: g_C[b] += XT^T @ XT (hi/lo, 3 products) ===============
// dynamic smem: Ah bf16[128][72] @0 (18432), Al @18432 (18432); outF reuses Ah.
#define SM_GRAM_BYTES 36864
__global__ __launch_bounds__(128)
void k_gram(){
  extern __shared__ unsigned char smraw[];
  __nv_bfloat16* Ah = (__nv_bfloat16*)smraw;
  __nv_bfloat16* Al = (__nv_bfloat16*)(smraw + 18432);
  int tid = threadIdx.x, wid = tid >> 5;
  int b = blockIdx.x;

  wmma::fragment<wmma::accumulator,16,16,16,float> acc[4];
#pragma unroll
  for (int j = 0; j < 4; j++) wmma::fill_fragment(acc[j], 0.f);

  for (int st = 0; st < 8; st++){
    int n0 = (blockIdx.y * 8 + st) * 128;
    const float* IN = g_XT + ((size_t)b*TOK + n0)*CH_;
    __syncthreads();
    for (int idx = tid; idx < 8192; idx += 128){
      int t = idx >> 6, c = idx & 63;
      __nv_bfloat16 h, l; split_bf16(IN[idx], h, l);
      Ah[t*72 + c] = h; Al[t*72 + c] = l;
    }
    __syncthreads();
    // warp wid: output rows c in [wid*16, wid*16+16)
#pragma unroll
    for (int k = 0; k < 8; k++){
      // A = X^T (col_major view of X[t][c]): element (m=c, k=t) at Ah[c + t*72]
      wmma::fragment<wmma::matrix_a,16,16,16,__nv_bfloat16,wmma::col_major> ah, al;
      wmma::load_matrix_sync(ah, Ah + wid*16 + (k*16)*72, 72);
      wmma::load_matrix_sync(al, Al + wid*16 + (k*16)*72, 72);
#pragma unroll
      for (int j = 0; j < 4; j++){
        wmma::fragment<wmma::matrix_b,16,16,16,__nv_bfloat16,wmma::row_major> bh, bl;
        wmma::load_matrix_sync(bh, Ah + (k*16)*72 + j*16, 72);
        wmma::load_matrix_sync(bl, Al + (k*16)*72 + j*16, 72);
        wmma::mma_sync(acc[j], ah, bh, acc[j]);
        wmma::mma_sync(acc[j], ah, bl, acc[j]);
        wmma::mma_sync(acc[j], al, bh, acc[j]);
      }
    }
  }
  __syncthreads();
  float* outF = (float*)smraw;   // 64*68 floats = 17408 B, fits in Ah region
#pragma unroll
  for (int j = 0; j < 4; j++)
    wmma::store_matrix_sync(outF + (wid*16)*68 + j*16, acc[j], 68, wmma::mem_row_major);
  __syncthreads();
  for (int idx = tid; idx < 4096; idx += 128)
    atomicAdd(&g_C[b*4096 + idx], outF[(idx>>6)*68 + (idx&63)]);
}

// ------- per-batch attention stats + fold into Weff -------
__global__ void k_attn_weff(const float* __restrict__ wq, const float* __restrict__ wk,
                            const float* __restrict__ wproj){
  extern __shared__ float sm[];
  float* Cs  = sm;
  float* wqs = sm + 4096;
  float* wks = sm + 8192;
  float* wps = sm + 12288;
  float* T1  = sm + 16384;
  float* T2  = sm + 20480;
  __shared__ float attn_s[512];
  __shared__ float qq[64], kk[64];
  int b = blockIdx.x;
  for (int i = threadIdx.x; i < 4096; i += 256){
    Cs[i]  = g_C[b*4096 + i];
    wqs[i] = wq[i]; wks[i] = wk[i]; wps[i] = wproj[i];
  }
  __syncthreads();
  for (int i = threadIdx.x; i < 4096; i += 256){
    int r = i >> 6, e = i & 63; float s1 = 0.f, s2 = 0.f;
    for (int c = 0; c < 64; c++){
      float cv = Cs[r*64 + c];
      s1 = fmaf(cv, wqs[c*64 + e], s1);
      s2 = fmaf(cv, wks[c*64 + e], s2);
    }
    T1[i] = s1; T2[i] = s2;
  }
  __syncthreads();
  if (threadIdx.x < 64){
    int e = threadIdx.x; float s1 = 0.f, s2 = 0.f;
    for (int c = 0; c < 64; c++){
      s1 = fmaf(wqs[c*64 + e], T1[c*64 + e], s1);
      s2 = fmaf(wks[c*64 + e], T2[c*64 + e], s2);
    }
    qq[e] = s1; kk[e] = s2;
  }
  __syncthreads();
  if (threadIdx.x < 64){
    int h = threadIdx.x >> 3, dd = threadIdx.x & 7;
    float nk = fmaxf(sqrtf(kk[h*8 + dd]), 1e-12f);
    float lo[8]; float mx = -3.4e38f;
#pragma unroll
    for (int e = 0; e < 8; e++){
      float gg = 0.f;
      for (int c = 0; c < 64; c++)
        gg = fmaf(wks[c*64 + h*8 + dd], T1[c*64 + h*8 + e], gg);
      float nq = fmaxf(sqrtf(qq[h*8 + e]), 1e-12f);
      lo[e] = gg / (nk * nq);
      mx = fmaxf(mx, lo[e]);
    }
    float sum = 0.f;
#pragma unroll
    for (int e = 0; e < 8; e++){ lo[e] = expf(lo[e] - mx); sum += lo[e]; }
    float inv = 1.f / sum;
#pragma unroll
    for (int e = 0; e < 8; e++) attn_s[(h*8 + dd)*8 + e] = lo[e] * inv;
  }
  __syncthreads();
  for (int i = threadIdx.x; i < 4096; i += 256){
    int cin = i >> 6, oc = i & 63;
    int h = cin >> 3, e = cin & 7;
    float s = 0.f;
#pragma unroll
    for (int dd = 0; dd < 8; dd++)
      s = fmaf(attn_s[(h*8 + dd)*8 + e], wps[(h*8 + dd)*64 + oc], s);
    g_Weff[b*4096 + i] = s;
  }
}

// ---------------- depthwise 3x3 on V -> P ----------------
__global__ void k_dwconv(const float* __restrict__ wpos){
  int bh = blockIdx.x; int b = bh >> 7; int y = bh & 127;
  int cg = threadIdx.x & 15;
  int x  = blockIdx.y * 16 + (threadIdx.x >> 4);
  __shared__ float wp[576];
  for (int i = threadIdx.x; i < 576; i += 256) wp[i] = wpos[i];
  __syncthreads();
  float a0 = 0.f, a1 = 0.f, a2 = 0.f, a3 = 0.f;
  const float* Vb = g_V + (size_t)b*TOK*CH_;
#pragma unroll
  for (int ky = 0; ky < 3; ky++){
    int yy = y + ky - 1; if (yy < 0 || yy > 127) continue;
#pragma unroll
    for (int kx = 0; kx < 3; kx++){
      int xx = x + kx - 1; if (xx < 0 || xx > 127) continue;
      float4 v = *(const float4*)&Vb[((size_t)yy*128 + xx)*64 + cg*4];
      int wi = ky*3 + kx;
      a0 = fmaf(v.x, wp[(cg*4+0)*9 + wi], a0);
      a1 = fmaf(v.y, wp[(cg*4+1)*9 + wi], a1);
      a2 = fmaf(v.z, wp[(cg*4+2)*9 + wi], a2);
      a3 = fmaf(v.w, wp[(cg*4+3)*9 + wi], a3);
    }
  }
  *(float4*)&g_P[((size_t)b*TOK + y*128 + x)*64 + cg*4] = make_float4(a0,a1,a2,a3);
}

// ---- BN2 + residual + NCHW out + pooled sums ----
__global__ void k_bn2_add_pool(const float* __restrict__ x_orig, float* __restrict__ out,
                               const float* __restrict__ g2, const float* __restrict__ b2){
  int b = blockIdx.x, n0 = blockIdx.y * 64;
  __shared__ float s[64*65];
  __shared__ float scale[64], shift[64];
  if (threadIdx.x < 64){
    int c = threadIdx.x;
    float m   = g_stats[128 + c] * (1.f/CNT);
    float var = g_stats[192 + c] * (1.f/CNT) - m*m;
    float sc  = g2[c] * rsqrtf(var + 1e-4f);
    scale[c] = sc; shift[c] = b2[c] - m*sc;
  }
  const float* R = g_V + ((size_t)b*TOK + n0)*CH_;
  for (int idx = threadIdx.x; idx < 4096; idx += 256){
    int t = idx >> 6, c = idx & 63;
    s[t*65 + c] = R[idx];
  }
  __syncthreads();
  int y = n0 >> 7, x0 = n0 & 127;
  int iblk = y >> 4, jbase = x0 >> 4;
  const float* xb = x_orig + (size_t)b*CH_*TOK;
  float* ob = out + (size_t)b*CH_*TOK;
  for (int idx = threadIdx.x; idx < 4096; idx += 256){
    int c = idx >> 6, j = idx & 63;
    float f = leaky(s[j*65 + c]) * scale[c] + shift[c];
    size_t off = (size_t)c*TOK + n0 + j;
    float sval = f + xb[off];
    ob[off] = sval;
    float r = sval;
    r += __shfl_down_sync(0xffffffffu, r, 8, 16);
    r += __shfl_down_sync(0xffffffffu, r, 4, 16);
    r += __shfl_down_sync(0xffffffffu, r, 2, 16);
    r += __shfl_down_sync(0xffffffffu, r, 1, 16);
    if ((threadIdx.x & 15) == 0)
      atomicAdd(&g_pooled[(b*64 + c)*64 + iblk*8 + jbase + (j >> 4)], r);
  }
}

__global__ void k_minmax(){
  float mn = 3.4e38f, mx = -3.4e38f;
  for (int i = threadIdx.x; i < B_*4096; i += 1024){
    float v = g_pooled[i] * (1.f/256.f);
    mn = fminf(mn, v); mx = fmaxf(mx, v);
  }
#pragma unroll
  for (int o = 16; o > 0; o >>= 1){
    mn = fminf(mn, __shfl_xor_sync(0xffffffffu, mn, o));
    mx = fmaxf(mx, __shfl_xor_sync(0xffffffffu, mx, o));
  }
  __shared__ float smn[32], smx[32];
  if ((threadIdx.x & 31) == 0){ smn[threadIdx.x >> 5] = mn; smx[threadIdx.x >> 5] = mx; }
  __syncthreads();
  if (threadIdx.x < 32){
    mn = smn[threadIdx.x]; mx = smx[threadIdx.x];
#pragma unroll
    for (int o = 16; o > 0; o >>= 1){
      mn = fminf(mn, __shfl_xor_sync(0xffffffffu, mn, o));
      mx = fmaxf(mx, __shfl_xor_sync(0xffffffffu, mx, o));
    }
    if (threadIdx.x == 0){ g_minmax[0] = mn; g_minmax[1] = mx; }
  }
}

__global__ void k_gate(const float* __restrict__ w1, const float* __restrict__ w2){
  int b = blockIdx.x;
  __shared__ float y[4096];
  __shared__ float S[64];
  __shared__ float g0[64];
  __shared__ float hid[4];
  float mn = g_minmax[0];
  float inv = 1.f / (g_minmax[1] - mn);
  for (int i = threadIdx.x; i < 4096; i += 64)
    y[i] = (g_pooled[b*4096 + i] * (1.f/256.f) - mn) * inv;
  __syncthreads();
  {
    int i = threadIdx.x; float s = 0.f;
    for (int c = 0; c < 64; c++) s += y[c*64 + i];
    S[i] = s;
  }
  __syncthreads();
  {
    int c = threadIdx.x; float s = 0.f, sm2 = 0.f;
    for (int i = 0; i < 64; i++){
      s = fmaf(y[c*64 + i], S[i], s);
      sm2 += g_pooled[b*4096 + c*64 + i];
    }
    g0[c] = (s * (1.f/64.f)) * (sm2 * (1.f/16384.f));
  }
  __syncthreads();
  if (threadIdx.x < 4){
    int j = threadIdx.x; float h = 0.f;
    for (int c = 0; c < 64; c++) h = fmaf(g0[c], w1[c*4 + j], h);
    hid[j] = leaky(h);
  }
  __syncthreads();
  {
    int c = threadIdx.x; float o = 0.f;
#pragma unroll
    for (int j = 0; j < 4; j++) o = fmaf(hid[j], w2[j*64 + c], o);
    g_gate[b*64 + c] = 1.f / (1.f + expf(-o));
  }
}

__global__ void k_scale(float* __restrict__ out){
  size_t i = (size_t)blockIdx.x * 256 + threadIdx.x;
  out[i] *= g_gate[i >> 14];
}

// ================================ launch ========================================
extern "C" void kernel_launch(void* const* d_in, const int* in_sizes, int n_in,
                              void* d_out, int out_size){
  const float* x     = (const float*)d_in[0];
  const float* wq    = (const float*)d_in[1];
  const float* wk    = (const float*)d_in[2];
  const float* wv    = (const float*)d_in[3];
  const float* wproj = (const float*)d_in[4];
  const float* bproj = (const float*)d_in[5];
  const float* wpos  = (const float*)d_in[6];
  const float* ln_g  = (const float*)d_in[7];
  const float* ln_b  = (const float*)d_in[8];
  const float* wff   = (const float*)d_in[9];
  const float* bn1_g = (const float*)d_in[10];
  const float* bn1_b = (const float*)d_in[11];
  const float* wd    = (const float*)d_in[12];
  const float* bn2_g = (const float*)d_in[13];
  const float* bn2_b = (const float*)d_in[14];
  const float* sw1   = (const float*)d_in[15];
  const float* sw2   = (const float*)d_in[16];
  float* out = (float*)d_out;

  cudaFuncSetAttribute(k_gemm<0,0>, cudaFuncAttributeMaxDynamicSharedMemorySize, SM_GEMM_BYTES);
  cudaFuncSetAttribute(k_gemm<1,0>, cudaFuncAttributeMaxDynamicSharedMemorySize, SM_GEMM_BYTES);
  cudaFuncSetAttribute(k_gemm<2,0>, cudaFuncAttributeMaxDynamicSharedMemorySize, SM_GEMM_BYTES);
  cudaFuncSetAttribute(k_gemm<2,1>, cudaFuncAttributeMaxDynamicSharedMemorySize, SM_GEMM_BYTES);
  cudaFuncSetAttribute(k_gemm<3,0>, cudaFuncAttributeMaxDynamicSharedMemorySize, SM_GEMM_BYTES);
  cudaFuncSetAttribute(k_gram,      cudaFuncAttributeMaxDynamicSharedMemorySize, SM_GRAM_BYTES);
  cudaFuncSetAttribute(k_attn_weff, cudaFuncAttributeMaxDynamicSharedMemorySize, 100*1024);

  void *pC = nullptr, *pStats = nullptr, *pPooled = nullptr;
  cudaGetSymbolAddress(&pC, g_C);
  cudaGetSymbolAddress(&pStats, g_stats);
  cudaGetSymbolAddress(&pPooled, g_pooled);

  cudaMemsetAsync(pStats, 0, 256*sizeof(float));
  k_transpose_in<<<dim3(16, 256), 256>>>(x);
  for (int l = 0; l < 2; l++){
    cudaMemsetAsync(pC, 0, 16*4096*sizeof(float));
    k_gram<<<dim3(16, 16), 128, SM_GRAM_BYTES>>>();
    k_attn_weff<<<16, 256, 6*4096*sizeof(float)>>>(wq + l*4096, wk + l*4096, wproj + l*4096);
    k_gemm<0,0><<<dim3(16, 128), 128, SM_GEMM_BYTES>>>(wv + l*4096, nullptr, nullptr);
    k_dwconv<<<dim3(16*128, 8), 256>>>(wpos + l*576);
    k_gemm<1,0><<<dim3(16, 128), 128, SM_GEMM_BYTES>>>(nullptr, bproj + l*64, nullptr);
    if (l == 0)
      k_gemm<2,0><<<dim3(16, 128), 128, SM_GEMM_BYTES>>>(wff + l*4096, ln_g + l*64, ln_b + l*64);
    else
      k_gemm<2,1><<<dim3(16, 128), 128, SM_GEMM_BYTES>>>(wff + l*4096, ln_g + l*64, ln_b + l*64);
  }
  k_gemm<3,0><<<dim3(16, 128), 128, SM_GEMM_BYTES>>>(wd, bn1_g, bn1_b);
  cudaMemsetAsync(pPooled, 0, 16*4096*sizeof(float));
  k_bn2_add_pool<<<dim3(16, 256), 256>>>(x, out, bn2_g, bn2_b);
  k_minmax<<<1, 1024>>>();
  k_gate<<<16, 64>>>(sw1, sw2);
  k_scale<<<65536, 256>>>(out);
}

// round 9
// speedup vs baseline: 2.1030x; 1.4811x over previous
#include <cuda_runtime.h>
#include <cuda_bf16.h>
#include <mma.h>
#include <cstdint>

using namespace nvcuda;

#define B_   16
#define CH_  64
#define TOK  16384
#define CNT  (16.0f*16384.0f)

__device__ float g_XT[B_*TOK*CH_];
__device__ float g_V [B_*TOK*CH_];
__device__ float g_P [B_*TOK*CH_];
__device__ float g_C    [B_*64*64];
__device__ float g_Weff [B_*64*64];
__device__ float g_stats[256];
__device__ float g_pooled[B_*64*64];
__device__ float g_minmax[2];
__device__ float g_gate[B_*64];

__device__ __forceinline__ float leaky(float x){ return x >= 0.f ? x : 0.2f*x; }
__device__ __forceinline__ void split_bf16(float f, __nv_bfloat16& h, __nv_bfloat16& l){
  h = __float2bfloat16_rn(f);
  l = __float2bfloat16_rn(f - __bfloat162float(h));
}

// ---------------- NCHW -> BHWC transpose ----------------
__global__ void k_transpose_in(const float* __restrict__ x){
  int b = blockIdx.x, n0 = blockIdx.y * 64;
  __shared__ float s[64*65];
  const float* xb = x + (size_t)b*CH_*TOK;
  for (int idx = threadIdx.x; idx < 4096; idx += 256){
    int c = idx >> 6, j = idx & 63;
    s[c*65 + j] = xb[(size_t)c*TOK + n0 + j];
  }
  __syncthreads();
  float* xt = g_XT + ((size_t)b*TOK + n0)*CH_;
  for (int idx = threadIdx.x; idx < 4096; idx += 256){
    int j = idx >> 6, c = idx & 63;
    xt[j*CH_ + c] = s[c*65 + j];
  }
}

// =============== wmma GEMM, fused pre/post ===============
// MODE 0: V = XT @ W
// MODE 1: XT += (V @ Weff_b + bproj) * P
// MODE 2: XT += LN(XT) @ W   (STATS=1: leaky stats of new XT -> g_stats[0..127], scalar loop)
// MODE 3: V = BN1(leaky(XT)) @ W ; leaky stats -> g_stats[128..255] (scalar loop)
// smem: xs f32[128][68] 34816 | Ah bf16[128][72] 18432 | Al 18432 | Bh bf16[64][72] 9216 | Bl 9216 = 90112
#define SM_GEMM_BYTES 90112
template<int MODE, int STATS>
__global__ __launch_bounds__(256)
void k_gemm(const float* __restrict__ W, const float* __restrict__ aux0,
            const float* __restrict__ aux1){
  extern __shared__ unsigned char smraw[];
  float* xs = (float*)smraw;
  __nv_bfloat16* Ah = (__nv_bfloat16*)(smraw + 34816);
  __nv_bfloat16* Al = (__nv_bfloat16*)(smraw + 53248);
  __nv_bfloat16* Bh = (__nv_bfloat16*)(smraw + 71680);
  __nv_bfloat16* Bl = (__nv_bfloat16*)(smraw + 80896);
  __shared__ float s_a[64], s_b[64];
  __shared__ float red[512];

  int tid = threadIdx.x, wid = tid >> 5;
  int b = blockIdx.x, n0 = blockIdx.y * 128;

  // aux preload
  if (MODE == 1 && tid < 64) s_a[tid] = aux0[tid];
  if (MODE == 2 && tid < 64){ s_a[tid] = aux0[tid]; s_b[tid] = aux1[tid]; }
  if (MODE == 3 && tid < 64){
    float m   = g_stats[tid]      * (1.f/CNT);
    float var = g_stats[64 + tid] * (1.f/CNT) - m*m;
    float sc  = aux0[tid] * rsqrtf(var + 1e-4f);
    s_a[tid] = sc; s_b[tid] = aux1[tid] - m*sc;
  }

  // stage W -> Bh/Bl (float4)
  const float* Wb = (MODE == 1) ? (g_Weff + b*4096) : W;
  const float4* W4 = (const float4*)Wb;
  for (int i = tid; i < 1024; i += 256){
    float4 v = W4[i];
    int k = i >> 4, n = (i & 15) * 4;
    __nv_bfloat16 h, l;
    split_bf16(v.x, h, l); Bh[k*72+n  ] = h; Bl[k*72+n  ] = l;
    split_bf16(v.y, h, l); Bh[k*72+n+1] = h; Bl[k*72+n+1] = l;
    split_bf16(v.z, h, l); Bh[k*72+n+2] = h; Bl[k*72+n+2] = l;
    split_bf16(v.w, h, l); Bh[k*72+n+3] = h; Bl[k*72+n+3] = l;
  }
  __syncthreads();   // s_a/s_b ready (needed by MODE 3 staging)

  // stage input
  const float* IN = (MODE == 1 ? g_V : g_XT) + ((size_t)b*TOK + n0)*CH_;
  const float4* IN4 = (const float4*)IN;
  if (MODE == 2){
    for (int i = tid; i < 2048; i += 256){
      float4 v = IN4[i];
      int t = i >> 4, c = (i & 15) * 4;
      *(float4*)&xs[t*68 + c] = v;
    }
    __syncthreads();
    if (tid < 128){
      const float* row = &xs[tid*68];
      float s = 0.f, ss = 0.f;
#pragma unroll
      for (int c = 0; c < 64; c++){ float xv = row[c]; s += xv; ss = fmaf(xv, xv, ss); }
      float mean = s * (1.f/64.f);
      float rstd = rsqrtf(ss*(1.f/64.f) - mean*mean + 1e-5f);
#pragma unroll
      for (int c = 0; c < 64; c++){
        float f = (row[c] - mean) * rstd * s_a[c] + s_b[c];
        __nv_bfloat16 h, l; split_bf16(f, h, l);
        Ah[tid*72 + c] = h; Al[tid*72 + c] = l;
      }
    }
  } else {
    for (int i = tid; i < 2048; i += 256){
      float4 v = IN4[i];
      int t = i >> 4, c = (i & 15) * 4;
      float f0 = v.x, f1 = v.y, f2 = v.z, f3 = v.w;
      if (MODE == 3){
        f0 = leaky(f0)*s_a[c  ] + s_b[c  ];
        f1 = leaky(f1)*s_a[c+1] + s_b[c+1];
        f2 = leaky(f2)*s_a[c+2] + s_b[c+2];
        f3 = leaky(f3)*s_a[c+3] + s_b[c+3];
      }
      __nv_bfloat16 h, l;
      split_bf16(f0, h, l); Ah[t*72+c  ] = h; Al[t*72+c  ] = l;
      split_bf16(f1, h, l); Ah[t*72+c+1] = h; Al[t*72+c+1] = l;
      split_bf16(f2, h, l); Ah[t*72+c+2] = h; Al[t*72+c+2] = l;
      split_bf16(f3, h, l); Ah[t*72+c+3] = h; Al[t*72+c+3] = l;
    }
  }
  __syncthreads();

  // wmma: 8 warps, each 16 token rows x 64 out
  {
    int m0 = wid * 16;
    wmma::fragment<wmma::accumulator,16,16,16,float> acc[4];
#pragma unroll
    for (int j = 0; j < 4; j++) wmma::fill_fragment(acc[j], 0.f);
#pragma unroll
    for (int k = 0; k < 4; k++){
      wmma::fragment<wmma::matrix_a,16,16,16,__nv_bfloat16,wmma::row_major> ah, al;
      wmma::load_matrix_sync(ah, Ah + m0*72 + k*16, 72);
      wmma::load_matrix_sync(al, Al + m0*72 + k*16, 72);
#pragma unroll
      for (int j = 0; j < 4; j++){
        wmma::fragment<wmma::matrix_b,16,16,16,__nv_bfloat16,wmma::row_major> bh, bl;
        wmma::load_matrix_sync(bh, Bh + (k*16)*72 + j*16, 72);
        wmma::load_matrix_sync(bl, Bl + (k*16)*72 + j*16, 72);
        wmma::mma_sync(acc[j], ah, bh, acc[j]);
        wmma::mma_sync(acc[j], ah, bl, acc[j]);
        wmma::mma_sync(acc[j], al, bh, acc[j]);
      }
    }
    __syncthreads();   // MODE 2: all LN reads of xs complete before overwrite
#pragma unroll
    for (int j = 0; j < 4; j++)
      wmma::store_matrix_sync(xs + m0*68 + j*16, acc[j], 68, wmma::mem_row_major);
  }
  __syncthreads();

  // epilogue
  float s = 0.f, ss = 0.f;
  if (MODE == 0){
    float4* O4 = (float4*)(g_V + ((size_t)b*TOK + n0)*CH_);
    for (int i = tid; i < 2048; i += 256){
      int t = i >> 4, c = (i & 15) * 4;
      O4[i] = *(float4*)&xs[t*68 + c];
    }
  } else if (MODE == 1){
    float4* XT4 = (float4*)(g_XT + ((size_t)b*TOK + n0)*CH_);
    const float4* P4 = (const float4*)(g_P + ((size_t)b*TOK + n0)*CH_);
    for (int i = tid; i < 2048; i += 256){
      int t = i >> 4, c = (i & 15) * 4;
      float4 xv = XT4[i], pv = P4[i], ov = *(float4*)&xs[t*68 + c];
      xv.x += (ov.x + s_a[c  ]) * pv.x;
      xv.y += (ov.y + s_a[c+1]) * pv.y;
      xv.z += (ov.z + s_a[c+2]) * pv.z;
      xv.w += (ov.w + s_a[c+3]) * pv.w;
      XT4[i] = xv;
    }
  } else if (MODE == 2){
    float* XT = g_XT + ((size_t)b*TOK + n0)*CH_;
    if (STATS){
      // SCALAR loop: stride 256 keeps per-thread channel purity (idx & 63 == tid & 63)
      for (int idx = tid; idx < 8192; idx += 256){
        float nv = XT[idx] + xs[(idx>>6)*68 + (idx&63)];
        XT[idx] = nv;
        float lf = leaky(nv); s += lf; ss = fmaf(lf, lf, ss);
      }
    } else {
      float4* XT4 = (float4*)XT;
      for (int i = tid; i < 2048; i += 256){
        int t = i >> 4, c = (i & 15) * 4;
        float4 xv = XT4[i], ov = *(float4*)&xs[t*68 + c];
        xv.x += ov.x; xv.y += ov.y; xv.z += ov.z; xv.w += ov.w;
        XT4[i] = xv;
      }
    }
  } else {
    // MODE 3: SCALAR loop for channel-pure stats
    float* O = g_V + ((size_t)b*TOK + n0)*CH_;
    for (int idx = tid; idx < 8192; idx += 256){
      float f = xs[(idx>>6)*68 + (idx&63)];
      O[idx] = f;
      float lf = leaky(f); s += lf; ss = fmaf(lf, lf, ss);
    }
  }
  if ((MODE == 2 && STATS) || MODE == 3){
    red[tid] = s; red[256 + tid] = ss;
    __syncthreads();
    int base = (MODE == 3) ? 128 : 0;
    if (tid < 64){
      atomicAdd(&g_stats[base + tid],
                red[tid] + red[tid+64] + red[tid+128] + red[tid+192]);
      atomicAdd(&g_stats[base + 64 + tid],
                red[256+tid] + red[320+tid] + red[384+tid] + red[448+tid]);
    }
  }
}

// =============== wmma gram: g_C[b] += XT^T @ XT (hi/lo, 3 products) — R6 VERBATIM ===============
#define SM_GRAM_BYTES 36864
__global__ __launch_bounds__(128)
void k_gram(){
  extern __shared__ unsigned char smraw[];
  __nv_bfloat16* Ah = (__nv_bfloat16*)smraw;
  __nv_bfloat16* Al = (__nv_bfloat16*)(smraw + 18432);
  int tid = threadIdx.x, wid = tid >> 5;
  int b = blockIdx.x;

  wmma::fragment<wmma::accumulator,16,16,16,float> acc[4];
#pragma unroll
  for (int j = 0; j < 4; j++) wmma::fill_fragment(acc[j], 0.f);

  for (int st = 0; st < 8; st++){
    int n0 = (blockIdx.y * 8 + st) * 128;
    const float* IN = g_XT + ((size_t)b*TOK + n0)*CH_;
    __syncthreads();
    for (int idx = tid; idx < 8192; idx += 128){
      int t = idx >> 6, c = idx & 63;
      __nv_bfloat16 h, l; split_bf16(IN[idx], h, l);
      Ah[t*72 + c] = h; Al[t*72 + c] = l;
    }
    __syncthreads();
#pragma unroll
    for (int k = 0; k < 8; k++){
      wmma::fragment<wmma::matrix_a,16,16,16,__nv_bfloat16,wmma::col_major> ah, al;
      wmma::load_matrix_sync(ah, Ah + wid*16 + (k*16)*72, 72);
      wmma::load_matrix_sync(al, Al + wid*16 + (k*16)*72, 72);
#pragma unroll
      for (int j = 0; j < 4; j++){
        wmma::fragment<wmma::matrix_b,16,16,16,__nv_bfloat16,wmma::row_major> bh, bl;
        wmma::load_matrix_sync(bh, Ah + (k*16)*72 + j*16, 72);
        wmma::load_matrix_sync(bl, Al + (k*16)*72 + j*16, 72);
        wmma::mma_sync(acc[j], ah, bh, acc[j]);
        wmma::mma_sync(acc[j], ah, bl, acc[j]);
        wmma::mma_sync(acc[j], al, bh, acc[j]);
      }
    }
  }
  __syncthreads();
  float* outF = (float*)smraw;
#pragma unroll
  for (int j = 0; j < 4; j++)
    wmma::store_matrix_sync(outF + (wid*16)*68 + j*16, acc[j], 68, wmma::mem_row_major);
  __syncthreads();
  for (int idx = tid; idx < 4096; idx += 128)
    atomicAdd(&g_C[b*4096 + idx], outF[(idx>>6)*68 + (idx&63)]);
}

// ------- per-batch attention stats + fold into Weff -------
__global__ void k_attn_weff(const float* __restrict__ wq, const float* __restrict__ wk,
                            const float* __restrict__ wproj){
  extern __shared__ float sm[];
  float* Cs  = sm;
  float* wqs = sm + 4096;
  float* wks = sm + 8192;
  float* wps = sm + 12288;
  float* T1  = sm + 16384;
  float* T2  = sm + 20480;
  __shared__ float attn_s[512];
  __shared__ float qq[64], kk[64];
  int b = blockIdx.x;
  for (int i = threadIdx.x; i < 4096; i += 256){
    Cs[i]  = g_C[b*4096 + i];
    wqs[i] = wq[i]; wks[i] = wk[i]; wps[i] = wproj[i];
  }
  __syncthreads();
  for (int i = threadIdx.x; i < 4096; i += 256){
    int r = i >> 6, e = i & 63; float s1 = 0.f, s2 = 0.f;
    for (int c = 0; c < 64; c++){
      float cv = Cs[r*64 + c];
      s1 = fmaf(cv, wqs[c*64 + e], s1);
      s2 = fmaf(cv, wks[c*64 + e], s2);
    }
    T1[i] = s1; T2[i] = s2;
  }
  __syncthreads();
  if (threadIdx.x < 64){
    int e = threadIdx.x; float s1 = 0.f, s2 = 0.f;
    for (int c = 0; c < 64; c++){
      s1 = fmaf(wqs[c*64 + e], T1[c*64 + e], s1);
      s2 = fmaf(wks[c*64 + e], T2[c*64 + e], s2);
    }
    qq[e] = s1; kk[e] = s2;
  }
  __syncthreads();
  if (threadIdx.x < 64){
    int h = threadIdx.x >> 3, dd = threadIdx.x & 7;
    float nk = fmaxf(sqrtf(kk[h*8 + dd]), 1e-12f);
    float lo[8]; float mx = -3.4e38f;
#pragma unroll
    for (int e = 0; e < 8; e++){
      float gg = 0.f;
      for (int c = 0; c < 64; c++)
        gg = fmaf(wks[c*64 + h*8 + dd], T1[c*64 + h*8 + e], gg);
      float nq = fmaxf(sqrtf(qq[h*8 + e]), 1e-12f);
      lo[e] = gg / (nk * nq);
      mx = fmaxf(mx, lo[e]);
    }
    float sum = 0.f;
#pragma unroll
    for (int e = 0; e < 8; e++){ lo[e] = expf(lo[e] - mx); sum += lo[e]; }
    float inv = 1.f / sum;
#pragma unroll
    for (int e = 0; e < 8; e++) attn_s[(h*8 + dd)*8 + e] = lo[e] * inv;
  }
  __syncthreads();
  for (int i = threadIdx.x; i < 4096; i += 256){
    int cin = i >> 6, oc = i & 63;
    int h = cin >> 3, e = cin & 7;
    float s = 0.f;
#pragma unroll
    for (int dd = 0; dd < 8; dd++)
      s = fmaf(attn_s[(h*8 + dd)*8 + e], wps[(h*8 + dd)*64 + oc], s);
    g_Weff[b*4096 + i] = s;
  }
}

// ---------------- depthwise 3x3 on V -> P ----------------
__global__ void k_dwconv(const float* __restrict__ wpos){
  int bh = blockIdx.x; int b = bh >> 7; int y = bh & 127;
  int cg = threadIdx.x & 15;
  int x  = blockIdx.y * 16 + (threadIdx.x >> 4);
  __shared__ float wp[576];
  for (int i = threadIdx.x; i < 576; i += 256) wp[i] = wpos[i];
  __syncthreads();
  float a0 = 0.f, a1 = 0.f, a2 = 0.f, a3 = 0.f;
  const float* Vb = g_V + (size_t)b*TOK*CH_;
#pragma unroll
  for (int ky = 0; ky < 3; ky++){
    int yy = y + ky - 1; if (yy < 0 || yy > 127) continue;
#pragma unroll
    for (int kx = 0; kx < 3; kx++){
      int xx = x + kx - 1; if (xx < 0 || xx > 127) continue;
      float4 v = *(const float4*)&Vb[((size_t)yy*128 + xx)*64 + cg*4];
      int wi = ky*3 + kx;
      a0 = fmaf(v.x, wp[(cg*4+0)*9 + wi], a0);
      a1 = fmaf(v.y, wp[(cg*4+1)*9 + wi], a1);
      a2 = fmaf(v.z, wp[(cg*4+2)*9 + wi], a2);
      a3 = fmaf(v.w, wp[(cg*4+3)*9 + wi], a3);
    }
  }
  *(float4*)&g_P[((size_t)b*TOK + y*128 + x)*64 + cg*4] = make_float4(a0,a1,a2,a3);
}

// ---- BN2 + residual + NCHW out + pooled sums ----
__global__ void k_bn2_add_pool(const float* __restrict__ x_orig, float* __restrict__ out,
                               const float* __restrict__ g2, const float* __restrict__ b2){
  int b = blockIdx.x, n0 = blockIdx.y * 64;
  __shared__ float s[64*65];
  __shared__ float scale[64], shift[64];
  if (threadIdx.x < 64){
    int c = threadIdx.x;
    float m   = g_stats[128 + c] * (1.f/CNT);
    float var = g_stats[192 + c] * (1.f/CNT) - m*m;
    float sc  = g2[c] * rsqrtf(var + 1e-4f);
    scale[c] = sc; shift[c] = b2[c] - m*sc;
  }
  const float* R = g_V + ((size_t)b*TOK + n0)*CH_;
  for (int idx = threadIdx.x; idx < 4096; idx += 256){
    int t = idx >> 6, c = idx & 63;
    s[t*65 + c] = R[idx];
  }
  __syncthreads();
  int y = n0 >> 7, x0 = n0 & 127;
  int iblk = y >> 4, jbase = x0 >> 4;
  const float* xb = x_orig + (size_t)b*CH_*TOK;
  float* ob = out + (size_t)b*CH_*TOK;
  for (int idx = threadIdx.x; idx < 4096; idx += 256){
    int c = idx >> 6, j = idx & 63;
    float f = leaky(s[j*65 + c]) * scale[c] + shift[c];
    size_t off = (size_t)c*TOK + n0 + j;
    float sval = f + xb[off];
    ob[off] = sval;
    float r = sval;
    r += __shfl_down_sync(0xffffffffu, r, 8, 16);
    r += __shfl_down_sync(0xffffffffu, r, 4, 16);
    r += __shfl_down_sync(0xffffffffu, r, 2, 16);
    r += __shfl_down_sync(0xffffffffu, r, 1, 16);
    if ((threadIdx.x & 15) == 0)
      atomicAdd(&g_pooled[(b*64 + c)*64 + iblk*8 + jbase + (j >> 4)], r);
  }
}

__global__ void k_minmax(){
  float mn = 3.4e38f, mx = -3.4e38f;
  for (int i = threadIdx.x; i < B_*4096; i += 1024){
    float v = g_pooled[i] * (1.f/256.f);
    mn = fminf(mn, v); mx = fmaxf(mx, v);
  }
#pragma unroll
  for (int o = 16; o > 0; o >>= 1){
    mn = fminf(mn, __shfl_xor_sync(0xffffffffu, mn, o));
    mx = fmaxf(mx, __shfl_xor_sync(0xffffffffu, mx, o));
  }
  __shared__ float smn[32], smx[32];
  if ((threadIdx.x & 31) == 0){ smn[threadIdx.x >> 5] = mn; smx[threadIdx.x >> 5] = mx; }
  __syncthreads();
  if (threadIdx.x < 32){
    mn = smn[threadIdx.x]; mx = smx[threadIdx.x];
#pragma unroll
    for (int o = 16; o > 0; o >>= 1){
      mn = fminf(mn, __shfl_xor_sync(0xffffffffu, mn, o));
      mx = fmaxf(mx, __shfl_xor_sync(0xffffffffu, mx, o));
    }
    if (threadIdx.x == 0){ g_minmax[0] = mn; g_minmax[1] = mx; }
  }
}

__global__ void k_gate(const float* __restrict__ w1, const float* __restrict__ w2){
  int b = blockIdx.x;
  __shared__ float y[4096];
  __shared__ float S[64];
  __shared__ float g0[64];
  __shared__ float hid[4];
  float mn = g_minmax[0];
  float inv = 1.f / (g_minmax[1] - mn);
  for (int i = threadIdx.x; i < 4096; i += 64)
    y[i] = (g_pooled[b*4096 + i] * (1.f/256.f) - mn) * inv;
  __syncthreads();
  {
    int i = threadIdx.x; float s = 0.f;
    for (int c = 0; c < 64; c++) s += y[c*64 + i];
    S[i] = s;
  }
  __syncthreads();
  {
    int c = threadIdx.x; float s = 0.f, sm2 = 0.f;
    for (int i = 0; i < 64; i++){
      s = fmaf(y[c*64 + i], S[i], s);
      sm2 += g_pooled[b*4096 + c*64 + i];
    }
    g0[c] = (s * (1.f/64.f)) * (sm2 * (1.f/16384.f));
  }
  __syncthreads();
  if (threadIdx.x < 4){
    int j = threadIdx.x; float h = 0.f;
    for (int c = 0; c < 64; c++) h = fmaf(g0[c], w1[c*4 + j], h);
    hid[j] = leaky(h);
  }
  __syncthreads();
  {
    int c = threadIdx.x; float o = 0.f;
#pragma unroll
    for (int j = 0; j < 4; j++) o = fmaf(hid[j], w2[j*64 + c], o);
    g_gate[b*64 + c] = 1.f / (1.f + expf(-o));
  }
}

__global__ void k_scale(float* __restrict__ out){
  size_t i = (size_t)blockIdx.x * 256 + threadIdx.x;
  out[i] *= g_gate[i >> 14];
}

// ================================ launch ========================================
extern "C" void kernel_launch(void* const* d_in, const int* in_sizes, int n_in,
                              void* d_out, int out_size){
  const float* x     = (const float*)d_in[0];
  const float* wq    = (const float*)d_in[1];
  const float* wk    = (const float*)d_in[2];
  const float* wv    = (const float*)d_in[3];
  const float* wproj = (const float*)d_in[4];
  const float* bproj = (const float*)d_in[5];
  const float* wpos  = (const float*)d_in[6];
  const float* ln_g  = (const float*)d_in[7];
  const float* ln_b  = (const float*)d_in[8];
  const float* wff   = (const float*)d_in[9];
  const float* bn1_g = (const float*)d_in[10];
  const float* bn1_b = (const float*)d_in[11];
  const float* wd    = (const float*)d_in[12];
  const float* bn2_g = (const float*)d_in[13];
  const float* bn2_b = (const float*)d_in[14];
  const float* sw1   = (const float*)d_in[15];
  const float* sw2   = (const float*)d_in[16];
  float* out = (float*)d_out;

  cudaFuncSetAttribute(k_gemm<0,0>, cudaFuncAttributeMaxDynamicSharedMemorySize, SM_GEMM_BYTES);
  cudaFuncSetAttribute(k_gemm<1,0>, cudaFuncAttributeMaxDynamicSharedMemorySize, SM_GEMM_BYTES);
  cudaFuncSetAttribute(k_gemm<2,0>, cudaFuncAttributeMaxDynamicSharedMemorySize, SM_GEMM_BYTES);
  cudaFuncSetAttribute(k_gemm<2,1>, cudaFuncAttributeMaxDynamicSharedMemorySize, SM_GEMM_BYTES);
  cudaFuncSetAttribute(k_gemm<3,0>, cudaFuncAttributeMaxDynamicSharedMemorySize, SM_GEMM_BYTES);
  cudaFuncSetAttribute(k_gram,      cudaFuncAttributeMaxDynamicSharedMemorySize, SM_GRAM_BYTES);
  cudaFuncSetAttribute(k_attn_weff, cudaFuncAttributeMaxDynamicSharedMemorySize, 100*1024);

  void *pC = nullptr, *pStats = nullptr, *pPooled = nullptr;
  cudaGetSymbolAddress(&pC, g_C);
  cudaGetSymbolAddress(&pStats, g_stats);
  cudaGetSymbolAddress(&pPooled, g_pooled);

  cudaMemsetAsync(pStats, 0, 256*sizeof(float));
  k_transpose_in<<<dim3(16, 256), 256>>>(x);
  for (int l = 0; l < 2; l++){
    cudaMemsetAsync(pC, 0, 16*4096*sizeof(float));
    k_gram<<<dim3(16, 16), 128, SM_GRAM_BYTES>>>();
    k_attn_weff<<<16, 256, 6*4096*sizeof(float)>>>(wq + l*4096, wk + l*4096, wproj + l*4096);
    k_gemm<0,0><<<dim3(16, 128), 256, SM_GEMM_BYTES>>>(wv + l*4096, nullptr, nullptr);
    k_dwconv<<<dim3(16*128, 8), 256>>>(wpos + l*576);
    k_gemm<1,0><<<dim3(16, 128), 256, SM_GEMM_BYTES>>>(nullptr, bproj + l*64, nullptr);
    if (l == 0)
      k_gemm<2,0><<<dim3(16, 128), 256, SM_GEMM_BYTES>>>(wff + l*4096, ln_g + l*64, ln_b + l*64);
    else
      k_gemm<2,1><<<dim3(16, 128), 256, SM_GEMM_BYTES>>>(wff + l*4096, ln_g + l*64, ln_b + l*64);
  }
  k_gemm<3,0><<<dim3(16, 128), 256, SM_GEMM_BYTES>>>(wd, bn1_g, bn1_b);
  cudaMemsetAsync(pPooled, 0, 16*4096*sizeof(float));
  k_bn2_add_pool<<<dim3(16, 256), 256>>>(x, out, bn2_g, bn2_b);
  k_minmax<<<1, 1024>>>();
  k_gate<<<16, 64>>>(sw1, sw2);
  k_scale<<<65536, 256>>>(out);
}

// round 10
// speedup vs baseline: 2.1845x; 1.0388x over previous
#include <cuda_runtime.h>
#include <cuda_bf16.h>
#include <mma.h>
#include <cstdint>

using namespace nvcuda;

#define B_   16
#define CH_  64
#define TOK  16384
#define CNT  (16.0f*16384.0f)

__device__ float g_XT[B_*TOK*CH_];
__device__ float g_V [B_*TOK*CH_];
__device__ float g_P [B_*TOK*CH_];
__device__ float g_C    [B_*64*64];
__device__ float g_Weff [B_*64*64];
__device__ float g_stats[256];
__device__ float g_pooled[B_*64*64];
__device__ float g_minmax[2];
__device__ float g_gate[B_*64];

__device__ __forceinline__ float leaky(float x){ return x >= 0.f ? x : 0.2f*x; }
__device__ __forceinline__ void split_bf16(float f, __nv_bfloat16& h, __nv_bfloat16& l){
  h = __float2bfloat16_rn(f);
  l = __float2bfloat16_rn(f - __bfloat162float(h));
}

// ---------------- NCHW -> BHWC transpose ----------------
__global__ void k_transpose_in(const float* __restrict__ x){
  int b = blockIdx.x, n0 = blockIdx.y * 64;
  __shared__ float s[64*65];
  const float* xb = x + (size_t)b*CH_*TOK;
  for (int idx = threadIdx.x; idx < 4096; idx += 256){
    int c = idx >> 6, j = idx & 63;
    s[c*65 + j] = xb[(size_t)c*TOK + n0 + j];
  }
  __syncthreads();
  float* xt = g_XT + ((size_t)b*TOK + n0)*CH_;
  for (int idx = threadIdx.x; idx < 4096; idx += 256){
    int j = idx >> 6, c = idx & 63;
    xt[j*CH_ + c] = s[c*65 + j];
  }
}

// =============== wmma GEMM (R9 structure) ===============
// MODE 0: V = XT @ W
// MODE 3: V = BN1(leaky(XT)) @ W ; leaky stats -> g_stats[128..255] (scalar loop)
#define SM_GEMM_BYTES 90112
template<int MODE, int STATS>
__global__ __launch_bounds__(256)
void k_gemm(const float* __restrict__ W, const float* __restrict__ aux0,
            const float* __restrict__ aux1){
  extern __shared__ unsigned char smraw[];
  float* xs = (float*)smraw;
  __nv_bfloat16* Ah = (__nv_bfloat16*)(smraw + 34816);
  __nv_bfloat16* Al = (__nv_bfloat16*)(smraw + 53248);
  __nv_bfloat16* Bh = (__nv_bfloat16*)(smraw + 71680);
  __nv_bfloat16* Bl = (__nv_bfloat16*)(smraw + 80896);
  __shared__ float s_a[64], s_b[64];
  __shared__ float red[512];

  int tid = threadIdx.x, wid = tid >> 5;
  int b = blockIdx.x, n0 = blockIdx.y * 128;

  if (MODE == 3 && tid < 64){
    float m   = g_stats[tid]      * (1.f/CNT);
    float var = g_stats[64 + tid] * (1.f/CNT) - m*m;
    float sc  = aux0[tid] * rsqrtf(var + 1e-4f);
    s_a[tid] = sc; s_b[tid] = aux1[tid] - m*sc;
  }

  const float4* W4 = (const float4*)W;
  for (int i = tid; i < 1024; i += 256){
    float4 v = W4[i];
    int k = i >> 4, n = (i & 15) * 4;
    __nv_bfloat16 h, l;
    split_bf16(v.x, h, l); Bh[k*72+n  ] = h; Bl[k*72+n  ] = l;
    split_bf16(v.y, h, l); Bh[k*72+n+1] = h; Bl[k*72+n+1] = l;
    split_bf16(v.z, h, l); Bh[k*72+n+2] = h; Bl[k*72+n+2] = l;
    split_bf16(v.w, h, l); Bh[k*72+n+3] = h; Bl[k*72+n+3] = l;
  }
  __syncthreads();

  const float4* IN4 = (const float4*)(g_XT + ((size_t)b*TOK + n0)*CH_);
  for (int i = tid; i < 2048; i += 256){
    float4 v = IN4[i];
    int t = i >> 4, c = (i & 15) * 4;
    float f0 = v.x, f1 = v.y, f2 = v.z, f3 = v.w;
    if (MODE == 3){
      f0 = leaky(f0)*s_a[c  ] + s_b[c  ];
      f1 = leaky(f1)*s_a[c+1] + s_b[c+1];
      f2 = leaky(f2)*s_a[c+2] + s_b[c+2];
      f3 = leaky(f3)*s_a[c+3] + s_b[c+3];
    }
    __nv_bfloat16 h, l;
    split_bf16(f0, h, l); Ah[t*72+c  ] = h; Al[t*72+c  ] = l;
    split_bf16(f1, h, l); Ah[t*72+c+1] = h; Al[t*72+c+1] = l;
    split_bf16(f2, h, l); Ah[t*72+c+2] = h; Al[t*72+c+2] = l;
    split_bf16(f3, h, l); Ah[t*72+c+3] = h; Al[t*72+c+3] = l;
  }
  __syncthreads();

  {
    int m0 = wid * 16;
    wmma::fragment<wmma::accumulator,16,16,16,float> acc[4];
#pragma unroll
    for (int j = 0; j < 4; j++) wmma::fill_fragment(acc[j], 0.f);
#pragma unroll
    for (int k = 0; k < 4; k++){
      wmma::fragment<wmma::matrix_a,16,16,16,__nv_bfloat16,wmma::row_major> ah, al;
      wmma::load_matrix_sync(ah, Ah + m0*72 + k*16, 72);
      wmma::load_matrix_sync(al, Al + m0*72 + k*16, 72);
#pragma unroll
      for (int j = 0; j < 4; j++){
        wmma::fragment<wmma::matrix_b,16,16,16,__nv_bfloat16,wmma::row_major> bh, bl;
        wmma::load_matrix_sync(bh, Bh + (k*16)*72 + j*16, 72);
        wmma::load_matrix_sync(bl, Bl + (k*16)*72 + j*16, 72);
        wmma::mma_sync(acc[j], ah, bh, acc[j]);
        wmma::mma_sync(acc[j], ah, bl, acc[j]);
        wmma::mma_sync(acc[j], al, bh, acc[j]);
      }
    }
    __syncthreads();
#pragma unroll
    for (int j = 0; j < 4; j++)
      wmma::store_matrix_sync(xs + m0*68 + j*16, acc[j], 68, wmma::mem_row_major);
  }
  __syncthreads();

  float s = 0.f, ss = 0.f;
  if (MODE == 0){
    float4* O4 = (float4*)(g_V + ((size_t)b*TOK + n0)*CH_);
    for (int i = tid; i < 2048; i += 256){
      int t = i >> 4, c = (i & 15) * 4;
      O4[i] = *(float4*)&xs[t*68 + c];
    }
  } else {
    float* O = g_V + ((size_t)b*TOK + n0)*CH_;
    for (int idx = tid; idx < 8192; idx += 256){
      float f = xs[(idx>>6)*68 + (idx&63)];
      O[idx] = f;
      float lf = leaky(f); s += lf; ss = fmaf(lf, lf, ss);
    }
  }
  if (MODE == 3){
    red[tid] = s; red[256 + tid] = ss;
    __syncthreads();
    if (tid < 64){
      atomicAdd(&g_stats[128 + tid],
                red[tid] + red[tid+64] + red[tid+128] + red[tid+192]);
      atomicAdd(&g_stats[192 + tid],
                red[256+tid] + red[320+tid] + red[384+tid] + red[448+tid]);
    }
  }
}

// ====== fused: XT' = Y + LN(Y)@wff,  Y = XT + (V@Weff + bproj)*P ======
// STATS=1: leaky stats of XT' -> g_stats[0..127] (scalar channel-pure loop)
// smem identical budget to k_gemm: 90112. wff re-staged into Bh/Bl after MMA1;
// MMA2 output stored into Ah/Al region reinterpreted as float (outF).
#define SM_F_BYTES 90112
template<int STATS>
__global__ __launch_bounds__(256)
void k_fused12(const float* __restrict__ wff, const float* __restrict__ bproj,
               const float* __restrict__ lng, const float* __restrict__ lnb){
  extern __shared__ unsigned char smraw[];
  float* xs = (float*)smraw;                                  // [128][68] f32
  __nv_bfloat16* Ah = (__nv_bfloat16*)(smraw + 34816);
  __nv_bfloat16* Al = (__nv_bfloat16*)(smraw + 53248);
  __nv_bfloat16* Bh = (__nv_bfloat16*)(smraw + 71680);
  __nv_bfloat16* Bl = (__nv_bfloat16*)(smraw + 80896);
  float* outF = (float*)(smraw + 34816);                      // aliases Ah/Al (needs 34816 <= 36864)
  __shared__ float s_bias[64], s_g[64], s_bb[64];
  __shared__ float red[512];

  int tid = threadIdx.x, wid = tid >> 5;
  int b = blockIdx.x, n0 = blockIdx.y * 128;
  int m0 = wid * 16;

  if (tid < 64){ s_bias[tid] = bproj[tid]; s_g[tid] = lng[tid]; s_bb[tid] = lnb[tid]; }

  // stage V -> Ah/Al ; Weff -> Bh/Bl
  const float4* IN4 = (const float4*)(g_V + ((size_t)b*TOK + n0)*CH_);
  for (int i = tid; i < 2048; i += 256){
    float4 v = IN4[i];
    int t = i >> 4, c = (i & 15) * 4;
    __nv_bfloat16 h, l;
    split_bf16(v.x, h, l); Ah[t*72+c  ] = h; Al[t*72+c  ] = l;
    split_bf16(v.y, h, l); Ah[t*72+c+1] = h; Al[t*72+c+1] = l;
    split_bf16(v.z, h, l); Ah[t*72+c+2] = h; Al[t*72+c+2] = l;
    split_bf16(v.w, h, l); Ah[t*72+c+3] = h; Al[t*72+c+3] = l;
  }
  const float4* WE4 = (const float4*)(g_Weff + b*4096);
  for (int i = tid; i < 1024; i += 256){
    float4 v = WE4[i];
    int k = i >> 4, n = (i & 15) * 4;
    __nv_bfloat16 h, l;
    split_bf16(v.x, h, l); Bh[k*72+n  ] = h; Bl[k*72+n  ] = l;
    split_bf16(v.y, h, l); Bh[k*72+n+1] = h; Bl[k*72+n+1] = l;
    split_bf16(v.z, h, l); Bh[k*72+n+2] = h; Bl[k*72+n+2] = l;
    split_bf16(v.w, h, l); Bh[k*72+n+3] = h; Bl[k*72+n+3] = l;
  }
  __syncthreads();

  // MMA1: V @ Weff -> xs
  {
    wmma::fragment<wmma::accumulator,16,16,16,float> acc[4];
#pragma unroll
    for (int j = 0; j < 4; j++) wmma::fill_fragment(acc[j], 0.f);
#pragma unroll
    for (int k = 0; k < 4; k++){
      wmma::fragment<wmma::matrix_a,16,16,16,__nv_bfloat16,wmma::row_major> ah, al;
      wmma::load_matrix_sync(ah, Ah + m0*72 + k*16, 72);
      wmma::load_matrix_sync(al, Al + m0*72 + k*16, 72);
#pragma unroll
      for (int j = 0; j < 4; j++){
        wmma::fragment<wmma::matrix_b,16,16,16,__nv_bfloat16,wmma::row_major> bh, bl;
        wmma::load_matrix_sync(bh, Bh + (k*16)*72 + j*16, 72);
        wmma::load_matrix_sync(bl, Bl + (k*16)*72 + j*16, 72);
        wmma::mma_sync(acc[j], ah, bh, acc[j]);
        wmma::mma_sync(acc[j], ah, bl, acc[j]);
        wmma::mma_sync(acc[j], al, bh, acc[j]);
      }
    }
    __syncthreads();   // all MMA1 fragment reads of Ah/Al/Bh/Bl complete
#pragma unroll
    for (int j = 0; j < 4; j++)
      wmma::store_matrix_sync(xs + m0*68 + j*16, acc[j], 68, wmma::mem_row_major);
  }
  __syncthreads();

  // Y = XT + (xs + bias)*P -> xs ; concurrently restage wff -> Bh/Bl
  {
    const float4* XT4 = (const float4*)(g_XT + ((size_t)b*TOK + n0)*CH_);
    const float4* P4  = (const float4*)(g_P  + ((size_t)b*TOK + n0)*CH_);
    for (int i = tid; i < 2048; i += 256){
      int t = i >> 4, c = (i & 15) * 4;
      float4 xv = XT4[i], pv = P4[i];
      float* o = &xs[t*68 + c];
      o[0] = xv.x + (o[0] + s_bias[c  ]) * pv.x;
      o[1] = xv.y + (o[1] + s_bias[c+1]) * pv.y;
      o[2] = xv.z + (o[2] + s_bias[c+2]) * pv.z;
      o[3] = xv.w + (o[3] + s_bias[c+3]) * pv.w;
    }
    const float4* WF4 = (const float4*)wff;
    for (int i = tid; i < 1024; i += 256){
      float4 v = WF4[i];
      int k = i >> 4, n = (i & 15) * 4;
      __nv_bfloat16 h, l;
      split_bf16(v.x, h, l); Bh[k*72+n  ] = h; Bl[k*72+n  ] = l;
      split_bf16(v.y, h, l); Bh[k*72+n+1] = h; Bl[k*72+n+1] = l;
      split_bf16(v.z, h, l); Bh[k*72+n+2] = h; Bl[k*72+n+2] = l;
      split_bf16(v.w, h, l); Bh[k*72+n+3] = h; Bl[k*72+n+3] = l;
    }
  }
  __syncthreads();

  // LN(Y) -> Ah/Al (row per thread, tid < 128; same proven scheme as R9 MODE 2)
  if (tid < 128){
    const float* row = &xs[tid*68];
    float s = 0.f, ss = 0.f;
#pragma unroll
    for (int c = 0; c < 64; c++){ float xv = row[c]; s += xv; ss = fmaf(xv, xv, ss); }
    float mean = s * (1.f/64.f);
    float rstd = rsqrtf(ss*(1.f/64.f) - mean*mean + 1e-5f);
#pragma unroll
    for (int c = 0; c < 64; c++){
      float f = (row[c] - mean) * rstd * s_g[c] + s_bb[c];
      __nv_bfloat16 h, l; split_bf16(f, h, l);
      Ah[tid*72 + c] = h; Al[tid*72 + c] = l;
    }
  }
  __syncthreads();

  // MMA2: LN(Y) @ wff -> outF (aliases Ah/Al; sync before store)
  {
    wmma::fragment<wmma::accumulator,16,16,16,float> acc[4];
#pragma unroll
    for (int j = 0; j < 4; j++) wmma::fill_fragment(acc[j], 0.f);
#pragma unroll
    for (int k = 0; k < 4; k++){
      wmma::fragment<wmma::matrix_a,16,16,16,__nv_bfloat16,wmma::row_major> ah, al;
      wmma::load_matrix_sync(ah, Ah + m0*72 + k*16, 72);
      wmma::load_matrix_sync(al, Al + m0*72 + k*16, 72);
#pragma unroll
      for (int j = 0; j < 4; j++){
        wmma::fragment<wmma::matrix_b,16,16,16,__nv_bfloat16,wmma::row_major> bh, bl;
        wmma::load_matrix_sync(bh, Bh + (k*16)*72 + j*16, 72);
        wmma::load_matrix_sync(bl, Bl + (k*16)*72 + j*16, 72);
        wmma::mma_sync(acc[j], ah, bh, acc[j]);
        wmma::mma_sync(acc[j], ah, bl, acc[j]);
        wmma::mma_sync(acc[j], al, bh, acc[j]);
      }
    }
    __syncthreads();   // all MMA2 fragment reads done before outF overwrites Ah/Al
#pragma unroll
    for (int j = 0; j < 4; j++)
      wmma::store_matrix_sync(outF + m0*68 + j*16, acc[j], 68, wmma::mem_row_major);
  }
  __syncthreads();

  // XT' = Y + FF
  float s = 0.f, ss = 0.f;
  if (STATS){
    float* XT = g_XT + ((size_t)b*TOK + n0)*CH_;
    for (int idx = tid; idx < 8192; idx += 256){
      float nv = xs[(idx>>6)*68 + (idx&63)] + outF[(idx>>6)*68 + (idx&63)];
      XT[idx] = nv;
      float lf = leaky(nv); s += lf; ss = fmaf(lf, lf, ss);
    }
    red[tid] = s; red[256 + tid] = ss;
    __syncthreads();
    if (tid < 64){
      atomicAdd(&g_stats[tid],
                red[tid] + red[tid+64] + red[tid+128] + red[tid+192]);
      atomicAdd(&g_stats[64 + tid],
                red[256+tid] + red[320+tid] + red[384+tid] + red[448+tid]);
    }
  } else {
    float4* XT4 = (float4*)(g_XT + ((size_t)b*TOK + n0)*CH_);
    for (int i = tid; i < 2048; i += 256){
      int t = i >> 4, c = (i & 15) * 4;
      float4 o;
      o.x = xs[t*68+c  ] + outF[t*68+c  ];
      o.y = xs[t*68+c+1] + outF[t*68+c+1];
      o.z = xs[t*68+c+2] + outF[t*68+c+2];
      o.w = xs[t*68+c+3] + outF[t*68+c+3];
      XT4[i] = o;
    }
  }
}

// =============== wmma gram (R9 verbatim) ===============
#define SM_GRAM_BYTES 36864
__global__ __launch_bounds__(128)
void k_gram(){
  extern __shared__ unsigned char smraw[];
  __nv_bfloat16* Ah = (__nv_bfloat16*)smraw;
  __nv_bfloat16* Al = (__nv_bfloat16*)(smraw + 18432);
  int tid = threadIdx.x, wid = tid >> 5;
  int b = blockIdx.x;

  wmma::fragment<wmma::accumulator,16,16,16,float> acc[4];
#pragma unroll
  for (int j = 0; j < 4; j++) wmma::fill_fragment(acc[j], 0.f);

  for (int st = 0; st < 8; st++){
    int n0 = (blockIdx.y * 8 + st) * 128;
    const float* IN = g_XT + ((size_t)b*TOK + n0)*CH_;
    __syncthreads();
    for (int idx = tid; idx < 8192; idx += 128){
      int t = idx >> 6, c = idx & 63;
      __nv_bfloat16 h, l; split_bf16(IN[idx], h, l);
      Ah[t*72 + c] = h; Al[t*72 + c] = l;
    }
    __syncthreads();
#pragma unroll
    for (int k = 0; k < 8; k++){
      wmma::fragment<wmma::matrix_a,16,16,16,__nv_bfloat16,wmma::col_major> ah, al;
      wmma::load_matrix_sync(ah, Ah + wid*16 + (k*16)*72, 72);
      wmma::load_matrix_sync(al, Al + wid*16 + (k*16)*72, 72);
#pragma unroll
      for (int j = 0; j < 4; j++){
        wmma::fragment<wmma::matrix_b,16,16,16,__nv_bfloat16,wmma::row_major> bh, bl;
        wmma::load_matrix_sync(bh, Ah + (k*16)*72 + j*16, 72);
        wmma::load_matrix_sync(bl, Al + (k*16)*72 + j*16, 72);
        wmma::mma_sync(acc[j], ah, bh, acc[j]);
        wmma::mma_sync(acc[j], ah, bl, acc[j]);
        wmma::mma_sync(acc[j], al, bh, acc[j]);
      }
    }
  }
  __syncthreads();
  float* outF = (float*)smraw;
#pragma unroll
  for (int j = 0; j < 4; j++)
    wmma::store_matrix_sync(outF + (wid*16)*68 + j*16, acc[j], 68, wmma::mem_row_major);
  __syncthreads();
  for (int idx = tid; idx < 4096; idx += 128)
    atomicAdd(&g_C[b*4096 + idx], outF[(idx>>6)*68 + (idx&63)]);
}

// ------- per-batch attention stats + fold into Weff -------
__global__ void k_attn_weff(const float* __restrict__ wq, const float* __restrict__ wk,
                            const float* __restrict__ wproj){
  extern __shared__ float sm[];
  float* Cs  = sm;
  float* wqs = sm + 4096;
  float* wks = sm + 8192;
  float* wps = sm + 12288;
  float* T1  = sm + 16384;
  float* T2  = sm + 20480;
  __shared__ float attn_s[512];
  __shared__ float qq[64], kk[64];
  int b = blockIdx.x;
  for (int i = threadIdx.x; i < 4096; i += 256){
    Cs[i]  = g_C[b*4096 + i];
    wqs[i] = wq[i]; wks[i] = wk[i]; wps[i] = wproj[i];
  }
  __syncthreads();
  for (int i = threadIdx.x; i < 4096; i += 256){
    int r = i >> 6, e = i & 63; float s1 = 0.f, s2 = 0.f;
    for (int c = 0; c < 64; c++){
      float cv = Cs[r*64 + c];
      s1 = fmaf(cv, wqs[c*64 + e], s1);
      s2 = fmaf(cv, wks[c*64 + e], s2);
    }
    T1[i] = s1; T2[i] = s2;
  }
  __syncthreads();
  if (threadIdx.x < 64){
    int e = threadIdx.x; float s1 = 0.f, s2 = 0.f;
    for (int c = 0; c < 64; c++){
      s1 = fmaf(wqs[c*64 + e], T1[c*64 + e], s1);
      s2 = fmaf(wks[c*64 + e], T2[c*64 + e], s2);
    }
    qq[e] = s1; kk[e] = s2;
  }
  __syncthreads();
  if (threadIdx.x < 64){
    int h = threadIdx.x >> 3, dd = threadIdx.x & 7;
    float nk = fmaxf(sqrtf(kk[h*8 + dd]), 1e-12f);
    float lo[8]; float mx = -3.4e38f;
#pragma unroll
    for (int e = 0; e < 8; e++){
      float gg = 0.f;
      for (int c = 0; c < 64; c++)
        gg = fmaf(wks[c*64 + h*8 + dd], T1[c*64 + h*8 + e], gg);
      float nq = fmaxf(sqrtf(qq[h*8 + e]), 1e-12f);
      lo[e] = gg / (nk * nq);
      mx = fmaxf(mx, lo[e]);
    }
    float sum = 0.f;
#pragma unroll
    for (int e = 0; e < 8; e++){ lo[e] = expf(lo[e] - mx); sum += lo[e]; }
    float inv = 1.f / sum;
#pragma unroll
    for (int e = 0; e < 8; e++) attn_s[(h*8 + dd)*8 + e] = lo[e] * inv;
  }
  __syncthreads();
  for (int i = threadIdx.x; i < 4096; i += 256){
    int cin = i >> 6, oc = i & 63;
    int h = cin >> 3, e = cin & 7;
    float s = 0.f;
#pragma unroll
    for (int dd = 0; dd < 8; dd++)
      s = fmaf(attn_s[(h*8 + dd)*8 + e], wps[(h*8 + dd)*64 + oc], s);
    g_Weff[b*4096 + i] = s;
  }
}

// ---------------- depthwise 3x3 on V -> P ----------------
__global__ void k_dwconv(const float* __restrict__ wpos){
  int bh = blockIdx.x; int b = bh >> 7; int y = bh & 127;
  int cg = threadIdx.x & 15;
  int x  = blockIdx.y * 16 + (threadIdx.x >> 4);
  __shared__ float wp[576];
  for (int i = threadIdx.x; i < 576; i += 256) wp[i] = wpos[i];
  __syncthreads();
  float a0 = 0.f, a1 = 0.f, a2 = 0.f, a3 = 0.f;
  const float* Vb = g_V + (size_t)b*TOK*CH_;
#pragma unroll
  for (int ky = 0; ky < 3; ky++){
    int yy = y + ky - 1; if (yy < 0 || yy > 127) continue;
#pragma unroll
    for (int kx = 0; kx < 3; kx++){
      int xx = x + kx - 1; if (xx < 0 || xx > 127) continue;
      float4 v = *(const float4*)&Vb[((size_t)yy*128 + xx)*64 + cg*4];
      int wi = ky*3 + kx;
      a0 = fmaf(v.x, wp[(cg*4+0)*9 + wi], a0);
      a1 = fmaf(v.y, wp[(cg*4+1)*9 + wi], a1);
      a2 = fmaf(v.z, wp[(cg*4+2)*9 + wi], a2);
      a3 = fmaf(v.w, wp[(cg*4+3)*9 + wi], a3);
    }
  }
  *(float4*)&g_P[((size_t)b*TOK + y*128 + x)*64 + cg*4] = make_float4(a0,a1,a2,a3);
}

// ---- BN2 + residual + NCHW out + pooled sums ----
__global__ void k_bn2_add_pool(const float* __restrict__ x_orig, float* __restrict__ out,
                               const float* __restrict__ g2, const float* __restrict__ b2){
  int b = blockIdx.x, n0 = blockIdx.y * 64;
  __shared__ float s[64*65];
  __shared__ float scale[64], shift[64];
  if (threadIdx.x < 64){
    int c = threadIdx.x;
    float m   = g_stats[128 + c] * (1.f/CNT);
    float var = g_stats[192 + c] * (1.f/CNT) - m*m;
    float sc  = g2[c] * rsqrtf(var + 1e-4f);
    scale[c] = sc; shift[c] = b2[c] - m*sc;
  }
  const float* R = g_V + ((size_t)b*TOK + n0)*CH_;
  for (int idx = threadIdx.x; idx < 4096; idx += 256){
    int t = idx >> 6, c = idx & 63;
    s[t*65 + c] = R[idx];
  }
  __syncthreads();
  int y = n0 >> 7, x0 = n0 & 127;
  int iblk = y >> 4, jbase = x0 >> 4;
  const float* xb = x_orig + (size_t)b*CH_*TOK;
  float* ob = out + (size_t)b*CH_*TOK;
  for (int idx = threadIdx.x; idx < 4096; idx += 256){
    int c = idx >> 6, j = idx & 63;
    float f = leaky(s[j*65 + c]) * scale[c] + shift[c];
    size_t off = (size_t)c*TOK + n0 + j;
    float sval = f + xb[off];
    ob[off] = sval;
    float r = sval;
    r += __shfl_down_sync(0xffffffffu, r, 8, 16);
    r += __shfl_down_sync(0xffffffffu, r, 4, 16);
    r += __shfl_down_sync(0xffffffffu, r, 2, 16);
    r += __shfl_down_sync(0xffffffffu, r, 1, 16);
    if ((threadIdx.x & 15) == 0)
      atomicAdd(&g_pooled[(b*64 + c)*64 + iblk*8 + jbase + (j >> 4)], r);
  }
}

__global__ void k_minmax(){
  float mn = 3.4e38f, mx = -3.4e38f;
  for (int i = threadIdx.x; i < B_*4096; i += 1024){
    float v = g_pooled[i] * (1.f/256.f);
    mn = fminf(mn, v); mx = fmaxf(mx, v);
  }
#pragma unroll
  for (int o = 16; o > 0; o >>= 1){
    mn = fminf(mn, __shfl_xor_sync(0xffffffffu, mn, o));
    mx = fmaxf(mx, __shfl_xor_sync(0xffffffffu, mx, o));
  }
  __shared__ float smn[32], smx[32];
  if ((threadIdx.x & 31) == 0){ smn[threadIdx.x >> 5] = mn; smx[threadIdx.x >> 5] = mx; }
  __syncthreads();
  if (threadIdx.x < 32){
    mn = smn[threadIdx.x]; mx = smx[threadIdx.x];
#pragma unroll
    for (int o = 16; o > 0; o >>= 1){
      mn = fminf(mn, __shfl_xor_sync(0xffffffffu, mn, o));
      mx = fmaxf(mx, __shfl_xor_sync(0xffffffffu, mx, o));
    }
    if (threadIdx.x == 0){ g_minmax[0] = mn; g_minmax[1] = mx; }
  }
}

__global__ void k_gate(const float* __restrict__ w1, const float* __restrict__ w2){
  int b = blockIdx.x;
  __shared__ float y[4096];
  __shared__ float S[64];
  __shared__ float g0[64];
  __shared__ float hid[4];
  float mn = g_minmax[0];
  float inv = 1.f / (g_minmax[1] - mn);
  for (int i = threadIdx.x; i < 4096; i += 64)
    y[i] = (g_pooled[b*4096 + i] * (1.f/256.f) - mn) * inv;
  __syncthreads();
  {
    int i = threadIdx.x; float s = 0.f;
    for (int c = 0; c < 64; c++) s += y[c*64 + i];
    S[i] = s;
  }
  __syncthreads();
  {
    int c = threadIdx.x; float s = 0.f, sm2 = 0.f;
    for (int i = 0; i < 64; i++){
      s = fmaf(y[c*64 + i], S[i], s);
      sm2 += g_pooled[b*4096 + c*64 + i];
    }
    g0[c] = (s * (1.f/64.f)) * (sm2 * (1.f/16384.f));
  }
  __syncthreads();
  if (threadIdx.x < 4){
    int j = threadIdx.x; float h = 0.f;
    for (int c = 0; c < 64; c++) h = fmaf(g0[c], w1[c*4 + j], h);
    hid[j] = leaky(h);
  }
  __syncthreads();
  {
    int c = threadIdx.x; float o = 0.f;
#pragma unroll
    for (int j = 0; j < 4; j++) o = fmaf(hid[j], w2[j*64 + c], o);
    g_gate[b*64 + c] = 1.f / (1.f + expf(-o));
  }
}

__global__ void k_scale(float* __restrict__ out){
  size_t i = (size_t)blockIdx.x * 256 + threadIdx.x;
  out[i] *= g_gate[i >> 14];
}

// ================================ launch ========================================
extern "C" void kernel_launch(void* const* d_in, const int* in_sizes, int n_in,
                              void* d_out, int out_size){
  const float* x     = (const float*)d_in[0];
  const float* wq    = (const float*)d_in[1];
  const float* wk    = (const float*)d_in[2];
  const float* wv    = (const float*)d_in[3];
  const float* wproj = (const float*)d_in[4];
  const float* bproj = (const float*)d_in[5];
  const float* wpos  = (const float*)d_in[6];
  const float* ln_g  = (const float*)d_in[7];
  const float* ln_b  = (const float*)d_in[8];
  const float* wff   = (const float*)d_in[9];
  const float* bn1_g = (const float*)d_in[10];
  const float* bn1_b = (const float*)d_in[11];
  const float* wd    = (const float*)d_in[12];
  const float* bn2_g = (const float*)d_in[13];
  const float* bn2_b = (const float*)d_in[14];
  const float* sw1   = (const float*)d_in[15];
  const float* sw2   = (const float*)d_in[16];
  float* out = (float*)d_out;

  cudaFuncSetAttribute(k_gemm<0,0>,  cudaFuncAttributeMaxDynamicSharedMemorySize, SM_GEMM_BYTES);
  cudaFuncSetAttribute(k_gemm<3,0>,  cudaFuncAttributeMaxDynamicSharedMemorySize, SM_GEMM_BYTES);
  cudaFuncSetAttribute(k_fused12<0>, cudaFuncAttributeMaxDynamicSharedMemorySize, SM_F_BYTES);
  cudaFuncSetAttribute(k_fused12<1>, cudaFuncAttributeMaxDynamicSharedMemorySize, SM_F_BYTES);
  cudaFuncSetAttribute(k_gram,       cudaFuncAttributeMaxDynamicSharedMemorySize, SM_GRAM_BYTES);
  cudaFuncSetAttribute(k_attn_weff,  cudaFuncAttributeMaxDynamicSharedMemorySize, 100*1024);

  void *pC = nullptr, *pStats = nullptr, *pPooled = nullptr;
  cudaGetSymbolAddress(&pC, g_C);
  cudaGetSymbolAddress(&pStats, g_stats);
  cudaGetSymbolAddress(&pPooled, g_pooled);

  cudaMemsetAsync(pStats, 0, 256*sizeof(float));
  k_transpose_in<<<dim3(16, 256), 256>>>(x);
  for (int l = 0; l < 2; l++){
    cudaMemsetAsync(pC, 0, 16*4096*sizeof(float));
    k_gram<<<dim3(16, 16), 128, SM_GRAM_BYTES>>>();
    k_attn_weff<<<16, 256, 6*4096*sizeof(float)>>>(wq + l*4096, wk + l*4096, wproj + l*4096);
    k_gemm<0,0><<<dim3(16, 128), 256, SM_GEMM_BYTES>>>(wv + l*4096, nullptr, nullptr);
    k_dwconv<<<dim3(16*128, 8), 256>>>(wpos + l*576);
    if (l == 0)
      k_fused12<0><<<dim3(16, 128), 256, SM_F_BYTES>>>(wff + l*4096, bproj + l*64, ln_g + l*64, ln_b + l*64);
    else
      k_fused12<1><<<dim3(16, 128), 256, SM_F_BYTES>>>(wff + l*4096, bproj + l*64, ln_g + l*64, ln_b + l*64);
  }
  k_gemm<3,0><<<dim3(16, 128), 256, SM_GEMM_BYTES>>>(wd, bn1_g, bn1_b);
  cudaMemsetAsync(pPooled, 0, 16*4096*sizeof(float));
  k_bn2_add_pool<<<dim3(16, 256), 256>>>(x, out, bn2_g, bn2_b);
  k_minmax<<<1, 1024>>>();
  k_gate<<<16, 64>>>(sw1, sw2);
  k_scale<<<65536, 256>>>(out);
}

// round 11
// speedup vs baseline: 2.3281x; 1.0658x over previous
#include <cuda_runtime.h>
#include <cuda_bf16.h>
#include <mma.h>
#include <cstdint>

using namespace nvcuda;

#define B_   16
#define CH_  64
#define TOK  16384
#define CNT  (16.0f*16384.0f)

__device__ float g_XT[B_*TOK*CH_];
__device__ float g_V [B_*TOK*CH_];
__device__ float g_P [B_*TOK*CH_];
__device__ float g_C    [B_*64*64];
__device__ float g_Weff [B_*64*64];
__device__ float g_stats[256];
__device__ float g_pooled[B_*64*64];
__device__ float g_minmax[2];
__device__ float g_gate[B_*64];

__device__ __forceinline__ float leaky(float x){ return x >= 0.f ? x : 0.2f*x; }
__device__ __forceinline__ void split_bf16(float f, __nv_bfloat16& h, __nv_bfloat16& l){
  h = __float2bfloat16_rn(f);
  l = __float2bfloat16_rn(f - __bfloat162float(h));
}

// ---------------- NCHW -> BHWC transpose ----------------
__global__ void k_transpose_in(const float* __restrict__ x){
  int b = blockIdx.x, n0 = blockIdx.y * 64;
  __shared__ float s[64*65];
  const float* xb = x + (size_t)b*CH_*TOK;
  for (int idx = threadIdx.x; idx < 4096; idx += 256){
    int c = idx >> 6, j = idx & 63;
    s[c*65 + j] = xb[(size_t)c*TOK + n0 + j];
  }
  __syncthreads();
  float* xt = g_XT + ((size_t)b*TOK + n0)*CH_;
  for (int idx = threadIdx.x; idx < 4096; idx += 256){
    int j = idx >> 6, c = idx & 63;
    xt[j*CH_ + c] = s[c*65 + j];
  }
}

// =============== wmma GEMM — slim smem (55296B -> 4 CTAs/SM) ===============
// MODE 0: V = XT @ W                 (direct global accumulator store)
// MODE 3: V = BN1(leaky(XT)) @ W ; leaky stats -> g_stats[128..255]
// smem: Ah bf16[128][72] @0 (18432) | Al @18432 (18432) | Bh @36864 (9216) | Bl @46080 (9216) = 55296
// MODE 3 outF (f32 [128][68] = 34816B) aliases Ah/Al after MMA.
#define SM_GEMM_BYTES 55296
template<int MODE>
__global__ __launch_bounds__(256)
void k_gemm(const float* __restrict__ W, const float* __restrict__ aux0,
            const float* __restrict__ aux1){
  extern __shared__ unsigned char smraw[];
  __nv_bfloat16* Ah = (__nv_bfloat16*)smraw;
  __nv_bfloat16* Al = (__nv_bfloat16*)(smraw + 18432);
  __nv_bfloat16* Bh = (__nv_bfloat16*)(smraw + 36864);
  __nv_bfloat16* Bl = (__nv_bfloat16*)(smraw + 46080);
  float* outF = (float*)smraw;   // MODE 3: aliases Ah/Al after MMA
  __shared__ float s_a[64], s_b[64];
  __shared__ float red[512];

  int tid = threadIdx.x, wid = tid >> 5;
  int b = blockIdx.x, n0 = blockIdx.y * 128;
  int m0 = wid * 16;

  if (MODE == 3 && tid < 64){
    float m   = g_stats[tid]      * (1.f/CNT);
    float var = g_stats[64 + tid] * (1.f/CNT) - m*m;
    float sc  = aux0[tid] * rsqrtf(var + 1e-4f);
    s_a[tid] = sc; s_b[tid] = aux1[tid] - m*sc;
  }

  const float4* W4 = (const float4*)W;
  for (int i = tid; i < 1024; i += 256){
    float4 v = W4[i];
    int k = i >> 4, n = (i & 15) * 4;
    __nv_bfloat16 h, l;
    split_bf16(v.x, h, l); Bh[k*72+n  ] = h; Bl[k*72+n  ] = l;
    split_bf16(v.y, h, l); Bh[k*72+n+1] = h; Bl[k*72+n+1] = l;
    split_bf16(v.z, h, l); Bh[k*72+n+2] = h; Bl[k*72+n+2] = l;
    split_bf16(v.w, h, l); Bh[k*72+n+3] = h; Bl[k*72+n+3] = l;
  }
  __syncthreads();   // s_a/s_b ready for MODE 3 staging

  const float4* IN4 = (const float4*)(g_XT + ((size_t)b*TOK + n0)*CH_);
  for (int i = tid; i < 2048; i += 256){
    float4 v = IN4[i];
    int t = i >> 4, c = (i & 15) * 4;
    float f0 = v.x, f1 = v.y, f2 = v.z, f3 = v.w;
    if (MODE == 3){
      f0 = leaky(f0)*s_a[c  ] + s_b[c  ];
      f1 = leaky(f1)*s_a[c+1] + s_b[c+1];
      f2 = leaky(f2)*s_a[c+2] + s_b[c+2];
      f3 = leaky(f3)*s_a[c+3] + s_b[c+3];
    }
    __nv_bfloat16 h, l;
    split_bf16(f0, h, l); Ah[t*72+c  ] = h; Al[t*72+c  ] = l;
    split_bf16(f1, h, l); Ah[t*72+c+1] = h; Al[t*72+c+1] = l;
    split_bf16(f2, h, l); Ah[t*72+c+2] = h; Al[t*72+c+2] = l;
    split_bf16(f3, h, l); Ah[t*72+c+3] = h; Al[t*72+c+3] = l;
  }
  __syncthreads();

  wmma::fragment<wmma::accumulator,16,16,16,float> acc[4];
#pragma unroll
  for (int j = 0; j < 4; j++) wmma::fill_fragment(acc[j], 0.f);
#pragma unroll
  for (int k = 0; k < 4; k++){
    wmma::fragment<wmma::matrix_a,16,16,16,__nv_bfloat16,wmma::row_major> ah, al;
    wmma::load_matrix_sync(ah, Ah + m0*72 + k*16, 72);
    wmma::load_matrix_sync(al, Al + m0*72 + k*16, 72);
#pragma unroll
    for (int j = 0; j < 4; j++){
      wmma::fragment<wmma::matrix_b,16,16,16,__nv_bfloat16,wmma::row_major> bh, bl;
      wmma::load_matrix_sync(bh, Bh + (k*16)*72 + j*16, 72);
      wmma::load_matrix_sync(bl, Bl + (k*16)*72 + j*16, 72);
      wmma::mma_sync(acc[j], ah, bh, acc[j]);
      wmma::mma_sync(acc[j], ah, bl, acc[j]);
      wmma::mma_sync(acc[j], al, bh, acc[j]);
    }
  }

  if (MODE == 0){
    // direct global store (row stride 64 floats)
    float* O = g_V + ((size_t)b*TOK + n0 + m0)*CH_;
#pragma unroll
    for (int j = 0; j < 4; j++)
      wmma::store_matrix_sync(O + j*16, acc[j], 64, wmma::mem_row_major);
  } else {
    __syncthreads();   // all fragment reads of Ah/Al done before outF overwrite
#pragma unroll
    for (int j = 0; j < 4; j++)
      wmma::store_matrix_sync(outF + m0*68 + j*16, acc[j], 68, wmma::mem_row_major);
    __syncthreads();
    float* O = g_V + ((size_t)b*TOK + n0)*CH_;
    float s = 0.f, ss = 0.f;
    for (int idx = tid; idx < 8192; idx += 256){
      float f = outF[(idx>>6)*68 + (idx&63)];
      O[idx] = f;
      float lf = leaky(f); s += lf; ss = fmaf(lf, lf, ss);
    }
    red[tid] = s; red[256 + tid] = ss;
    __syncthreads();
    if (tid < 64){
      atomicAdd(&g_stats[128 + tid],
                red[tid] + red[tid+64] + red[tid+128] + red[tid+192]);
      atomicAdd(&g_stats[192 + tid],
                red[256+tid] + red[320+tid] + red[384+tid] + red[448+tid]);
    }
  }
}

// ====== fused attn-epilogue + LN-FF (R10 verbatim) ======
#define SM_F_BYTES 90112
template<int STATS>
__global__ __launch_bounds__(256)
void k_fused12(const float* __restrict__ wff, const float* __restrict__ bproj,
               const float* __restrict__ lng, const float* __restrict__ lnb){
  extern __shared__ unsigned char smraw[];
  float* xs = (float*)smraw;
  __nv_bfloat16* Ah = (__nv_bfloat16*)(smraw + 34816);
  __nv_bfloat16* Al = (__nv_bfloat16*)(smraw + 53248);
  __nv_bfloat16* Bh = (__nv_bfloat16*)(smraw + 71680);
  __nv_bfloat16* Bl = (__nv_bfloat16*)(smraw + 80896);
  float* outF = (float*)(smraw + 34816);
  __shared__ float s_bias[64], s_g[64], s_bb[64];
  __shared__ float red[512];

  int tid = threadIdx.x, wid = tid >> 5;
  int b = blockIdx.x, n0 = blockIdx.y * 128;
  int m0 = wid * 16;

  if (tid < 64){ s_bias[tid] = bproj[tid]; s_g[tid] = lng[tid]; s_bb[tid] = lnb[tid]; }

  const float4* IN4 = (const float4*)(g_V + ((size_t)b*TOK + n0)*CH_);
  for (int i = tid; i < 2048; i += 256){
    float4 v = IN4[i];
    int t = i >> 4, c = (i & 15) * 4;
    __nv_bfloat16 h, l;
    split_bf16(v.x, h, l); Ah[t*72+c  ] = h; Al[t*72+c  ] = l;
    split_bf16(v.y, h, l); Ah[t*72+c+1] = h; Al[t*72+c+1] = l;
    split_bf16(v.z, h, l); Ah[t*72+c+2] = h; Al[t*72+c+2] = l;
    split_bf16(v.w, h, l); Ah[t*72+c+3] = h; Al[t*72+c+3] = l;
  }
  const float4* WE4 = (const float4*)(g_Weff + b*4096);
  for (int i = tid; i < 1024; i += 256){
    float4 v = WE4[i];
    int k = i >> 4, n = (i & 15) * 4;
    __nv_bfloat16 h, l;
    split_bf16(v.x, h, l); Bh[k*72+n  ] = h; Bl[k*72+n  ] = l;
    split_bf16(v.y, h, l); Bh[k*72+n+1] = h; Bl[k*72+n+1] = l;
    split_bf16(v.z, h, l); Bh[k*72+n+2] = h; Bl[k*72+n+2] = l;
    split_bf16(v.w, h, l); Bh[k*72+n+3] = h; Bl[k*72+n+3] = l;
  }
  __syncthreads();

  {
    wmma::fragment<wmma::accumulator,16,16,16,float> acc[4];
#pragma unroll
    for (int j = 0; j < 4; j++) wmma::fill_fragment(acc[j], 0.f);
#pragma unroll
    for (int k = 0; k < 4; k++){
      wmma::fragment<wmma::matrix_a,16,16,16,__nv_bfloat16,wmma::row_major> ah, al;
      wmma::load_matrix_sync(ah, Ah + m0*72 + k*16, 72);
      wmma::load_matrix_sync(al, Al + m0*72 + k*16, 72);
#pragma unroll
      for (int j = 0; j < 4; j++){
        wmma::fragment<wmma::matrix_b,16,16,16,__nv_bfloat16,wmma::row_major> bh, bl;
        wmma::load_matrix_sync(bh, Bh + (k*16)*72 + j*16, 72);
        wmma::load_matrix_sync(bl, Bl + (k*16)*72 + j*16, 72);
        wmma::mma_sync(acc[j], ah, bh, acc[j]);
        wmma::mma_sync(acc[j], ah, bl, acc[j]);
        wmma::mma_sync(acc[j], al, bh, acc[j]);
      }
    }
    __syncthreads();
#pragma unroll
    for (int j = 0; j < 4; j++)
      wmma::store_matrix_sync(xs + m0*68 + j*16, acc[j], 68, wmma::mem_row_major);
  }
  __syncthreads();

  {
    const float4* XT4 = (const float4*)(g_XT + ((size_t)b*TOK + n0)*CH_);
    const float4* P4  = (const float4*)(g_P  + ((size_t)b*TOK + n0)*CH_);
    for (int i = tid; i < 2048; i += 256){
      int t = i >> 4, c = (i & 15) * 4;
      float4 xv = XT4[i], pv = P4[i];
      float* o = &xs[t*68 + c];
      o[0] = xv.x + (o[0] + s_bias[c  ]) * pv.x;
      o[1] = xv.y + (o[1] + s_bias[c+1]) * pv.y;
      o[2] = xv.z + (o[2] + s_bias[c+2]) * pv.z;
      o[3] = xv.w + (o[3] + s_bias[c+3]) * pv.w;
    }
    const float4* WF4 = (const float4*)wff;
    for (int i = tid; i < 1024; i += 256){
      float4 v = WF4[i];
      int k = i >> 4, n = (i & 15) * 4;
      __nv_bfloat16 h, l;
      split_bf16(v.x, h, l); Bh[k*72+n  ] = h; Bl[k*72+n  ] = l;
      split_bf16(v.y, h, l); Bh[k*72+n+1] = h; Bl[k*72+n+1] = l;
      split_bf16(v.z, h, l); Bh[k*72+n+2] = h; Bl[k*72+n+2] = l;
      split_bf16(v.w, h, l); Bh[k*72+n+3] = h; Bl[k*72+n+3] = l;
    }
  }
  __syncthreads();

  if (tid < 128){
    const float* row = &xs[tid*68];
    float s = 0.f, ss = 0.f;
#pragma unroll
    for (int c = 0; c < 64; c++){ float xv = row[c]; s += xv; ss = fmaf(xv, xv, ss); }
    float mean = s * (1.f/64.f);
    float rstd = rsqrtf(ss*(1.f/64.f) - mean*mean + 1e-5f);
#pragma unroll
    for (int c = 0; c < 64; c++){
      float f = (row[c] - mean) * rstd * s_g[c] + s_bb[c];
      __nv_bfloat16 h, l; split_bf16(f, h, l);
      Ah[tid*72 + c] = h; Al[tid*72 + c] = l;
    }
  }
  __syncthreads();

  {
    wmma::fragment<wmma::accumulator,16,16,16,float> acc[4];
#pragma unroll
    for (int j = 0; j < 4; j++) wmma::fill_fragment(acc[j], 0.f);
#pragma unroll
    for (int k = 0; k < 4; k++){
      wmma::fragment<wmma::matrix_a,16,16,16,__nv_bfloat16,wmma::row_major> ah, al;
      wmma::load_matrix_sync(ah, Ah + m0*72 + k*16, 72);
      wmma::load_matrix_sync(al, Al + m0*72 + k*16, 72);
#pragma unroll
      for (int j = 0; j < 4; j++){
        wmma::fragment<wmma::matrix_b,16,16,16,__nv_bfloat16,wmma::row_major> bh, bl;
        wmma::load_matrix_sync(bh, Bh + (k*16)*72 + j*16, 72);
        wmma::load_matrix_sync(bl, Bl + (k*16)*72 + j*16, 72);
        wmma::mma_sync(acc[j], ah, bh, acc[j]);
        wmma::mma_sync(acc[j], ah, bl, acc[j]);
        wmma::mma_sync(acc[j], al, bh, acc[j]);
      }
    }
    __syncthreads();
#pragma unroll
    for (int j = 0; j < 4; j++)
      wmma::store_matrix_sync(outF + m0*68 + j*16, acc[j], 68, wmma::mem_row_major);
  }
  __syncthreads();

  float s = 0.f, ss = 0.f;
  if (STATS){
    float* XT = g_XT + ((size_t)b*TOK + n0)*CH_;
    for (int idx = tid; idx < 8192; idx += 256){
      float nv = xs[(idx>>6)*68 + (idx&63)] + outF[(idx>>6)*68 + (idx&63)];
      XT[idx] = nv;
      float lf = leaky(nv); s += lf; ss = fmaf(lf, lf, ss);
    }
    red[tid] = s; red[256 + tid] = ss;
    __syncthreads();
    if (tid < 64){
      atomicAdd(&g_stats[tid],
                red[tid] + red[tid+64] + red[tid+128] + red[tid+192]);
      atomicAdd(&g_stats[64 + tid],
                red[256+tid] + red[320+tid] + red[384+tid] + red[448+tid]);
    }
  } else {
    float4* XT4 = (float4*)(g_XT + ((size_t)b*TOK + n0)*CH_);
    for (int i = tid; i < 2048; i += 256){
      int t = i >> 4, c = (i & 15) * 4;
      float4 o;
      o.x = xs[t*68+c  ] + outF[t*68+c  ];
      o.y = xs[t*68+c+1] + outF[t*68+c+1];
      o.z = xs[t*68+c+2] + outF[t*68+c+2];
      o.w = xs[t*68+c+3] + outF[t*68+c+3];
      XT4[i] = o;
    }
  }
}

// =============== wmma gram (verbatim) ===============
#define SM_GRAM_BYTES 36864
__global__ __launch_bounds__(128)
void k_gram(){
  extern __shared__ unsigned char smraw[];
  __nv_bfloat16* Ah = (__nv_bfloat16*)smraw;
  __nv_bfloat16* Al = (__nv_bfloat16*)(smraw + 18432);
  int tid = threadIdx.x, wid = tid >> 5;
  int b = blockIdx.x;

  wmma::fragment<wmma::accumulator,16,16,16,float> acc[4];
#pragma unroll
  for (int j = 0; j < 4; j++) wmma::fill_fragment(acc[j], 0.f);

  for (int st = 0; st < 8; st++){
    int n0 = (blockIdx.y * 8 + st) * 128;
    const float* IN = g_XT + ((size_t)b*TOK + n0)*CH_;
    __syncthreads();
    for (int idx = tid; idx < 8192; idx += 128){
      int t = idx >> 6, c = idx & 63;
      __nv_bfloat16 h, l; split_bf16(IN[idx], h, l);
      Ah[t*72 + c] = h; Al[t*72 + c] = l;
    }
    __syncthreads();
#pragma unroll
    for (int k = 0; k < 8; k++){
      wmma::fragment<wmma::matrix_a,16,16,16,__nv_bfloat16,wmma::col_major> ah, al;
      wmma::load_matrix_sync(ah, Ah + wid*16 + (k*16)*72, 72);
      wmma::load_matrix_sync(al, Al + wid*16 + (k*16)*72, 72);
#pragma unroll
      for (int j = 0; j < 4; j++){
        wmma::fragment<wmma::matrix_b,16,16,16,__nv_bfloat16,wmma::row_major> bh, bl;
        wmma::load_matrix_sync(bh, Ah + (k*16)*72 + j*16, 72);
        wmma::load_matrix_sync(bl, Al + (k*16)*72 + j*16, 72);
        wmma::mma_sync(acc[j], ah, bh, acc[j]);
        wmma::mma_sync(acc[j], ah, bl, acc[j]);
        wmma::mma_sync(acc[j], al, bh, acc[j]);
      }
    }
  }
  __syncthreads();
  float* outF = (float*)smraw;
#pragma unroll
  for (int j = 0; j < 4; j++)
    wmma::store_matrix_sync(outF + (wid*16)*68 + j*16, acc[j], 68, wmma::mem_row_major);
  __syncthreads();
  for (int idx = tid; idx < 4096; idx += 128)
    atomicAdd(&g_C[b*4096 + idx], outF[(idx>>6)*68 + (idx&63)]);
}

// ------- per-batch attention stats + fold into Weff -------
__global__ void k_attn_weff(const float* __restrict__ wq, const float* __restrict__ wk,
                            const float* __restrict__ wproj){
  extern __shared__ float sm[];
  float* Cs  = sm;
  float* wqs = sm + 4096;
  float* wks = sm + 8192;
  float* wps = sm + 12288;
  float* T1  = sm + 16384;
  float* T2  = sm + 20480;
  __shared__ float attn_s[512];
  __shared__ float qq[64], kk[64];
  int b = blockIdx.x;
  for (int i = threadIdx.x; i < 4096; i += 256){
    Cs[i]  = g_C[b*4096 + i];
    wqs[i] = wq[i]; wks[i] = wk[i]; wps[i] = wproj[i];
  }
  __syncthreads();
  for (int i = threadIdx.x; i < 4096; i += 256){
    int r = i >> 6, e = i & 63; float s1 = 0.f, s2 = 0.f;
    for (int c = 0; c < 64; c++){
      float cv = Cs[r*64 + c];
      s1 = fmaf(cv, wqs[c*64 + e], s1);
      s2 = fmaf(cv, wks[c*64 + e], s2);
    }
    T1[i] = s1; T2[i] = s2;
  }
  __syncthreads();
  if (threadIdx.x < 64){
    int e = threadIdx.x; float s1 = 0.f, s2 = 0.f;
    for (int c = 0; c < 64; c++){
      s1 = fmaf(wqs[c*64 + e], T1[c*64 + e], s1);
      s2 = fmaf(wks[c*64 + e], T2[c*64 + e], s2);
    }
    qq[e] = s1; kk[e] = s2;
  }
  __syncthreads();
  if (threadIdx.x < 64){
    int h = threadIdx.x >> 3, dd = threadIdx.x & 7;
    float nk = fmaxf(sqrtf(kk[h*8 + dd]), 1e-12f);
    float lo[8]; float mx = -3.4e38f;
#pragma unroll
    for (int e = 0; e < 8; e++){
      float gg = 0.f;
      for (int c = 0; c < 64; c++)
        gg = fmaf(wks[c*64 + h*8 + dd], T1[c*64 + h*8 + e], gg);
      float nq = fmaxf(sqrtf(qq[h*8 + e]), 1e-12f);
      lo[e] = gg / (nk * nq);
      mx = fmaxf(mx, lo[e]);
    }
    float sum = 0.f;
#pragma unroll
    for (int e = 0; e < 8; e++){ lo[e] = expf(lo[e] - mx); sum += lo[e]; }
    float inv = 1.f / sum;
#pragma unroll
    for (int e = 0; e < 8; e++) attn_s[(h*8 + dd)*8 + e] = lo[e] * inv;
  }
  __syncthreads();
  for (int i = threadIdx.x; i < 4096; i += 256){
    int cin = i >> 6, oc = i & 63;
    int h = cin >> 3, e = cin & 7;
    float s = 0.f;
#pragma unroll
    for (int dd = 0; dd < 8; dd++)
      s = fmaf(attn_s[(h*8 + dd)*8 + e], wps[(h*8 + dd)*64 + oc], s);
    g_Weff[b*4096 + i] = s;
  }
}

// ---------------- depthwise 3x3 on V -> P ----------------
__global__ void k_dwconv(const float* __restrict__ wpos){
  int bh = blockIdx.x; int b = bh >> 7; int y = bh & 127;
  int cg = threadIdx.x & 15;
  int x  = blockIdx.y * 16 + (threadIdx.x >> 4);
  __shared__ float wp[576];
  for (int i = threadIdx.x; i < 576; i += 256) wp[i] = wpos[i];
  __syncthreads();
  float a0 = 0.f, a1 = 0.f, a2 = 0.f, a3 = 0.f;
  const float* Vb = g_V + (size_t)b*TOK*CH_;
#pragma unroll
  for (int ky = 0; ky < 3; ky++){
    int yy = y + ky - 1; if (yy < 0 || yy > 127) continue;
#pragma unroll
    for (int kx = 0; kx < 3; kx++){
      int xx = x + kx - 1; if (xx < 0 || xx > 127) continue;
      float4 v = *(const float4*)&Vb[((size_t)yy*128 + xx)*64 + cg*4];
      int wi = ky*3 + kx;
      a0 = fmaf(v.x, wp[(cg*4+0)*9 + wi], a0);
      a1 = fmaf(v.y, wp[(cg*4+1)*9 + wi], a1);
      a2 = fmaf(v.z, wp[(cg*4+2)*9 + wi], a2);
      a3 = fmaf(v.w, wp[(cg*4+3)*9 + wi], a3);
    }
  }
  *(float4*)&g_P[((size_t)b*TOK + y*128 + x)*64 + cg*4] = make_float4(a0,a1,a2,a3);
}

// ---- BN2 + residual + NCHW out + pooled sums ----
__global__ void k_bn2_add_pool(const float* __restrict__ x_orig, float* __restrict__ out,
                               const float* __restrict__ g2, const float* __restrict__ b2){
  int b = blockIdx.x, n0 = blockIdx.y * 64;
  __shared__ float s[64*65];
  __shared__ float scale[64], shift[64];
  if (threadIdx.x < 64){
    int c = threadIdx.x;
    float m   = g_stats[128 + c] * (1.f/CNT);
    float var = g_stats[192 + c] * (1.f/CNT) - m*m;
    float sc  = g2[c] * rsqrtf(var + 1e-4f);
    scale[c] = sc; shift[c] = b2[c] - m*sc;
  }
  const float* R = g_V + ((size_t)b*TOK + n0)*CH_;
  for (int idx = threadIdx.x; idx < 4096; idx += 256){
    int t = idx >> 6, c = idx & 63;
    s[t*65 + c] = R[idx];
  }
  __syncthreads();
  int y = n0 >> 7, x0 = n0 & 127;
  int iblk = y >> 4, jbase = x0 >> 4;
  const float* xb = x_orig + (size_t)b*CH_*TOK;
  float* ob = out + (size_t)b*CH_*TOK;
  for (int idx = threadIdx.x; idx < 4096; idx += 256){
    int c = idx >> 6, j = idx & 63;
    float f = leaky(s[j*65 + c]) * scale[c] + shift[c];
    size_t off = (size_t)c*TOK + n0 + j;
    float sval = f + xb[off];
    ob[off] = sval;
    float r = sval;
    r += __shfl_down_sync(0xffffffffu, r, 8, 16);
    r += __shfl_down_sync(0xffffffffu, r, 4, 16);
    r += __shfl_down_sync(0xffffffffu, r, 2, 16);
    r += __shfl_down_sync(0xffffffffu, r, 1, 16);
    if ((threadIdx.x & 15) == 0)
      atomicAdd(&g_pooled[(b*64 + c)*64 + iblk*8 + jbase + (j >> 4)], r);
  }
}

__global__ void k_minmax(){
  float mn = 3.4e38f, mx = -3.4e38f;
  for (int i = threadIdx.x; i < B_*4096; i += 1024){
    float v = g_pooled[i] * (1.f/256.f);
    mn = fminf(mn, v); mx = fmaxf(mx, v);
  }
#pragma unroll
  for (int o = 16; o > 0; o >>= 1){
    mn = fminf(mn, __shfl_xor_sync(0xffffffffu, mn, o));
    mx = fmaxf(mx, __shfl_xor_sync(0xffffffffu, mx, o));
  }
  __shared__ float smn[32], smx[32];
  if ((threadIdx.x & 31) == 0){ smn[threadIdx.x >> 5] = mn; smx[threadIdx.x >> 5] = mx; }
  __syncthreads();
  if (threadIdx.x < 32){
    mn = smn[threadIdx.x]; mx = smx[threadIdx.x];
#pragma unroll
    for (int o = 16; o > 0; o >>= 1){
      mn = fminf(mn, __shfl_xor_sync(0xffffffffu, mn, o));
      mx = fmaxf(mx, __shfl_xor_sync(0xffffffffu, mx, o));
    }
    if (threadIdx.x == 0){ g_minmax[0] = mn; g_minmax[1] = mx; }
  }
}

__global__ void k_gate(const float* __restrict__ w1, const float* __restrict__ w2){
  int b = blockIdx.x;
  __shared__ float y[4096];
  __shared__ float S[64];
  __shared__ float g0[64];
  __shared__ float hid[4];
  float mn = g_minmax[0];
  float inv = 1.f / (g_minmax[1] - mn);
  for (int i = threadIdx.x; i < 4096; i += 64)
    y[i] = (g_pooled[b*4096 + i] * (1.f/256.f) - mn) * inv;
  __syncthreads();
  {
    int i = threadIdx.x; float s = 0.f;
    for (int c = 0; c < 64; c++) s += y[c*64 + i];
    S[i] = s;
  }
  __syncthreads();
  {
    int c = threadIdx.x; float s = 0.f, sm2 = 0.f;
    for (int i = 0; i < 64; i++){
      s = fmaf(y[c*64 + i], S[i], s);
      sm2 += g_pooled[b*4096 + c*64 + i];
    }
    g0[c] = (s * (1.f/64.f)) * (sm2 * (1.f/16384.f));
  }
  __syncthreads();
  if (threadIdx.x < 4){
    int j = threadIdx.x; float h = 0.f;
    for (int c = 0; c < 64; c++) h = fmaf(g0[c], w1[c*4 + j], h);
    hid[j] = leaky(h);
  }
  __syncthreads();
  {
    int c = threadIdx.x; float o = 0.f;
#pragma unroll
    for (int j = 0; j < 4; j++) o = fmaf(hid[j], w2[j*64 + c], o);
    g_gate[b*64 + c] = 1.f / (1.f + expf(-o));
  }
}

__global__ void k_scale(float* __restrict__ out){
  size_t i = (size_t)blockIdx.x * 256 + threadIdx.x;
  out[i] *= g_gate[i >> 14];
}

// ================================ launch ========================================
extern "C" void kernel_launch(void* const* d_in, const int* in_sizes, int n_in,
                              void* d_out, int out_size){
  const float* x     = (const float*)d_in[0];
  const float* wq    = (const float*)d_in[1];
  const float* wk    = (const float*)d_in[2];
  const float* wv    = (const float*)d_in[3];
  const float* wproj = (const float*)d_in[4];
  const float* bproj = (const float*)d_in[5];
  const float* wpos  = (const float*)d_in[6];
  const float* ln_g  = (const float*)d_in[7];
  const float* ln_b  = (const float*)d_in[8];
  const float* wff   = (const float*)d_in[9];
  const float* bn1_g = (const float*)d_in[10];
  const float* bn1_b = (const float*)d_in[11];
  const float* wd    = (const float*)d_in[12];
  const float* bn2_g = (const float*)d_in[13];
  const float* bn2_b = (const float*)d_in[14];
  const float* sw1   = (const float*)d_in[15];
  const float* sw2   = (const float*)d_in[16];
  float* out = (float*)d_out;

  cudaFuncSetAttribute(k_gemm<0>,    cudaFuncAttributeMaxDynamicSharedMemorySize, SM_GEMM_BYTES);
  cudaFuncSetAttribute(k_gemm<3>,    cudaFuncAttributeMaxDynamicSharedMemorySize, SM_GEMM_BYTES);
  cudaFuncSetAttribute(k_fused12<0>, cudaFuncAttributeMaxDynamicSharedMemorySize, SM_F_BYTES);
  cudaFuncSetAttribute(k_fused12<1>, cudaFuncAttributeMaxDynamicSharedMemorySize, SM_F_BYTES);
  cudaFuncSetAttribute(k_gram,       cudaFuncAttributeMaxDynamicSharedMemorySize, SM_GRAM_BYTES);
  cudaFuncSetAttribute(k_attn_weff,  cudaFuncAttributeMaxDynamicSharedMemorySize, 100*1024);

  void *pC = nullptr, *pStats = nullptr, *pPooled = nullptr;
  cudaGetSymbolAddress(&pC, g_C);
  cudaGetSymbolAddress(&pStats, g_stats);
  cudaGetSymbolAddress(&pPooled, g_pooled);

  cudaMemsetAsync(pStats, 0, 256*sizeof(float));
  k_transpose_in<<<dim3(16, 256), 256>>>(x);
  for (int l = 0; l < 2; l++){
    cudaMemsetAsync(pC, 0, 16*4096*sizeof(float));
    k_gram<<<dim3(16, 16), 128, SM_GRAM_BYTES>>>();
    k_attn_weff<<<16, 256, 6*4096*sizeof(float)>>>(wq + l*4096, wk + l*4096, wproj + l*4096);
    k_gemm<0><<<dim3(16, 128), 256, SM_GEMM_BYTES>>>(wv + l*4096, nullptr, nullptr);
    k_dwconv<<<dim3(16*128, 8), 256>>>(wpos + l*576);
    if (l == 0)
      k_fused12<0><<<dim3(16, 128), 256, SM_F_BYTES>>>(wff + l*4096, bproj + l*64, ln_g + l*64, ln_b + l*64);
    else
      k_fused12<1><<<dim3(16, 128), 256, SM_F_BYTES>>>(wff + l*4096, bproj + l*64, ln_g + l*64, ln_b + l*64);
  }
  k_gemm<3><<<dim3(16, 128), 256, SM_GEMM_BYTES>>>(wd, bn1_g, bn1_b);
  cudaMemsetAsync(pPooled, 0, 16*4096*sizeof(float));
  k_bn2_add_pool<<<dim3(16, 256), 256>>>(x, out, bn2_g, bn2_b);
  k_minmax<<<1, 1024>>>();
  k_gate<<<16, 64>>>(sw1, sw2);
  k_scale<<<65536, 256>>>(out);
}

// round 12
// speedup vs baseline: 2.7240x; 1.1700x over previous
#include <cuda_runtime.h>
#include <cuda_bf16.h>
#include <mma.h>
#include <cstdint>

using namespace nvcuda;

#define B_   16
#define CH_  64
#define TOK  16384
#define CNT  (16.0f*16384.0f)

__device__ float g_XT[B_*TOK*CH_];
__device__ float g_V [B_*TOK*CH_];
__device__ float g_C    [B_*64*64];
__device__ float g_Weff [B_*64*64];
__device__ float g_stats[256];
__device__ float g_pooled[B_*64*64];
__device__ float g_minmax[2];
__device__ float g_gate[B_*64];

__device__ __forceinline__ float leaky(float x){ return x >= 0.f ? x : 0.2f*x; }
__device__ __forceinline__ void split_bf16(float f, __nv_bfloat16& h, __nv_bfloat16& l){
  h = __float2bfloat16_rn(f);
  l = __float2bfloat16_rn(f - __bfloat162float(h));
}

// ---------------- NCHW -> BHWC transpose ----------------
__global__ void k_transpose_in(const float* __restrict__ x){
  int b = blockIdx.x, n0 = blockIdx.y * 64;
  __shared__ float s[64*65];
  const float* xb = x + (size_t)b*CH_*TOK;
  for (int idx = threadIdx.x; idx < 4096; idx += 256){
    int c = idx >> 6, j = idx & 63;
    s[c*65 + j] = xb[(size_t)c*TOK + n0 + j];
  }
  __syncthreads();
  float* xt = g_XT + ((size_t)b*TOK + n0)*CH_;
  for (int idx = threadIdx.x; idx < 4096; idx += 256){
    int j = idx >> 6, c = idx & 63;
    xt[j*CH_ + c] = s[c*65 + j];
  }
}

// =============== wmma GEMM — slim smem (R11 verbatim) ===============
// MODE 0: V = XT @ W (direct global store)
// MODE 3: V = BN1(leaky(XT)) @ W ; leaky stats -> g_stats[128..255]
#define SM_GEMM_BYTES 55296
template<int MODE>
__global__ __launch_bounds__(256)
void k_gemm(const float* __restrict__ W, const float* __restrict__ aux0,
            const float* __restrict__ aux1){
  extern __shared__ unsigned char smraw[];
  __nv_bfloat16* Ah = (__nv_bfloat16*)smraw;
  __nv_bfloat16* Al = (__nv_bfloat16*)(smraw + 18432);
  __nv_bfloat16* Bh = (__nv_bfloat16*)(smraw + 36864);
  __nv_bfloat16* Bl = (__nv_bfloat16*)(smraw + 46080);
  float* outF = (float*)smraw;
  __shared__ float s_a[64], s_b[64];
  __shared__ float red[512];

  int tid = threadIdx.x, wid = tid >> 5;
  int b = blockIdx.x, n0 = blockIdx.y * 128;
  int m0 = wid * 16;

  if (MODE == 3 && tid < 64){
    float m   = g_stats[tid]      * (1.f/CNT);
    float var = g_stats[64 + tid] * (1.f/CNT) - m*m;
    float sc  = aux0[tid] * rsqrtf(var + 1e-4f);
    s_a[tid] = sc; s_b[tid] = aux1[tid] - m*sc;
  }

  const float4* W4 = (const float4*)W;
  for (int i = tid; i < 1024; i += 256){
    float4 v = W4[i];
    int k = i >> 4, n = (i & 15) * 4;
    __nv_bfloat16 h, l;
    split_bf16(v.x, h, l); Bh[k*72+n  ] = h; Bl[k*72+n  ] = l;
    split_bf16(v.y, h, l); Bh[k*72+n+1] = h; Bl[k*72+n+1] = l;
    split_bf16(v.z, h, l); Bh[k*72+n+2] = h; Bl[k*72+n+2] = l;
    split_bf16(v.w, h, l); Bh[k*72+n+3] = h; Bl[k*72+n+3] = l;
  }
  __syncthreads();

  const float4* IN4 = (const float4*)(g_XT + ((size_t)b*TOK + n0)*CH_);
  for (int i = tid; i < 2048; i += 256){
    float4 v = IN4[i];
    int t = i >> 4, c = (i & 15) * 4;
    float f0 = v.x, f1 = v.y, f2 = v.z, f3 = v.w;
    if (MODE == 3){
      f0 = leaky(f0)*s_a[c  ] + s_b[c  ];
      f1 = leaky(f1)*s_a[c+1] + s_b[c+1];
      f2 = leaky(f2)*s_a[c+2] + s_b[c+2];
      f3 = leaky(f3)*s_a[c+3] + s_b[c+3];
    }
    __nv_bfloat16 h, l;
    split_bf16(f0, h, l); Ah[t*72+c  ] = h; Al[t*72+c  ] = l;
    split_bf16(f1, h, l); Ah[t*72+c+1] = h; Al[t*72+c+1] = l;
    split_bf16(f2, h, l); Ah[t*72+c+2] = h; Al[t*72+c+2] = l;
    split_bf16(f3, h, l); Ah[t*72+c+3] = h; Al[t*72+c+3] = l;
  }
  __syncthreads();

  wmma::fragment<wmma::accumulator,16,16,16,float> acc[4];
#pragma unroll
  for (int j = 0; j < 4; j++) wmma::fill_fragment(acc[j], 0.f);
#pragma unroll
  for (int k = 0; k < 4; k++){
    wmma::fragment<wmma::matrix_a,16,16,16,__nv_bfloat16,wmma::row_major> ah, al;
    wmma::load_matrix_sync(ah, Ah + m0*72 + k*16, 72);
    wmma::load_matrix_sync(al, Al + m0*72 + k*16, 72);
#pragma unroll
    for (int j = 0; j < 4; j++){
      wmma::fragment<wmma::matrix_b,16,16,16,__nv_bfloat16,wmma::row_major> bh, bl;
      wmma::load_matrix_sync(bh, Bh + (k*16)*72 + j*16, 72);
      wmma::load_matrix_sync(bl, Bl + (k*16)*72 + j*16, 72);
      wmma::mma_sync(acc[j], ah, bh, acc[j]);
      wmma::mma_sync(acc[j], ah, bl, acc[j]);
      wmma::mma_sync(acc[j], al, bh, acc[j]);
    }
  }

  if (MODE == 0){
    float* O = g_V + ((size_t)b*TOK + n0 + m0)*CH_;
#pragma unroll
    for (int j = 0; j < 4; j++)
      wmma::store_matrix_sync(O + j*16, acc[j], 64, wmma::mem_row_major);
  } else {
    __syncthreads();
#pragma unroll
    for (int j = 0; j < 4; j++)
      wmma::store_matrix_sync(outF + m0*68 + j*16, acc[j], 68, wmma::mem_row_major);
    __syncthreads();
    float* O = g_V + ((size_t)b*TOK + n0)*CH_;
    float s = 0.f, ss = 0.f;
    for (int idx = tid; idx < 8192; idx += 256){
      float f = outF[(idx>>6)*68 + (idx&63)];
      O[idx] = f;
      float lf = leaky(f); s += lf; ss = fmaf(lf, lf, ss);
    }
    red[tid] = s; red[256 + tid] = ss;
    __syncthreads();
    if (tid < 64){
      atomicAdd(&g_stats[128 + tid],
                red[tid] + red[tid+64] + red[tid+128] + red[tid+192]);
      atomicAdd(&g_stats[192 + tid],
                red[256+tid] + red[320+tid] + red[384+tid] + red[448+tid]);
    }
  }
}

// ====== fused: attn-epilogue (with INLINE dwconv) + LN-FF ======
// XT' = Y + LN(Y)@wff,  Y = XT + (V@Weff + bproj) * dwconv3x3(V)
// tile = image row y = blockIdx.y, tokens x = 0..127
#define SM_F_BYTES 90112
template<int STATS>
__global__ __launch_bounds__(256)
void k_fused12(const float* __restrict__ wff, const float* __restrict__ bproj,
               const float* __restrict__ lng, const float* __restrict__ lnb,
               const float* __restrict__ wpos){
  extern __shared__ unsigned char smraw[];
  float* xs = (float*)smraw;
  __nv_bfloat16* Ah = (__nv_bfloat16*)(smraw + 34816);
  __nv_bfloat16* Al = (__nv_bfloat16*)(smraw + 53248);
  __nv_bfloat16* Bh = (__nv_bfloat16*)(smraw + 71680);
  __nv_bfloat16* Bl = (__nv_bfloat16*)(smraw + 80896);
  float* outF = (float*)(smraw + 34816);
  __shared__ float s_bias[64], s_g[64], s_bb[64];
  __shared__ float red[512];
  __shared__ float wp[576];

  int tid = threadIdx.x, wid = tid >> 5;
  int b = blockIdx.x, n0 = blockIdx.y * 128;
  int y = blockIdx.y;
  int m0 = wid * 16;

  if (tid < 64){ s_bias[tid] = bproj[tid]; s_g[tid] = lng[tid]; s_bb[tid] = lnb[tid]; }
  for (int i = tid; i < 576; i += 256) wp[i] = wpos[i];

  const float4* IN4 = (const float4*)(g_V + ((size_t)b*TOK + n0)*CH_);
  for (int i = tid; i < 2048; i += 256){
    float4 v = IN4[i];
    int t = i >> 4, c = (i & 15) * 4;
    __nv_bfloat16 h, l;
    split_bf16(v.x, h, l); Ah[t*72+c  ] = h; Al[t*72+c  ] = l;
    split_bf16(v.y, h, l); Ah[t*72+c+1] = h; Al[t*72+c+1] = l;
    split_bf16(v.z, h, l); Ah[t*72+c+2] = h; Al[t*72+c+2] = l;
    split_bf16(v.w, h, l); Ah[t*72+c+3] = h; Al[t*72+c+3] = l;
  }
  const float4* WE4 = (const float4*)(g_Weff + b*4096);
  for (int i = tid; i < 1024; i += 256){
    float4 v = WE4[i];
    int k = i >> 4, n = (i & 15) * 4;
    __nv_bfloat16 h, l;
    split_bf16(v.x, h, l); Bh[k*72+n  ] = h; Bl[k*72+n  ] = l;
    split_bf16(v.y, h, l); Bh[k*72+n+1] = h; Bl[k*72+n+1] = l;
    split_bf16(v.z, h, l); Bh[k*72+n+2] = h; Bl[k*72+n+2] = l;
    split_bf16(v.w, h, l); Bh[k*72+n+3] = h; Bl[k*72+n+3] = l;
  }
  __syncthreads();

  // MMA1: V @ Weff -> xs
  {
    wmma::fragment<wmma::accumulator,16,16,16,float> acc[4];
#pragma unroll
    for (int j = 0; j < 4; j++) wmma::fill_fragment(acc[j], 0.f);
#pragma unroll
    for (int k = 0; k < 4; k++){
      wmma::fragment<wmma::matrix_a,16,16,16,__nv_bfloat16,wmma::row_major> ah, al;
      wmma::load_matrix_sync(ah, Ah + m0*72 + k*16, 72);
      wmma::load_matrix_sync(al, Al + m0*72 + k*16, 72);
#pragma unroll
      for (int j = 0; j < 4; j++){
        wmma::fragment<wmma::matrix_b,16,16,16,__nv_bfloat16,wmma::row_major> bh, bl;
        wmma::load_matrix_sync(bh, Bh + (k*16)*72 + j*16, 72);
        wmma::load_matrix_sync(bl, Bl + (k*16)*72 + j*16, 72);
        wmma::mma_sync(acc[j], ah, bh, acc[j]);
        wmma::mma_sync(acc[j], ah, bl, acc[j]);
        wmma::mma_sync(acc[j], al, bh, acc[j]);
      }
    }
    __syncthreads();
#pragma unroll
    for (int j = 0; j < 4; j++)
      wmma::store_matrix_sync(xs + m0*68 + j*16, acc[j], 68, wmma::mem_row_major);
  }
  __syncthreads();

  // Y = XT + (xs + bias) * dwconv(V) -> xs ; restage wff -> Bh/Bl
  {
    const float4* XT4 = (const float4*)(g_XT + ((size_t)b*TOK + n0)*CH_);
    const float* Vb = g_V + (size_t)b*TOK*CH_;
    for (int i = tid; i < 2048; i += 256){
      int t = i >> 4, c = (i & 15) * 4;
      float4 xv = XT4[i];
      float p0 = 0.f, p1 = 0.f, p2 = 0.f, p3 = 0.f;
#pragma unroll
      for (int ky = 0; ky < 3; ky++){
        int yy = y + ky - 1; if (yy < 0 || yy > 127) continue;
#pragma unroll
        for (int kx = 0; kx < 3; kx++){
          int xx = t + kx - 1; if (xx < 0 || xx > 127) continue;
          float4 v = *(const float4*)&Vb[((size_t)(yy*128 + xx))*64 + c];
          int wi = ky*3 + kx;
          p0 = fmaf(v.x, wp[(c  )*9 + wi], p0);
          p1 = fmaf(v.y, wp[(c+1)*9 + wi], p1);
          p2 = fmaf(v.z, wp[(c+2)*9 + wi], p2);
          p3 = fmaf(v.w, wp[(c+3)*9 + wi], p3);
        }
      }
      float* o = &xs[t*68 + c];
      o[0] = xv.x + (o[0] + s_bias[c  ]) * p0;
      o[1] = xv.y + (o[1] + s_bias[c+1]) * p1;
      o[2] = xv.z + (o[2] + s_bias[c+2]) * p2;
      o[3] = xv.w + (o[3] + s_bias[c+3]) * p3;
    }
    const float4* WF4 = (const float4*)wff;
    for (int i = tid; i < 1024; i += 256){
      float4 v = WF4[i];
      int k = i >> 4, n = (i & 15) * 4;
      __nv_bfloat16 h, l;
      split_bf16(v.x, h, l); Bh[k*72+n  ] = h; Bl[k*72+n  ] = l;
      split_bf16(v.y, h, l); Bh[k*72+n+1] = h; Bl[k*72+n+1] = l;
      split_bf16(v.z, h, l); Bh[k*72+n+2] = h; Bl[k*72+n+2] = l;
      split_bf16(v.w, h, l); Bh[k*72+n+3] = h; Bl[k*72+n+3] = l;
    }
  }
  __syncthreads();

  // LN(Y) -> Ah/Al
  if (tid < 128){
    const float* row = &xs[tid*68];
    float s = 0.f, ss = 0.f;
#pragma unroll
    for (int c = 0; c < 64; c++){ float xv = row[c]; s += xv; ss = fmaf(xv, xv, ss); }
    float mean = s * (1.f/64.f);
    float rstd = rsqrtf(ss*(1.f/64.f) - mean*mean + 1e-5f);
#pragma unroll
    for (int c = 0; c < 64; c++){
      float f = (row[c] - mean) * rstd * s_g[c] + s_bb[c];
      __nv_bfloat16 h, l; split_bf16(f, h, l);
      Ah[tid*72 + c] = h; Al[tid*72 + c] = l;
    }
  }
  __syncthreads();

  // MMA2: LN(Y) @ wff -> outF
  {
    wmma::fragment<wmma::accumulator,16,16,16,float> acc[4];
#pragma unroll
    for (int j = 0; j < 4; j++) wmma::fill_fragment(acc[j], 0.f);
#pragma unroll
    for (int k = 0; k < 4; k++){
      wmma::fragment<wmma::matrix_a,16,16,16,__nv_bfloat16,wmma::row_major> ah, al;
      wmma::load_matrix_sync(ah, Ah + m0*72 + k*16, 72);
      wmma::load_matrix_sync(al, Al + m0*72 + k*16, 72);
#pragma unroll
      for (int j = 0; j < 4; j++){
        wmma::fragment<wmma::matrix_b,16,16,16,__nv_bfloat16,wmma::row_major> bh, bl;
        wmma::load_matrix_sync(bh, Bh + (k*16)*72 + j*16, 72);
        wmma::load_matrix_sync(bl, Bl + (k*16)*72 + j*16, 72);
        wmma::mma_sync(acc[j], ah, bh, acc[j]);
        wmma::mma_sync(acc[j], ah, bl, acc[j]);
        wmma::mma_sync(acc[j], al, bh, acc[j]);
      }
    }
    __syncthreads();
#pragma unroll
    for (int j = 0; j < 4; j++)
      wmma::store_matrix_sync(outF + m0*68 + j*16, acc[j], 68, wmma::mem_row_major);
  }
  __syncthreads();

  float s = 0.f, ss = 0.f;
  if (STATS){
    float* XT = g_XT + ((size_t)b*TOK + n0)*CH_;
    for (int idx = tid; idx < 8192; idx += 256){
      float nv = xs[(idx>>6)*68 + (idx&63)] + outF[(idx>>6)*68 + (idx&63)];
      XT[idx] = nv;
      float lf = leaky(nv); s += lf; ss = fmaf(lf, lf, ss);
    }
    red[tid] = s; red[256 + tid] = ss;
    __syncthreads();
    if (tid < 64){
      atomicAdd(&g_stats[tid],
                red[tid] + red[tid+64] + red[tid+128] + red[tid+192]);
      atomicAdd(&g_stats[64 + tid],
                red[256+tid] + red[320+tid] + red[384+tid] + red[448+tid]);
    }
  } else {
    float4* XT4 = (float4*)(g_XT + ((size_t)b*TOK + n0)*CH_);
    for (int i = tid; i < 2048; i += 256){
      int t = i >> 4, c = (i & 15) * 4;
      float4 o;
      o.x = xs[t*68+c  ] + outF[t*68+c  ];
      o.y = xs[t*68+c+1] + outF[t*68+c+1];
      o.z = xs[t*68+c+2] + outF[t*68+c+2];
      o.w = xs[t*68+c+3] + outF[t*68+c+3];
      XT4[i] = o;
    }
  }
}

// =============== wmma gram — 256 threads, float4 staging (R7-exonerated) ===============
#define SM_GRAM_BYTES 36864
__global__ __launch_bounds__(256)
void k_gram(){
  extern __shared__ unsigned char smraw[];
  __nv_bfloat16* Ah = (__nv_bfloat16*)smraw;
  __nv_bfloat16* Al = (__nv_bfloat16*)(smraw + 18432);
  int tid = threadIdx.x, wid = tid >> 5;
  int b = blockIdx.x;
  int mwid = wid & 3, nh = wid >> 2;
  int m0 = mwid * 16, j0 = nh * 2;

  wmma::fragment<wmma::accumulator,16,16,16,float> acc[2];
#pragma unroll
  for (int j = 0; j < 2; j++) wmma::fill_fragment(acc[j], 0.f);

  for (int st = 0; st < 4; st++){
    int n0 = (blockIdx.y * 4 + st) * 128;
    const float4* IN4 = (const float4*)(g_XT + ((size_t)b*TOK + n0)*CH_);
    __syncthreads();
    for (int i = tid; i < 2048; i += 256){
      float4 v = IN4[i];
      int t = i >> 4, c = (i & 15) * 4;
      __nv_bfloat16 h, l;
      split_bf16(v.x, h, l); Ah[t*72+c  ] = h; Al[t*72+c  ] = l;
      split_bf16(v.y, h, l); Ah[t*72+c+1] = h; Al[t*72+c+1] = l;
      split_bf16(v.z, h, l); Ah[t*72+c+2] = h; Al[t*72+c+2] = l;
      split_bf16(v.w, h, l); Ah[t*72+c+3] = h; Al[t*72+c+3] = l;
    }
    __syncthreads();
#pragma unroll
    for (int k = 0; k < 8; k++){
      wmma::fragment<wmma::matrix_a,16,16,16,__nv_bfloat16,wmma::col_major> ah, al;
      wmma::load_matrix_sync(ah, Ah + (k*16)*72 + m0, 72);
      wmma::load_matrix_sync(al, Al + (k*16)*72 + m0, 72);
#pragma unroll
      for (int jj = 0; jj < 2; jj++){
        int j = j0 + jj;
        wmma::fragment<wmma::matrix_b,16,16,16,__nv_bfloat16,wmma::row_major> bh, bl;
        wmma::load_matrix_sync(bh, Ah + (k*16)*72 + j*16, 72);
        wmma::load_matrix_sync(bl, Al + (k*16)*72 + j*16, 72);
        wmma::mma_sync(acc[jj], ah, bh, acc[jj]);
        wmma::mma_sync(acc[jj], ah, bl, acc[jj]);
        wmma::mma_sync(acc[jj], al, bh, acc[jj]);
      }
    }
  }
  __syncthreads();
  float* outF = (float*)smraw;
#pragma unroll
  for (int jj = 0; jj < 2; jj++)
    wmma::store_matrix_sync(outF + m0*68 + (j0+jj)*16, acc[jj], 68, wmma::mem_row_major);
  __syncthreads();
  for (int idx = tid; idx < 4096; idx += 256)
    atomicAdd(&g_C[b*4096 + idx], outF[(idx>>6)*68 + (idx&63)]);
}

// ------- per-batch attention stats + fold into Weff -------
__global__ void k_attn_weff(const float* __restrict__ wq, const float* __restrict__ wk,
                            const float* __restrict__ wproj){
  extern __shared__ float sm[];
  float* Cs  = sm;
  float* wqs = sm + 4096;
  float* wks = sm + 8192;
  float* wps = sm + 12288;
  float* T1  = sm + 16384;
  float* T2  = sm + 20480;
  __shared__ float attn_s[512];
  __shared__ float qq[64], kk[64];
  int b = blockIdx.x;
  for (int i = threadIdx.x; i < 4096; i += 256){
    Cs[i]  = g_C[b*4096 + i];
    wqs[i] = wq[i]; wks[i] = wk[i]; wps[i] = wproj[i];
  }
  __syncthreads();
  for (int i = threadIdx.x; i < 4096; i += 256){
    int r = i >> 6, e = i & 63; float s1 = 0.f, s2 = 0.f;
    for (int c = 0; c < 64; c++){
      float cv = Cs[r*64 + c];
      s1 = fmaf(cv, wqs[c*64 + e], s1);
      s2 = fmaf(cv, wks[c*64 + e], s2);
    }
    T1[i] = s1; T2[i] = s2;
  }
  __syncthreads();
  if (threadIdx.x < 64){
    int e = threadIdx.x; float s1 = 0.f, s2 = 0.f;
    for (int c = 0; c < 64; c++){
      s1 = fmaf(wqs[c*64 + e], T1[c*64 + e], s1);
      s2 = fmaf(wks[c*64 + e], T2[c*64 + e], s2);
    }
    qq[e] = s1; kk[e] = s2;
  }
  __syncthreads();
  if (threadIdx.x < 64){
    int h = threadIdx.x >> 3, dd = threadIdx.x & 7;
    float nk = fmaxf(sqrtf(kk[h*8 + dd]), 1e-12f);
    float lo[8]; float mx = -3.4e38f;
#pragma unroll
    for (int e = 0; e < 8; e++){
      float gg = 0.f;
      for (int c = 0; c < 64; c++)
        gg = fmaf(wks[c*64 + h*8 + dd], T1[c*64 + h*8 + e], gg);
      float nq = fmaxf(sqrtf(qq[h*8 + e]), 1e-12f);
      lo[e] = gg / (nk * nq);
      mx = fmaxf(mx, lo[e]);
    }
    float sum = 0.f;
#pragma unroll
    for (int e = 0; e < 8; e++){ lo[e] = expf(lo[e] - mx); sum += lo[e]; }
    float inv = 1.f / sum;
#pragma unroll
    for (int e = 0; e < 8; e++) attn_s[(h*8 + dd)*8 + e] = lo[e] * inv;
  }
  __syncthreads();
  for (int i = threadIdx.x; i < 4096; i += 256){
    int cin = i >> 6, oc = i & 63;
    int h = cin >> 3, e = cin & 7;
    float s = 0.f;
#pragma unroll
    for (int dd = 0; dd < 8; dd++)
      s = fmaf(attn_s[(h*8 + dd)*8 + e], wps[(h*8 + dd)*64 + oc], s);
    g_Weff[b*4096 + i] = s;
  }
}

// ---- BN2 + residual + NCHW out + pooled sums ----
__global__ void k_bn2_add_pool(const float* __restrict__ x_orig, float* __restrict__ out,
                               const float* __restrict__ g2, const float* __restrict__ b2){
  int b = blockIdx.x, n0 = blockIdx.y * 64;
  __shared__ float s[64*65];
  __shared__ float scale[64], shift[64];
  if (threadIdx.x < 64){
    int c = threadIdx.x;
    float m   = g_stats[128 + c] * (1.f/CNT);
    float var = g_stats[192 + c] * (1.f/CNT) - m*m;
    float sc  = g2[c] * rsqrtf(var + 1e-4f);
    scale[c] = sc; shift[c] = b2[c] - m*sc;
  }
  const float* R = g_V + ((size_t)b*TOK + n0)*CH_;
  for (int idx = threadIdx.x; idx < 4096; idx += 256){
    int t = idx >> 6, c = idx & 63;
    s[t*65 + c] = R[idx];
  }
  __syncthreads();
  int y = n0 >> 7, x0 = n0 & 127;
  int iblk = y >> 4, jbase = x0 >> 4;
  const float* xb = x_orig + (size_t)b*CH_*TOK;
  float* ob = out + (size_t)b*CH_*TOK;
  for (int idx = threadIdx.x; idx < 4096; idx += 256){
    int c = idx >> 6, j = idx & 63;
    float f = leaky(s[j*65 + c]) * scale[c] + shift[c];
    size_t off = (size_t)c*TOK + n0 + j;
    float sval = f + xb[off];
    ob[off] = sval;
    float r = sval;
    r += __shfl_down_sync(0xffffffffu, r, 8, 16);
    r += __shfl_down_sync(0xffffffffu, r, 4, 16);
    r += __shfl_down_sync(0xffffffffu, r, 2, 16);
    r += __shfl_down_sync(0xffffffffu, r, 1, 16);
    if ((threadIdx.x & 15) == 0)
      atomicAdd(&g_pooled[(b*64 + c)*64 + iblk*8 + jbase + (j >> 4)], r);
  }
}

__global__ void k_minmax(){
  float mn = 3.4e38f, mx = -3.4e38f;
  for (int i = threadIdx.x; i < B_*4096; i += 1024){
    float v = g_pooled[i] * (1.f/256.f);
    mn = fminf(mn, v); mx = fmaxf(mx, v);
  }
#pragma unroll
  for (int o = 16; o > 0; o >>= 1){
    mn = fminf(mn, __shfl_xor_sync(0xffffffffu, mn, o));
    mx = fmaxf(mx, __shfl_xor_sync(0xffffffffu, mx, o));
  }
  __shared__ float smn[32], smx[32];
  if ((threadIdx.x & 31) == 0){ smn[threadIdx.x >> 5] = mn; smx[threadIdx.x >> 5] = mx; }
  __syncthreads();
  if (threadIdx.x < 32){
    mn = smn[threadIdx.x]; mx = smx[threadIdx.x];
#pragma unroll
    for (int o = 16; o > 0; o >>= 1){
      mn = fminf(mn, __shfl_xor_sync(0xffffffffu, mn, o));
      mx = fmaxf(mx, __shfl_xor_sync(0xffffffffu, mx, o));
    }
    if (threadIdx.x == 0){ g_minmax[0] = mn; g_minmax[1] = mx; }
  }
}

__global__ void k_gate(const float* __restrict__ w1, const float* __restrict__ w2){
  int b = blockIdx.x;
  __shared__ float y[4096];
  __shared__ float S[64];
  __shared__ float g0[64];
  __shared__ float hid[4];
  float mn = g_minmax[0];
  float inv = 1.f / (g_minmax[1] - mn);
  for (int i = threadIdx.x; i < 4096; i += 64)
    y[i] = (g_pooled[b*4096 + i] * (1.f/256.f) - mn) * inv;
  __syncthreads();
  {
    int i = threadIdx.x; float s = 0.f;
    for (int c = 0; c < 64; c++) s += y[c*64 + i];
    S[i] = s;
  }
  __syncthreads();
  {
    int c = threadIdx.x; float s = 0.f, sm2 = 0.f;
    for (int i = 0; i < 64; i++){
      s = fmaf(y[c*64 + i], S[i], s);
      sm2 += g_pooled[b*4096 + c*64 + i];
    }
    g0[c] = (s * (1.f/64.f)) * (sm2 * (1.f/16384.f));
  }
  __syncthreads();
  if (threadIdx.x < 4){
    int j = threadIdx.x; float h = 0.f;
    for (int c = 0; c < 64; c++) h = fmaf(g0[c], w1[c*4 + j], h);
    hid[j] = leaky(h);
  }
  __syncthreads();
  {
    int c = threadIdx.x; float o = 0.f;
#pragma unroll
    for (int j = 0; j < 4; j++) o = fmaf(hid[j], w2[j*64 + c], o);
    g_gate[b*64 + c] = 1.f / (1.f + expf(-o));
  }
}

__global__ void k_scale(float* __restrict__ out){
  size_t i = (size_t)blockIdx.x * 256 + threadIdx.x;
  out[i] *= g_gate[i >> 14];
}

// ================================ launch ========================================
extern "C" void kernel_launch(void* const* d_in, const int* in_sizes, int n_in,
                              void* d_out, int out_size){
  const float* x     = (const float*)d_in[0];
  const float* wq    = (const float*)d_in[1];
  const float* wk    = (const float*)d_in[2];
  const float* wv    = (const float*)d_in[3];
  const float* wproj = (const float*)d_in[4];
  const float* bproj = (const float*)d_in[5];
  const float* wpos  = (const float*)d_in[6];
  const float* ln_g  = (const float*)d_in[7];
  const float* ln_b  = (const float*)d_in[8];
  const float* wff   = (const float*)d_in[9];
  const float* bn1_g = (const float*)d_in[10];
  const float* bn1_b = (const float*)d_in[11];
  const float* wd    = (const float*)d_in[12];
  const float* bn2_g = (const float*)d_in[13];
  const float* bn2_b = (const float*)d_in[14];
  const float* sw1   = (const float*)d_in[15];
  const float* sw2   = (const float*)d_in[16];
  float* out = (float*)d_out;

  cudaFuncSetAttribute(k_gemm<0>,    cudaFuncAttributeMaxDynamicSharedMemorySize, SM_GEMM_BYTES);
  cudaFuncSetAttribute(k_gemm<3>,    cudaFuncAttributeMaxDynamicSharedMemorySize, SM_GEMM_BYTES);
  cudaFuncSetAttribute(k_fused12<0>, cudaFuncAttributeMaxDynamicSharedMemorySize, SM_F_BYTES);
  cudaFuncSetAttribute(k_fused12<1>, cudaFuncAttributeMaxDynamicSharedMemorySize, SM_F_BYTES);
  cudaFuncSetAttribute(k_gram,       cudaFuncAttributeMaxDynamicSharedMemorySize, SM_GRAM_BYTES);
  cudaFuncSetAttribute(k_attn_weff,  cudaFuncAttributeMaxDynamicSharedMemorySize, 100*1024);

  void *pC = nullptr, *pStats = nullptr, *pPooled = nullptr;
  cudaGetSymbolAddress(&pC, g_C);
  cudaGetSymbolAddress(&pStats, g_stats);
  cudaGetSymbolAddress(&pPooled, g_pooled);

  cudaMemsetAsync(pStats, 0, 256*sizeof(float));
  k_transpose_in<<<dim3(16, 256), 256>>>(x);
  for (int l = 0; l < 2; l++){
    cudaMemsetAsync(pC, 0, 16*4096*sizeof(float));
    k_gram<<<dim3(16, 32), 256, SM_GRAM_BYTES>>>();
    k_attn_weff<<<16, 256, 6*4096*sizeof(float)>>>(wq + l*4096, wk + l*4096, wproj + l*4096);
    k_gemm<0><<<dim3(16, 128), 256, SM_GEMM_BYTES>>>(wv + l*4096, nullptr, nullptr);
    if (l == 0)
      k_fused12<0><<<dim3(16, 128), 256, SM_F_BYTES>>>(wff + l*4096, bproj + l*64, ln_g + l*64, ln_b + l*64, wpos + l*576);
    else
      k_fused12<1><<<dim3(16, 128), 256, SM_F_BYTES>>>(wff + l*4096, bproj + l*64, ln_g + l*64, ln_b + l*64, wpos + l*576);
  }
  k_gemm<3><<<dim3(16, 128), 256, SM_GEMM_BYTES>>>(wd, bn1_g, bn1_b);
  cudaMemsetAsync(pPooled, 0, 16*4096*sizeof(float));
  k_bn2_add_pool<<<dim3(16, 256), 256>>>(x, out, bn2_g, bn2_b);
  k_minmax<<<1, 1024>>>();
  k_gate<<<16, 64>>>(sw1, sw2);
  k_scale<<<65536, 256>>>(out);
}

// round 13
// speedup vs baseline: 2.7656x; 1.0153x over previous
#include <cuda_runtime.h>
#include <cuda_bf16.h>
#include <mma.h>
#include <cstdint>

using namespace nvcuda;

#define B_   16
#define CH_  64
#define TOK  16384
#define CNT  (16.0f*16384.0f)

__device__ float g_XT[B_*TOK*CH_];
__device__ float g_V [B_*TOK*CH_];
__device__ float g_C    [B_*64*64];
__device__ float g_Weff [B_*64*64];
__device__ float g_stats[256];
__device__ float g_pooled[B_*64*64];
__device__ float g_minmax[2];
__device__ float g_gate[B_*64];

__device__ __forceinline__ float leaky(float x){ return x >= 0.f ? x : 0.2f*x; }
__device__ __forceinline__ void split_bf16(float f, __nv_bfloat16& h, __nv_bfloat16& l){
  h = __float2bfloat16_rn(f);
  l = __float2bfloat16_rn(f - __bfloat162float(h));
}

// ---------------- NCHW -> BHWC transpose ----------------
__global__ void k_transpose_in(const float* __restrict__ x){
  int b = blockIdx.x, n0 = blockIdx.y * 64;
  __shared__ float s[64*65];
  const float* xb = x + (size_t)b*CH_*TOK;
  for (int idx = threadIdx.x; idx < 4096; idx += 256){
    int c = idx >> 6, j = idx & 63;
    s[c*65 + j] = xb[(size_t)c*TOK + n0 + j];
  }
  __syncthreads();
  float* xt = g_XT + ((size_t)b*TOK + n0)*CH_;
  for (int idx = threadIdx.x; idx < 4096; idx += 256){
    int j = idx >> 6, c = idx & 63;
    xt[j*CH_ + c] = s[c*65 + j];
  }
}

// =============== wmma GEMM — slim smem ===============
// MODE 0: V = XT @ W (direct global store) + FUSED gram partial (g_C += XT^T XT tile)
// MODE 3: V = BN1(leaky(XT)) @ W ; leaky stats -> g_stats[128..255]
#define SM_GEMM_BYTES 55296
template<int MODE>
__global__ __launch_bounds__(256)
void k_gemm(const float* __restrict__ W, const float* __restrict__ aux0,
            const float* __restrict__ aux1){
  extern __shared__ unsigned char smraw[];
  __nv_bfloat16* Ah = (__nv_bfloat16*)smraw;
  __nv_bfloat16* Al = (__nv_bfloat16*)(smraw + 18432);
  __nv_bfloat16* Bh = (__nv_bfloat16*)(smraw + 36864);
  __nv_bfloat16* Bl = (__nv_bfloat16*)(smraw + 46080);
  float* outF = (float*)smraw;   // aliases Ah/Al after all MMA reads
  __shared__ float s_a[64], s_b[64];
  __shared__ float red[512];

  int tid = threadIdx.x, wid = tid >> 5;
  int b = blockIdx.x, n0 = blockIdx.y * 128;
  int m0 = wid * 16;

  if (MODE == 3 && tid < 64){
    float m   = g_stats[tid]      * (1.f/CNT);
    float var = g_stats[64 + tid] * (1.f/CNT) - m*m;
    float sc  = aux0[tid] * rsqrtf(var + 1e-4f);
    s_a[tid] = sc; s_b[tid] = aux1[tid] - m*sc;
  }

  const float4* W4 = (const float4*)W;
  for (int i = tid; i < 1024; i += 256){
    float4 v = W4[i];
    int k = i >> 4, n = (i & 15) * 4;
    __nv_bfloat16 h, l;
    split_bf16(v.x, h, l); Bh[k*72+n  ] = h; Bl[k*72+n  ] = l;
    split_bf16(v.y, h, l); Bh[k*72+n+1] = h; Bl[k*72+n+1] = l;
    split_bf16(v.z, h, l); Bh[k*72+n+2] = h; Bl[k*72+n+2] = l;
    split_bf16(v.w, h, l); Bh[k*72+n+3] = h; Bl[k*72+n+3] = l;
  }
  __syncthreads();   // s_a/s_b ready for MODE 3 staging

  const float4* IN4 = (const float4*)(g_XT + ((size_t)b*TOK + n0)*CH_);
  for (int i = tid; i < 2048; i += 256){
    float4 v = IN4[i];
    int t = i >> 4, c = (i & 15) * 4;
    float f0 = v.x, f1 = v.y, f2 = v.z, f3 = v.w;
    if (MODE == 3){
      f0 = leaky(f0)*s_a[c  ] + s_b[c  ];
      f1 = leaky(f1)*s_a[c+1] + s_b[c+1];
      f2 = leaky(f2)*s_a[c+2] + s_b[c+2];
      f3 = leaky(f3)*s_a[c+3] + s_b[c+3];
    }
    __nv_bfloat16 h, l;
    split_bf16(f0, h, l); Ah[t*72+c  ] = h; Al[t*72+c  ] = l;
    split_bf16(f1, h, l); Ah[t*72+c+1] = h; Al[t*72+c+1] = l;
    split_bf16(f2, h, l); Ah[t*72+c+2] = h; Al[t*72+c+2] = l;
    split_bf16(f3, h, l); Ah[t*72+c+3] = h; Al[t*72+c+3] = l;
  }
  __syncthreads();

  // ---- V MMA ----
  {
    wmma::fragment<wmma::accumulator,16,16,16,float> acc[4];
#pragma unroll
    for (int j = 0; j < 4; j++) wmma::fill_fragment(acc[j], 0.f);
#pragma unroll
    for (int k = 0; k < 4; k++){
      wmma::fragment<wmma::matrix_a,16,16,16,__nv_bfloat16,wmma::row_major> ah, al;
      wmma::load_matrix_sync(ah, Ah + m0*72 + k*16, 72);
      wmma::load_matrix_sync(al, Al + m0*72 + k*16, 72);
#pragma unroll
      for (int j = 0; j < 4; j++){
        wmma::fragment<wmma::matrix_b,16,16,16,__nv_bfloat16,wmma::row_major> bh, bl;
        wmma::load_matrix_sync(bh, Bh + (k*16)*72 + j*16, 72);
        wmma::load_matrix_sync(bl, Bl + (k*16)*72 + j*16, 72);
        wmma::mma_sync(acc[j], ah, bh, acc[j]);
        wmma::mma_sync(acc[j], ah, bl, acc[j]);
        wmma::mma_sync(acc[j], al, bh, acc[j]);
      }
    }
    if (MODE == 0){
      float* O = g_V + ((size_t)b*TOK + n0 + m0)*CH_;
#pragma unroll
      for (int j = 0; j < 4; j++)
        wmma::store_matrix_sync(O + j*16, acc[j], 64, wmma::mem_row_major);
    } else {
      __syncthreads();   // all fragment reads of Ah/Al done before outF overwrite
#pragma unroll
      for (int j = 0; j < 4; j++)
        wmma::store_matrix_sync(outF + m0*68 + j*16, acc[j], 68, wmma::mem_row_major);
    }
  }

  if (MODE == 0){
    // ---- fused gram partial: g_C[b] += XT_tile^T XT_tile (hi/lo 3-product) ----
    int mwid = wid & 3, nh = wid >> 2;
    int mg = mwid * 16, j0 = nh * 2;
    wmma::fragment<wmma::accumulator,16,16,16,float> acc2[2];
#pragma unroll
    for (int j = 0; j < 2; j++) wmma::fill_fragment(acc2[j], 0.f);
#pragma unroll
    for (int k = 0; k < 8; k++){
      wmma::fragment<wmma::matrix_a,16,16,16,__nv_bfloat16,wmma::col_major> ah, al;
      wmma::load_matrix_sync(ah, Ah + (k*16)*72 + mg, 72);
      wmma::load_matrix_sync(al, Al + (k*16)*72 + mg, 72);
#pragma unroll
      for (int jj = 0; jj < 2; jj++){
        int j = j0 + jj;
        wmma::fragment<wmma::matrix_b,16,16,16,__nv_bfloat16,wmma::row_major> bh, bl;
        wmma::load_matrix_sync(bh, Ah + (k*16)*72 + j*16, 72);
        wmma::load_matrix_sync(bl, Al + (k*16)*72 + j*16, 72);
        wmma::mma_sync(acc2[jj], ah, bh, acc2[jj]);
        wmma::mma_sync(acc2[jj], ah, bl, acc2[jj]);
        wmma::mma_sync(acc2[jj], al, bh, acc2[jj]);
      }
    }
    __syncthreads();   // all gram fragment reads done before outF overwrites Ah/Al
#pragma unroll
    for (int jj = 0; jj < 2; jj++)
      wmma::store_matrix_sync(outF + mg*68 + (j0+jj)*16, acc2[jj], 68, wmma::mem_row_major);
    __syncthreads();
    for (int idx = tid; idx < 4096; idx += 256)
      atomicAdd(&g_C[b*4096 + idx], outF[(idx>>6)*68 + (idx&63)]);
  } else {
    __syncthreads();
    float* O = g_V + ((size_t)b*TOK + n0)*CH_;
    float s = 0.f, ss = 0.f;
    for (int idx = tid; idx < 8192; idx += 256){
      float f = outF[(idx>>6)*68 + (idx&63)];
      O[idx] = f;
      float lf = leaky(f); s += lf; ss = fmaf(lf, lf, ss);
    }
    red[tid] = s; red[256 + tid] = ss;
    __syncthreads();
    if (tid < 64){
      atomicAdd(&g_stats[128 + tid],
                red[tid] + red[tid+64] + red[tid+128] + red[tid+192]);
      atomicAdd(&g_stats[192 + tid],
                red[256+tid] + red[320+tid] + red[384+tid] + red[448+tid]);
    }
  }
}

// ====== fused: attn-epilogue (with INLINE dwconv) + LN-FF (R12 verbatim) ======
#define SM_F_BYTES 90112
template<int STATS>
__global__ __launch_bounds__(256)
void k_fused12(const float* __restrict__ wff, const float* __restrict__ bproj,
               const float* __restrict__ lng, const float* __restrict__ lnb,
               const float* __restrict__ wpos){
  extern __shared__ unsigned char smraw[];
  float* xs = (float*)smraw;
  __nv_bfloat16* Ah = (__nv_bfloat16*)(smraw + 34816);
  __nv_bfloat16* Al = (__nv_bfloat16*)(smraw + 53248);
  __nv_bfloat16* Bh = (__nv_bfloat16*)(smraw + 71680);
  __nv_bfloat16* Bl = (__nv_bfloat16*)(smraw + 80896);
  float* outF = (float*)(smraw + 34816);
  __shared__ float s_bias[64], s_g[64], s_bb[64];
  __shared__ float red[512];
  __shared__ float wp[576];

  int tid = threadIdx.x, wid = tid >> 5;
  int b = blockIdx.x, n0 = blockIdx.y * 128;
  int y = blockIdx.y;
  int m0 = wid * 16;

  if (tid < 64){ s_bias[tid] = bproj[tid]; s_g[tid] = lng[tid]; s_bb[tid] = lnb[tid]; }
  for (int i = tid; i < 576; i += 256) wp[i] = wpos[i];

  const float4* IN4 = (const float4*)(g_V + ((size_t)b*TOK + n0)*CH_);
  for (int i = tid; i < 2048; i += 256){
    float4 v = IN4[i];
    int t = i >> 4, c = (i & 15) * 4;
    __nv_bfloat16 h, l;
    split_bf16(v.x, h, l); Ah[t*72+c  ] = h; Al[t*72+c  ] = l;
    split_bf16(v.y, h, l); Ah[t*72+c+1] = h; Al[t*72+c+1] = l;
    split_bf16(v.z, h, l); Ah[t*72+c+2] = h; Al[t*72+c+2] = l;
    split_bf16(v.w, h, l); Ah[t*72+c+3] = h; Al[t*72+c+3] = l;
  }
  const float4* WE4 = (const float4*)(g_Weff + b*4096);
  for (int i = tid; i < 1024; i += 256){
    float4 v = WE4[i];
    int k = i >> 4, n = (i & 15) * 4;
    __nv_bfloat16 h, l;
    split_bf16(v.x, h, l); Bh[k*72+n  ] = h; Bl[k*72+n  ] = l;
    split_bf16(v.y, h, l); Bh[k*72+n+1] = h; Bl[k*72+n+1] = l;
    split_bf16(v.z, h, l); Bh[k*72+n+2] = h; Bl[k*72+n+2] = l;
    split_bf16(v.w, h, l); Bh[k*72+n+3] = h; Bl[k*72+n+3] = l;
  }
  __syncthreads();

  // MMA1: V @ Weff -> xs
  {
    wmma::fragment<wmma::accumulator,16,16,16,float> acc[4];
#pragma unroll
    for (int j = 0; j < 4; j++) wmma::fill_fragment(acc[j], 0.f);
#pragma unroll
    for (int k = 0; k < 4; k++){
      wmma::fragment<wmma::matrix_a,16,16,16,__nv_bfloat16,wmma::row_major> ah, al;
      wmma::load_matrix_sync(ah, Ah + m0*72 + k*16, 72);
      wmma::load_matrix_sync(al, Al + m0*72 + k*16, 72);
#pragma unroll
      for (int j = 0; j < 4; j++){
        wmma::fragment<wmma::matrix_b,16,16,16,__nv_bfloat16,wmma::row_major> bh, bl;
        wmma::load_matrix_sync(bh, Bh + (k*16)*72 + j*16, 72);
        wmma::load_matrix_sync(bl, Bl + (k*16)*72 + j*16, 72);
        wmma::mma_sync(acc[j], ah, bh, acc[j]);
        wmma::mma_sync(acc[j], ah, bl, acc[j]);
        wmma::mma_sync(acc[j], al, bh, acc[j]);
      }
    }
    __syncthreads();
#pragma unroll
    for (int j = 0; j < 4; j++)
      wmma::store_matrix_sync(xs + m0*68 + j*16, acc[j], 68, wmma::mem_row_major);
  }
  __syncthreads();

  // Y = XT + (xs + bias) * dwconv(V) -> xs ; restage wff -> Bh/Bl
  {
    const float4* XT4 = (const float4*)(g_XT + ((size_t)b*TOK + n0)*CH_);
    const float* Vb = g_V + (size_t)b*TOK*CH_;
    for (int i = tid; i < 2048; i += 256){
      int t = i >> 4, c = (i & 15) * 4;
      float4 xv = XT4[i];
      float p0 = 0.f, p1 = 0.f, p2 = 0.f, p3 = 0.f;
#pragma unroll
      for (int ky = 0; ky < 3; ky++){
        int yy = y + ky - 1; if (yy < 0 || yy > 127) continue;
#pragma unroll
        for (int kx = 0; kx < 3; kx++){
          int xx = t + kx - 1; if (xx < 0 || xx > 127) continue;
          float4 v = *(const float4*)&Vb[((size_t)(yy*128 + xx))*64 + c];
          int wi = ky*3 + kx;
          p0 = fmaf(v.x, wp[(c  )*9 + wi], p0);
          p1 = fmaf(v.y, wp[(c+1)*9 + wi], p1);
          p2 = fmaf(v.z, wp[(c+2)*9 + wi], p2);
          p3 = fmaf(v.w, wp[(c+3)*9 + wi], p3);
        }
      }
      float* o = &xs[t*68 + c];
      o[0] = xv.x + (o[0] + s_bias[c  ]) * p0;
      o[1] = xv.y + (o[1] + s_bias[c+1]) * p1;
      o[2] = xv.z + (o[2] + s_bias[c+2]) * p2;
      o[3] = xv.w + (o[3] + s_bias[c+3]) * p3;
    }
    const float4* WF4 = (const float4*)wff;
    for (int i = tid; i < 1024; i += 256){
      float4 v = WF4[i];
      int k = i >> 4, n = (i & 15) * 4;
      __nv_bfloat16 h, l;
      split_bf16(v.x, h, l); Bh[k*72+n  ] = h; Bl[k*72+n  ] = l;
      split_bf16(v.y, h, l); Bh[k*72+n+1] = h; Bl[k*72+n+1] = l;
      split_bf16(v.z, h, l); Bh[k*72+n+2] = h; Bl[k*72+n+2] = l;
      split_bf16(v.w, h, l); Bh[k*72+n+3] = h; Bl[k*72+n+3] = l;
    }
  }
  __syncthreads();

  // LN(Y) -> Ah/Al
  if (tid < 128){
    const float* row = &xs[tid*68];
    float s = 0.f, ss = 0.f;
#pragma unroll
    for (int c = 0; c < 64; c++){ float xv = row[c]; s += xv; ss = fmaf(xv, xv, ss); }
    float mean = s * (1.f/64.f);
    float rstd = rsqrtf(ss*(1.f/64.f) - mean*mean + 1e-5f);
#pragma unroll
    for (int c = 0; c < 64; c++){
      float f = (row[c] - mean) * rstd * s_g[c] + s_bb[c];
      __nv_bfloat16 h, l; split_bf16(f, h, l);
      Ah[tid*72 + c] = h; Al[tid*72 + c] = l;
    }
  }
  __syncthreads();

  // MMA2: LN(Y) @ wff -> outF
  {
    wmma::fragment<wmma::accumulator,16,16,16,float> acc[4];
#pragma unroll
    for (int j = 0; j < 4; j++) wmma::fill_fragment(acc[j], 0.f);
#pragma unroll
    for (int k = 0; k < 4; k++){
      wmma::fragment<wmma::matrix_a,16,16,16,__nv_bfloat16,wmma::row_major> ah, al;
      wmma::load_matrix_sync(ah, Ah + m0*72 + k*16, 72);
      wmma::load_matrix_sync(al, Al + m0*72 + k*16, 72);
#pragma unroll
      for (int j = 0; j < 4; j++){
        wmma::fragment<wmma::matrix_b,16,16,16,__nv_bfloat16,wmma::row_major> bh, bl;
        wmma::load_matrix_sync(bh, Bh + (k*16)*72 + j*16, 72);
        wmma::load_matrix_sync(bl, Bl + (k*16)*72 + j*16, 72);
        wmma::mma_sync(acc[j], ah, bh, acc[j]);
        wmma::mma_sync(acc[j], ah, bl, acc[j]);
        wmma::mma_sync(acc[j], al, bh, acc[j]);
      }
    }
    __syncthreads();
#pragma unroll
    for (int j = 0; j < 4; j++)
      wmma::store_matrix_sync(outF + m0*68 + j*16, acc[j], 68, wmma::mem_row_major);
  }
  __syncthreads();

  float s = 0.f, ss = 0.f;
  if (STATS){
    float* XT = g_XT + ((size_t)b*TOK + n0)*CH_;
    for (int idx = tid; idx < 8192; idx += 256){
      float nv = xs[(idx>>6)*68 + (idx&63)] + outF[(idx>>6)*68 + (idx&63)];
      XT[idx] = nv;
      float lf = leaky(nv); s += lf; ss = fmaf(lf, lf, ss);
    }
    red[tid] = s; red[256 + tid] = ss;
    __syncthreads();
    if (tid < 64){
      atomicAdd(&g_stats[tid],
                red[tid] + red[tid+64] + red[tid+128] + red[tid+192]);
      atomicAdd(&g_stats[64 + tid],
                red[256+tid] + red[320+tid] + red[384+tid] + red[448+tid]);
    }
  } else {
    float4* XT4 = (float4*)(g_XT + ((size_t)b*TOK + n0)*CH_);
    for (int i = tid; i < 2048; i += 256){
      int t = i >> 4, c = (i & 15) * 4;
      float4 o;
      o.x = xs[t*68+c  ] + outF[t*68+c  ];
      o.y = xs[t*68+c+1] + outF[t*68+c+1];
      o.z = xs[t*68+c+2] + outF[t*68+c+2];
      o.w = xs[t*68+c+3] + outF[t*68+c+3];
      XT4[i] = o;
    }
  }
}

// ------- per-batch attention stats + fold into Weff -------
__global__ void k_attn_weff(const float* __restrict__ wq, const float* __restrict__ wk,
                            const float* __restrict__ wproj){
  extern __shared__ float sm[];
  float* Cs  = sm;
  float* wqs = sm + 4096;
  float* wks = sm + 8192;
  float* wps = sm + 12288;
  float* T1  = sm + 16384;
  float* T2  = sm + 20480;
  __shared__ float attn_s[512];
  __shared__ float qq[64], kk[64];
  int b = blockIdx.x;
  for (int i = threadIdx.x; i < 4096; i += 256){
    Cs[i]  = g_C[b*4096 + i];
    wqs[i] = wq[i]; wks[i] = wk[i]; wps[i] = wproj[i];
  }
  __syncthreads();
  for (int i = threadIdx.x; i < 4096; i += 256){
    int r = i >> 6, e = i & 63; float s1 = 0.f, s2 = 0.f;
    for (int c = 0; c < 64; c++){
      float cv = Cs[r*64 + c];
      s1 = fmaf(cv, wqs[c*64 + e], s1);
      s2 = fmaf(cv, wks[c*64 + e], s2);
    }
    T1[i] = s1; T2[i] = s2;
  }
  __syncthreads();
  if (threadIdx.x < 64){
    int e = threadIdx.x; float s1 = 0.f, s2 = 0.f;
    for (int c = 0; c < 64; c++){
      s1 = fmaf(wqs[c*64 + e], T1[c*64 + e], s1);
      s2 = fmaf(wks[c*64 + e], T2[c*64 + e], s2);
    }
    qq[e] = s1; kk[e] = s2;
  }
  __syncthreads();
  if (threadIdx.x < 64){
    int h = threadIdx.x >> 3, dd = threadIdx.x & 7;
    float nk = fmaxf(sqrtf(kk[h*8 + dd]), 1e-12f);
    float lo[8]; float mx = -3.4e38f;
#pragma unroll
    for (int e = 0; e < 8; e++){
      float gg = 0.f;
      for (int c = 0; c < 64; c++)
        gg = fmaf(wks[c*64 + h*8 + dd], T1[c*64 + h*8 + e], gg);
      float nq = fmaxf(sqrtf(qq[h*8 + e]), 1e-12f);
      lo[e] = gg / (nk * nq);
      mx = fmaxf(mx, lo[e]);
    }
    float sum = 0.f;
#pragma unroll
    for (int e = 0; e < 8; e++){ lo[e] = expf(lo[e] - mx); sum += lo[e]; }
    float inv = 1.f / sum;
#pragma unroll
    for (int e = 0; e < 8; e++) attn_s[(h*8 + dd)*8 + e] = lo[e] * inv;
  }
  __syncthreads();
  for (int i = threadIdx.x; i < 4096; i += 256){
    int cin = i >> 6, oc = i & 63;
    int h = cin >> 3, e = cin & 7;
    float s = 0.f;
#pragma unroll
    for (int dd = 0; dd < 8; dd++)
      s = fmaf(attn_s[(h*8 + dd)*8 + e], wps[(h*8 + dd)*64 + oc], s);
    g_Weff[b*4096 + i] = s;
  }
}

// ---- BN2 + residual + NCHW out + pooled sums ----
__global__ void k_bn2_add_pool(const float* __restrict__ x_orig, float* __restrict__ out,
                               const float* __restrict__ g2, const float* __restrict__ b2){
  int b = blockIdx.x, n0 = blockIdx.y * 64;
  __shared__ float s[64*65];
  __shared__ float scale[64], shift[64];
  if (threadIdx.x < 64){
    int c = threadIdx.x;
    float m   = g_stats[128 + c] * (1.f/CNT);
    float var = g_stats[192 + c] * (1.f/CNT) - m*m;
    float sc  = g2[c] * rsqrtf(var + 1e-4f);
    scale[c] = sc; shift[c] = b2[c] - m*sc;
  }
  const float* R = g_V + ((size_t)b*TOK + n0)*CH_;
  for (int idx = threadIdx.x; idx < 4096; idx += 256){
    int t = idx >> 6, c = idx & 63;
    s[t*65 + c] = R[idx];
  }
  __syncthreads();
  int y = n0 >> 7, x0 = n0 & 127;
  int iblk = y >> 4, jbase = x0 >> 4;
  const float* xb = x_orig + (size_t)b*CH_*TOK;
  float* ob = out + (size_t)b*CH_*TOK;
  for (int idx = threadIdx.x; idx < 4096; idx += 256){
    int c = idx >> 6, j = idx & 63;
    float f = leaky(s[j*65 + c]) * scale[c] + shift[c];
    size_t off = (size_t)c*TOK + n0 + j;
    float sval = f + xb[off];
    ob[off] = sval;
    float r = sval;
    r += __shfl_down_sync(0xffffffffu, r, 8, 16);
    r += __shfl_down_sync(0xffffffffu, r, 4, 16);
    r += __shfl_down_sync(0xffffffffu, r, 2, 16);
    r += __shfl_down_sync(0xffffffffu, r, 1, 16);
    if ((threadIdx.x & 15) == 0)
      atomicAdd(&g_pooled[(b*64 + c)*64 + iblk*8 + jbase + (j >> 4)], r);
  }
}

__global__ void k_minmax(){
  float mn = 3.4e38f, mx = -3.4e38f;
  for (int i = threadIdx.x; i < B_*4096; i += 1024){
    float v = g_pooled[i] * (1.f/256.f);
    mn = fminf(mn, v); mx = fmaxf(mx, v);
  }
#pragma unroll
  for (int o = 16; o > 0; o >>= 1){
    mn = fminf(mn, __shfl_xor_sync(0xffffffffu, mn, o));
    mx = fmaxf(mx, __shfl_xor_sync(0xffffffffu, mx, o));
  }
  __shared__ float smn[32], smx[32];
  if ((threadIdx.x & 31) == 0){ smn[threadIdx.x >> 5] = mn; smx[threadIdx.x >> 5] = mx; }
  __syncthreads();
  if (threadIdx.x < 32){
    mn = smn[threadIdx.x]; mx = smx[threadIdx.x];
#pragma unroll
    for (int o = 16; o > 0; o >>= 1){
      mn = fminf(mn, __shfl_xor_sync(0xffffffffu, mn, o));
      mx = fmaxf(mx, __shfl_xor_sync(0xffffffffu, mx, o));
    }
    if (threadIdx.x == 0){ g_minmax[0] = mn; g_minmax[1] = mx; }
  }
}

__global__ void k_gate(const float* __restrict__ w1, const float* __restrict__ w2){
  int b = blockIdx.x;
  __shared__ float y[4096];
  __shared__ float S[64];
  __shared__ float g0[64];
  __shared__ float hid[4];
  float mn = g_minmax[0];
  float inv = 1.f / (g_minmax[1] - mn);
  for (int i = threadIdx.x; i < 4096; i += 64)
    y[i] = (g_pooled[b*4096 + i] * (1.f/256.f) - mn) * inv;
  __syncthreads();
  {
    int i = threadIdx.x; float s = 0.f;
    for (int c = 0; c < 64; c++) s += y[c*64 + i];
    S[i] = s;
  }
  __syncthreads();
  {
    int c = threadIdx.x; float s = 0.f, sm2 = 0.f;
    for (int i = 0; i < 64; i++){
      s = fmaf(y[c*64 + i], S[i], s);
      sm2 += g_pooled[b*4096 + c*64 + i];
    }
    g0[c] = (s * (1.f/64.f)) * (sm2 * (1.f/16384.f));
  }
  __syncthreads();
  if (threadIdx.x < 4){
    int j = threadIdx.x; float h = 0.f;
    for (int c = 0; c < 64; c++) h = fmaf(g0[c], w1[c*4 + j], h);
    hid[j] = leaky(h);
  }
  __syncthreads();
  {
    int c = threadIdx.x; float o = 0.f;
#pragma unroll
    for (int j = 0; j < 4; j++) o = fmaf(hid[j], w2[j*64 + c], o);
    g_gate[b*64 + c] = 1.f / (1.f + expf(-o));
  }
}

__global__ void k_scale(float* __restrict__ out){
  size_t i = (size_t)blockIdx.x * 256 + threadIdx.x;
  out[i] *= g_gate[i >> 14];
}

// ================================ launch ========================================
extern "C" void kernel_launch(void* const* d_in, const int* in_sizes, int n_in,
                              void* d_out, int out_size){
  const float* x     = (const float*)d_in[0];
  const float* wq    = (const float*)d_in[1];
  const float* wk    = (const float*)d_in[2];
  const float* wv    = (const float*)d_in[3];
  const float* wproj = (const float*)d_in[4];
  const float* bproj = (const float*)d_in[5];
  const float* wpos  = (const float*)d_in[6];
  const float* ln_g  = (const float*)d_in[7];
  const float* ln_b  = (const float*)d_in[8];
  const float* wff   = (const float*)d_in[9];
  const float* bn1_g = (const float*)d_in[10];
  const float* bn1_b = (const float*)d_in[11];
  const float* wd    = (const float*)d_in[12];
  const float* bn2_g = (const float*)d_in[13];
  const float* bn2_b = (const float*)d_in[14];
  const float* sw1   = (const float*)d_in[15];
  const float* sw2   = (const float*)d_in[16];
  float* out = (float*)d_out;

  cudaFuncSetAttribute(k_gemm<0>,    cudaFuncAttributeMaxDynamicSharedMemorySize, SM_GEMM_BYTES);
  cudaFuncSetAttribute(k_gemm<3>,    cudaFuncAttributeMaxDynamicSharedMemorySize, SM_GEMM_BYTES);
  cudaFuncSetAttribute(k_fused12<0>, cudaFuncAttributeMaxDynamicSharedMemorySize, SM_F_BYTES);
  cudaFuncSetAttribute(k_fused12<1>, cudaFuncAttributeMaxDynamicSharedMemorySize, SM_F_BYTES);
  cudaFuncSetAttribute(k_attn_weff,  cudaFuncAttributeMaxDynamicSharedMemorySize, 100*1024);

  void *pC = nullptr, *pStats = nullptr, *pPooled = nullptr;
  cudaGetSymbolAddress(&pC, g_C);
  cudaGetSymbolAddress(&pStats, g_stats);
  cudaGetSymbolAddress(&pPooled, g_pooled);

  cudaMemsetAsync(pStats, 0, 256*sizeof(float));
  k_transpose_in<<<dim3(16, 256), 256>>>(x);
  for (int l = 0; l < 2; l++){
    cudaMemsetAsync(pC, 0, 16*4096*sizeof(float));
    k_gemm<0><<<dim3(16, 128), 256, SM_GEMM_BYTES>>>(wv + l*4096, nullptr, nullptr);
    k_attn_weff<<<16, 256, 6*4096*sizeof(float)>>>(wq + l*4096, wk + l*4096, wproj + l*4096);
    if (l == 0)
      k_fused12<0><<<dim3(16, 128), 256, SM_F_BYTES>>>(wff + l*4096, bproj + l*64, ln_g + l*64, ln_b + l*64, wpos + l*576);
    else
      k_fused12<1><<<dim3(16, 128), 256, SM_F_BYTES>>>(wff + l*4096, bproj + l*64, ln_g + l*64, ln_b + l*64, wpos + l*576);
  }
  k_gemm<3><<<dim3(16, 128), 256, SM_GEMM_BYTES>>>(wd, bn1_g, bn1_b);
  cudaMemsetAsync(pPooled, 0, 16*4096*sizeof(float));
  k_bn2_add_pool<<<dim3(16, 256), 256>>>(x, out, bn2_g, bn2_b);
  k_minmax<<<1, 1024>>>();
  k_gate<<<16, 64>>>(sw1, sw2);
  k_scale<<<65536, 256>>>(out);
}

// round 14
// speedup vs baseline: 3.0432x; 1.1004x over previous
#include <cuda_runtime.h>
#include <cuda_bf16.h>
#include <mma.h>
#include <cstdint>

using namespace nvcuda;

#define B_   16
#define CH_  64
#define TOK  16384
#define CNT  (16.0f*16384.0f)

__device__ float g_XT[B_*TOK*CH_];
__device__ float g_V [B_*TOK*CH_];
__device__ float g_C    [B_*64*64];
__device__ float g_Weff [B_*64*64];
__device__ float g_stats[256];
__device__ float g_pooled[B_*64*64];
__device__ float g_minmax[2];
__device__ float g_gate[B_*64];

__device__ __forceinline__ float leaky(float x){ return x >= 0.f ? x : 0.2f*x; }
__device__ __forceinline__ void split_bf16(float f, __nv_bfloat16& h, __nv_bfloat16& l){
  h = __float2bfloat16_rn(f);
  l = __float2bfloat16_rn(f - __bfloat162float(h));
}

// ---------------- NCHW -> BHWC transpose ----------------
__global__ void k_transpose_in(const float* __restrict__ x){
  int b = blockIdx.x, n0 = blockIdx.y * 64;
  __shared__ float s[64*65];
  const float* xb = x + (size_t)b*CH_*TOK;
  for (int idx = threadIdx.x; idx < 4096; idx += 256){
    int c = idx >> 6, j = idx & 63;
    s[c*65 + j] = xb[(size_t)c*TOK + n0 + j];
  }
  __syncthreads();
  float* xt = g_XT + ((size_t)b*TOK + n0)*CH_;
  for (int idx = threadIdx.x; idx < 4096; idx += 256){
    int j = idx >> 6, c = idx & 63;
    xt[j*CH_ + c] = s[c*65 + j];
  }
}

// =============== wmma GEMM — slim smem (R13 verbatim) ===============
// MODE 0: V = XT @ W (direct global store) + FUSED gram partial
// MODE 3: V = BN1(leaky(XT)) @ W ; leaky stats -> g_stats[128..255]
#define SM_GEMM_BYTES 55296
template<int MODE>
__global__ __launch_bounds__(256)
void k_gemm(const float* __restrict__ W, const float* __restrict__ aux0,
            const float* __restrict__ aux1){
  extern __shared__ unsigned char smraw[];
  __nv_bfloat16* Ah = (__nv_bfloat16*)smraw;
  __nv_bfloat16* Al = (__nv_bfloat16*)(smraw + 18432);
  __nv_bfloat16* Bh = (__nv_bfloat16*)(smraw + 36864);
  __nv_bfloat16* Bl = (__nv_bfloat16*)(smraw + 46080);
  float* outF = (float*)smraw;
  __shared__ float s_a[64], s_b[64];
  __shared__ float red[512];

  int tid = threadIdx.x, wid = tid >> 5;
  int b = blockIdx.x, n0 = blockIdx.y * 128;
  int m0 = wid * 16;

  if (MODE == 3 && tid < 64){
    float m   = g_stats[tid]      * (1.f/CNT);
    float var = g_stats[64 + tid] * (1.f/CNT) - m*m;
    float sc  = aux0[tid] * rsqrtf(var + 1e-4f);
    s_a[tid] = sc; s_b[tid] = aux1[tid] - m*sc;
  }

  const float4* W4 = (const float4*)W;
  for (int i = tid; i < 1024; i += 256){
    float4 v = W4[i];
    int k = i >> 4, n = (i & 15) * 4;
    __nv_bfloat16 h, l;
    split_bf16(v.x, h, l); Bh[k*72+n  ] = h; Bl[k*72+n  ] = l;
    split_bf16(v.y, h, l); Bh[k*72+n+1] = h; Bl[k*72+n+1] = l;
    split_bf16(v.z, h, l); Bh[k*72+n+2] = h; Bl[k*72+n+2] = l;
    split_bf16(v.w, h, l); Bh[k*72+n+3] = h; Bl[k*72+n+3] = l;
  }
  __syncthreads();

  const float4* IN4 = (const float4*)(g_XT + ((size_t)b*TOK + n0)*CH_);
  for (int i = tid; i < 2048; i += 256){
    float4 v = IN4[i];
    int t = i >> 4, c = (i & 15) * 4;
    float f0 = v.x, f1 = v.y, f2 = v.z, f3 = v.w;
    if (MODE == 3){
      f0 = leaky(f0)*s_a[c  ] + s_b[c  ];
      f1 = leaky(f1)*s_a[c+1] + s_b[c+1];
      f2 = leaky(f2)*s_a[c+2] + s_b[c+2];
      f3 = leaky(f3)*s_a[c+3] + s_b[c+3];
    }
    __nv_bfloat16 h, l;
    split_bf16(f0, h, l); Ah[t*72+c  ] = h; Al[t*72+c  ] = l;
    split_bf16(f1, h, l); Ah[t*72+c+1] = h; Al[t*72+c+1] = l;
    split_bf16(f2, h, l); Ah[t*72+c+2] = h; Al[t*72+c+2] = l;
    split_bf16(f3, h, l); Ah[t*72+c+3] = h; Al[t*72+c+3] = l;
  }
  __syncthreads();

  {
    wmma::fragment<wmma::accumulator,16,16,16,float> acc[4];
#pragma unroll
    for (int j = 0; j < 4; j++) wmma::fill_fragment(acc[j], 0.f);
#pragma unroll
    for (int k = 0; k < 4; k++){
      wmma::fragment<wmma::matrix_a,16,16,16,__nv_bfloat16,wmma::row_major> ah, al;
      wmma::load_matrix_sync(ah, Ah + m0*72 + k*16, 72);
      wmma::load_matrix_sync(al, Al + m0*72 + k*16, 72);
#pragma unroll
      for (int j = 0; j < 4; j++){
        wmma::fragment<wmma::matrix_b,16,16,16,__nv_bfloat16,wmma::row_major> bh, bl;
        wmma::load_matrix_sync(bh, Bh + (k*16)*72 + j*16, 72);
        wmma::load_matrix_sync(bl, Bl + (k*16)*72 + j*16, 72);
        wmma::mma_sync(acc[j], ah, bh, acc[j]);
        wmma::mma_sync(acc[j], ah, bl, acc[j]);
        wmma::mma_sync(acc[j], al, bh, acc[j]);
      }
    }
    if (MODE == 0){
      float* O = g_V + ((size_t)b*TOK + n0 + m0)*CH_;
#pragma unroll
      for (int j = 0; j < 4; j++)
        wmma::store_matrix_sync(O + j*16, acc[j], 64, wmma::mem_row_major);
    } else {
      __syncthreads();
#pragma unroll
      for (int j = 0; j < 4; j++)
        wmma::store_matrix_sync(outF + m0*68 + j*16, acc[j], 68, wmma::mem_row_major);
    }
  }

  if (MODE == 0){
    int mwid = wid & 3, nh = wid >> 2;
    int mg = mwid * 16, j0 = nh * 2;
    wmma::fragment<wmma::accumulator,16,16,16,float> acc2[2];
#pragma unroll
    for (int j = 0; j < 2; j++) wmma::fill_fragment(acc2[j], 0.f);
#pragma unroll
    for (int k = 0; k < 8; k++){
      wmma::fragment<wmma::matrix_a,16,16,16,__nv_bfloat16,wmma::col_major> ah, al;
      wmma::load_matrix_sync(ah, Ah + (k*16)*72 + mg, 72);
      wmma::load_matrix_sync(al, Al + (k*16)*72 + mg, 72);
#pragma unroll
      for (int jj = 0; jj < 2; jj++){
        int j = j0 + jj;
        wmma::fragment<wmma::matrix_b,16,16,16,__nv_bfloat16,wmma::row_major> bh, bl;
        wmma::load_matrix_sync(bh, Ah + (k*16)*72 + j*16, 72);
        wmma::load_matrix_sync(bl, Al + (k*16)*72 + j*16, 72);
        wmma::mma_sync(acc2[jj], ah, bh, acc2[jj]);
        wmma::mma_sync(acc2[jj], ah, bl, acc2[jj]);
        wmma::mma_sync(acc2[jj], al, bh, acc2[jj]);
      }
    }
    __syncthreads();
#pragma unroll
    for (int jj = 0; jj < 2; jj++)
      wmma::store_matrix_sync(outF + mg*68 + (j0+jj)*16, acc2[jj], 68, wmma::mem_row_major);
    __syncthreads();
    for (int idx = tid; idx < 4096; idx += 256)
      atomicAdd(&g_C[b*4096 + idx], outF[(idx>>6)*68 + (idx&63)]);
  } else {
    __syncthreads();
    float* O = g_V + ((size_t)b*TOK + n0)*CH_;
    float s = 0.f, ss = 0.f;
    for (int idx = tid; idx < 8192; idx += 256){
      float f = outF[(idx>>6)*68 + (idx&63)];
      O[idx] = f;
      float lf = leaky(f); s += lf; ss = fmaf(lf, lf, ss);
    }
    red[tid] = s; red[256 + tid] = ss;
    __syncthreads();
    if (tid < 64){
      atomicAdd(&g_stats[128 + tid],
                red[tid] + red[tid+64] + red[tid+128] + red[tid+192]);
      atomicAdd(&g_stats[192 + tid],
                red[256+tid] + red[320+tid] + red[384+tid] + red[448+tid]);
    }
  }
}

// ====== fused: attn-epilogue (sliding-window dwconv) + LN-FF ======
#define SM_F_BYTES 90112
template<int STATS>
__global__ __launch_bounds__(256,2)
void k_fused12(const float* __restrict__ wff, const float* __restrict__ bproj,
               const float* __restrict__ lng, const float* __restrict__ lnb,
               const float* __restrict__ wpos){
  extern __shared__ unsigned char smraw[];
  float* xs = (float*)smraw;
  __nv_bfloat16* Ah = (__nv_bfloat16*)(smraw + 34816);
  __nv_bfloat16* Al = (__nv_bfloat16*)(smraw + 53248);
  __nv_bfloat16* Bh = (__nv_bfloat16*)(smraw + 71680);
  __nv_bfloat16* Bl = (__nv_bfloat16*)(smraw + 80896);
  float* outF = (float*)(smraw + 34816);
  __shared__ float s_bias[64], s_g[64], s_bb[64];
  __shared__ float red[512];
  __shared__ float wp[576];

  int tid = threadIdx.x, wid = tid >> 5;
  int b = blockIdx.x, n0 = blockIdx.y * 128;
  int y = blockIdx.y;
  int m0 = wid * 16;

  if (tid < 64){ s_bias[tid] = bproj[tid]; s_g[tid] = lng[tid]; s_bb[tid] = lnb[tid]; }
  for (int i = tid; i < 576; i += 256) wp[i] = wpos[i];

  const float4* IN4 = (const float4*)(g_V + ((size_t)b*TOK + n0)*CH_);
  for (int i = tid; i < 2048; i += 256){
    float4 v = IN4[i];
    int t = i >> 4, c = (i & 15) * 4;
    __nv_bfloat16 h, l;
    split_bf16(v.x, h, l); Ah[t*72+c  ] = h; Al[t*72+c  ] = l;
    split_bf16(v.y, h, l); Ah[t*72+c+1] = h; Al[t*72+c+1] = l;
    split_bf16(v.z, h, l); Ah[t*72+c+2] = h; Al[t*72+c+2] = l;
    split_bf16(v.w, h, l); Ah[t*72+c+3] = h; Al[t*72+c+3] = l;
  }
  const float4* WE4 = (const float4*)(g_Weff + b*4096);
  for (int i = tid; i < 1024; i += 256){
    float4 v = WE4[i];
    int k = i >> 4, n = (i & 15) * 4;
    __nv_bfloat16 h, l;
    split_bf16(v.x, h, l); Bh[k*72+n  ] = h; Bl[k*72+n  ] = l;
    split_bf16(v.y, h, l); Bh[k*72+n+1] = h; Bl[k*72+n+1] = l;
    split_bf16(v.z, h, l); Bh[k*72+n+2] = h; Bl[k*72+n+2] = l;
    split_bf16(v.w, h, l); Bh[k*72+n+3] = h; Bl[k*72+n+3] = l;
  }
  __syncthreads();

  // MMA1: V @ Weff -> xs
  {
    wmma::fragment<wmma::accumulator,16,16,16,float> acc[4];
#pragma unroll
    for (int j = 0; j < 4; j++) wmma::fill_fragment(acc[j], 0.f);
#pragma unroll
    for (int k = 0; k < 4; k++){
      wmma::fragment<wmma::matrix_a,16,16,16,__nv_bfloat16,wmma::row_major> ah, al;
      wmma::load_matrix_sync(ah, Ah + m0*72 + k*16, 72);
      wmma::load_matrix_sync(al, Al + m0*72 + k*16, 72);
#pragma unroll
      for (int j = 0; j < 4; j++){
        wmma::fragment<wmma::matrix_b,16,16,16,__nv_bfloat16,wmma::row_major> bh, bl;
        wmma::load_matrix_sync(bh, Bh + (k*16)*72 + j*16, 72);
        wmma::load_matrix_sync(bl, Bl + (k*16)*72 + j*16, 72);
        wmma::mma_sync(acc[j], ah, bh, acc[j]);
        wmma::mma_sync(acc[j], ah, bl, acc[j]);
        wmma::mma_sync(acc[j], al, bh, acc[j]);
      }
    }
    __syncthreads();
#pragma unroll
    for (int j = 0; j < 4; j++)
      wmma::store_matrix_sync(xs + m0*68 + j*16, acc[j], 68, wmma::mem_row_major);
  }
  __syncthreads();

  // Y = XT + (xs + bias) * dwconv(V) -> xs ; restage wff -> Bh/Bl
  // sliding-window dwconv: thread handles 8 consecutive t for one c4
  {
    const float4* XT4 = (const float4*)(g_XT + ((size_t)b*TOK + n0)*CH_);
    const float* Vb = g_V + (size_t)b*TOK*CH_;
    int c4 = tid & 15, c = c4 * 4;
    int tseg = (tid >> 4) * 8;
    bool hasM = (y > 0), hasP = (y < 127);
    const float* rowM = Vb + ((size_t)(y - 1) * 128) * 64;
    const float* rowC = Vb + ((size_t)(y    ) * 128) * 64;
    const float* rowP = Vb + ((size_t)(y + 1) * 128) * 64;
    float4 vL[3], vC[3], vR[3];
    float4 z4 = make_float4(0.f, 0.f, 0.f, 0.f);
    // load column xx into dst[0..2] (rows y-1, y, y+1)
    #define LOADCOL(xx, dst) do { \
      int _x = (xx); \
      if (_x < 0 || _x > 127){ (dst)[0] = z4; (dst)[1] = z4; (dst)[2] = z4; } \
      else { \
        (dst)[0] = hasM ? *(const float4*)&rowM[_x*64 + c] : z4; \
        (dst)[1] = *(const float4*)&rowC[_x*64 + c]; \
        (dst)[2] = hasP ? *(const float4*)&rowP[_x*64 + c] : z4; \
      } \
    } while(0)
    LOADCOL(tseg - 1, vL);
    LOADCOL(tseg,     vC);
#pragma unroll
    for (int tt = 0; tt < 8; tt++){
      int t = tseg + tt;
      LOADCOL(t + 1, vR);
      float p0 = 0.f, p1 = 0.f, p2 = 0.f, p3 = 0.f;
#pragma unroll
      for (int r = 0; r < 3; r++){
        // tap order kx = 0 (vL), 1 (vC), 2 (vR) matches original (ky=r, kx)
        p0 = fmaf(vL[r].x, wp[(c  )*9 + r*3 + 0], p0);
        p1 = fmaf(vL[r].y, wp[(c+1)*9 + r*3 + 0], p1);
        p2 = fmaf(vL[r].z, wp[(c+2)*9 + r*3 + 0], p2);
        p3 = fmaf(vL[r].w, wp[(c+3)*9 + r*3 + 0], p3);
        p0 = fmaf(vC[r].x, wp[(c  )*9 + r*3 + 1], p0);
        p1 = fmaf(vC[r].y, wp[(c+1)*9 + r*3 + 1], p1);
        p2 = fmaf(vC[r].z, wp[(c+2)*9 + r*3 + 1], p2);
        p3 = fmaf(vC[r].w, wp[(c+3)*9 + r*3 + 1], p3);
        p0 = fmaf(vR[r].x, wp[(c  )*9 + r*3 + 2], p0);
        p1 = fmaf(vR[r].y, wp[(c+1)*9 + r*3 + 2], p1);
        p2 = fmaf(vR[r].z, wp[(c+2)*9 + r*3 + 2], p2);
        p3 = fmaf(vR[r].w, wp[(c+3)*9 + r*3 + 2], p3);
      }
      float4 xv = XT4[t*16 + c4];
      float* o = &xs[t*68 + c];
      o[0] = xv.x + (o[0] + s_bias[c  ]) * p0;
      o[1] = xv.y + (o[1] + s_bias[c+1]) * p1;
      o[2] = xv.z + (o[2] + s_bias[c+2]) * p2;
      o[3] = xv.w + (o[3] + s_bias[c+3]) * p3;
#pragma unroll
      for (int r = 0; r < 3; r++){ vL[r] = vC[r]; vC[r] = vR[r]; }
    }
    #undef LOADCOL
    const float4* WF4 = (const float4*)wff;
    for (int i = tid; i < 1024; i += 256){
      float4 v = WF4[i];
      int k = i >> 4, n = (i & 15) * 4;
      __nv_bfloat16 h, l;
      split_bf16(v.x, h, l); Bh[k*72+n  ] = h; Bl[k*72+n  ] = l;
      split_bf16(v.y, h, l); Bh[k*72+n+1] = h; Bl[k*72+n+1] = l;
      split_bf16(v.z, h, l); Bh[k*72+n+2] = h; Bl[k*72+n+2] = l;
      split_bf16(v.w, h, l); Bh[k*72+n+3] = h; Bl[k*72+n+3] = l;
    }
  }
  __syncthreads();

  // LN(Y) -> Ah/Al
  if (tid < 128){
    const float* row = &xs[tid*68];
    float s = 0.f, ss = 0.f;
#pragma unroll
    for (int c = 0; c < 64; c++){ float xv = row[c]; s += xv; ss = fmaf(xv, xv, ss); }
    float mean = s * (1.f/64.f);
    float rstd = rsqrtf(ss*(1.f/64.f) - mean*mean + 1e-5f);
#pragma unroll
    for (int c = 0; c < 64; c++){
      float f = (row[c] - mean) * rstd * s_g[c] + s_bb[c];
      __nv_bfloat16 h, l; split_bf16(f, h, l);
      Ah[tid*72 + c] = h; Al[tid*72 + c] = l;
    }
  }
  __syncthreads();

  // MMA2: LN(Y) @ wff -> outF
  {
    wmma::fragment<wmma::accumulator,16,16,16,float> acc[4];
#pragma unroll
    for (int j = 0; j < 4; j++) wmma::fill_fragment(acc[j], 0.f);
#pragma unroll
    for (int k = 0; k < 4; k++){
      wmma::fragment<wmma::matrix_a,16,16,16,__nv_bfloat16,wmma::row_major> ah, al;
      wmma::load_matrix_sync(ah, Ah + m0*72 + k*16, 72);
      wmma::load_matrix_sync(al, Al + m0*72 + k*16, 72);
#pragma unroll
      for (int j = 0; j < 4; j++){
        wmma::fragment<wmma::matrix_b,16,16,16,__nv_bfloat16,wmma::row_major> bh, bl;
        wmma::load_matrix_sync(bh, Bh + (k*16)*72 + j*16, 72);
        wmma::load_matrix_sync(bl, Bl + (k*16)*72 + j*16, 72);
        wmma::mma_sync(acc[j], ah, bh, acc[j]);
        wmma::mma_sync(acc[j], ah, bl, acc[j]);
        wmma::mma_sync(acc[j], al, bh, acc[j]);
      }
    }
    __syncthreads();
#pragma unroll
    for (int j = 0; j < 4; j++)
      wmma::store_matrix_sync(outF + m0*68 + j*16, acc[j], 68, wmma::mem_row_major);
  }
  __syncthreads();

  float s = 0.f, ss = 0.f;
  if (STATS){
    float* XT = g_XT + ((size_t)b*TOK + n0)*CH_;
    for (int idx = tid; idx < 8192; idx += 256){
      float nv = xs[(idx>>6)*68 + (idx&63)] + outF[(idx>>6)*68 + (idx&63)];
      XT[idx] = nv;
      float lf = leaky(nv); s += lf; ss = fmaf(lf, lf, ss);
    }
    red[tid] = s; red[256 + tid] = ss;
    __syncthreads();
    if (tid < 64){
      atomicAdd(&g_stats[tid],
                red[tid] + red[tid+64] + red[tid+128] + red[tid+192]);
      atomicAdd(&g_stats[64 + tid],
                red[256+tid] + red[320+tid] + red[384+tid] + red[448+tid]);
    }
  } else {
    float4* XT4 = (float4*)(g_XT + ((size_t)b*TOK + n0)*CH_);
    for (int i = tid; i < 2048; i += 256){
      int t = i >> 4, c = (i & 15) * 4;
      float4 o;
      o.x = xs[t*68+c  ] + outF[t*68+c  ];
      o.y = xs[t*68+c+1] + outF[t*68+c+1];
      o.z = xs[t*68+c+2] + outF[t*68+c+2];
      o.w = xs[t*68+c+3] + outF[t*68+c+3];
      XT4[i] = o;
    }
  }
}

// ------- per-batch attention stats + fold into Weff -------
__global__ void k_attn_weff(const float* __restrict__ wq, const float* __restrict__ wk,
                            const float* __restrict__ wproj){
  extern __shared__ float sm[];
  float* Cs  = sm;
  float* wqs = sm + 4096;
  float* wks = sm + 8192;
  float* wps = sm + 12288;
  float* T1  = sm + 16384;
  float* T2  = sm + 20480;
  __shared__ float attn_s[512];
  __shared__ float qq[64], kk[64];
  int b = blockIdx.x;
  for (int i = threadIdx.x; i < 4096; i += 256){
    Cs[i]  = g_C[b*4096 + i];
    wqs[i] = wq[i]; wks[i] = wk[i]; wps[i] = wproj[i];
  }
  __syncthreads();
  for (int i = threadIdx.x; i < 4096; i += 256){
    int r = i >> 6, e = i & 63; float s1 = 0.f, s2 = 0.f;
    for (int c = 0; c < 64; c++){
      float cv = Cs[r*64 + c];
      s1 = fmaf(cv, wqs[c*64 + e], s1);
      s2 = fmaf(cv, wks[c*64 + e], s2);
    }
    T1[i] = s1; T2[i] = s2;
  }
  __syncthreads();
  if (threadIdx.x < 64){
    int e = threadIdx.x; float s1 = 0.f, s2 = 0.f;
    for (int c = 0; c < 64; c++){
      s1 = fmaf(wqs[c*64 + e], T1[c*64 + e], s1);
      s2 = fmaf(wks[c*64 + e], T2[c*64 + e], s2);
    }
    qq[e] = s1; kk[e] = s2;
  }
  __syncthreads();
  if (threadIdx.x < 64){
    int h = threadIdx.x >> 3, dd = threadIdx.x & 7;
    float nk = fmaxf(sqrtf(kk[h*8 + dd]), 1e-12f);
    float lo[8]; float mx = -3.4e38f;
#pragma unroll
    for (int e = 0; e < 8; e++){
      float gg = 0.f;
      for (int c = 0; c < 64; c++)
        gg = fmaf(wks[c*64 + h*8 + dd], T1[c*64 + h*8 + e], gg);
      float nq = fmaxf(sqrtf(qq[h*8 + e]), 1e-12f);
      lo[e] = gg / (nk * nq);
      mx = fmaxf(mx, lo[e]);
    }
    float sum = 0.f;
#pragma unroll
    for (int e = 0; e < 8; e++){ lo[e] = expf(lo[e] - mx); sum += lo[e]; }
    float inv = 1.f / sum;
#pragma unroll
    for (int e = 0; e < 8; e++) attn_s[(h*8 + dd)*8 + e] = lo[e] * inv;
  }
  __syncthreads();
  for (int i = threadIdx.x; i < 4096; i += 256){
    int cin = i >> 6, oc = i & 63;
    int h = cin >> 3, e = cin & 7;
    float s = 0.f;
#pragma unroll
    for (int dd = 0; dd < 8; dd++)
      s = fmaf(attn_s[(h*8 + dd)*8 + e], wps[(h*8 + dd)*64 + oc], s);
    g_Weff[b*4096 + i] = s;
  }
}

// ---- BN2 + residual + NCHW out + pooled sums ----
__global__ void k_bn2_add_pool(const float* __restrict__ x_orig, float* __restrict__ out,
                               const float* __restrict__ g2, const float* __restrict__ b2){
  int b = blockIdx.x, n0 = blockIdx.y * 64;
  __shared__ float s[64*65];
  __shared__ float scale[64], shift[64];
  if (threadIdx.x < 64){
    int c = threadIdx.x;
    float m   = g_stats[128 + c] * (1.f/CNT);
    float var = g_stats[192 + c] * (1.f/CNT) - m*m;
    float sc  = g2[c] * rsqrtf(var + 1e-4f);
    scale[c] = sc; shift[c] = b2[c] - m*sc;
  }
  const float* R = g_V + ((size_t)b*TOK + n0)*CH_;
  for (int idx = threadIdx.x; idx < 4096; idx += 256){
    int t = idx >> 6, c = idx & 63;
    s[t*65 + c] = R[idx];
  }
  __syncthreads();
  int y = n0 >> 7, x0 = n0 & 127;
  int iblk = y >> 4, jbase = x0 >> 4;
  const float* xb = x_orig + (size_t)b*CH_*TOK;
  float* ob = out + (size_t)b*CH_*TOK;
  for (int idx = threadIdx.x; idx < 4096; idx += 256){
    int c = idx >> 6, j = idx & 63;
    float f = leaky(s[j*65 + c]) * scale[c] + shift[c];
    size_t off = (size_t)c*TOK + n0 + j;
    float sval = f + xb[off];
    ob[off] = sval;
    float r = sval;
    r += __shfl_down_sync(0xffffffffu, r, 8, 16);
    r += __shfl_down_sync(0xffffffffu, r, 4, 16);
    r += __shfl_down_sync(0xffffffffu, r, 2, 16);
    r += __shfl_down_sync(0xffffffffu, r, 1, 16);
    if ((threadIdx.x & 15) == 0)
      atomicAdd(&g_pooled[(b*64 + c)*64 + iblk*8 + jbase + (j >> 4)], r);
  }
}

__global__ void k_minmax(){
  float mn = 3.4e38f, mx = -3.4e38f;
  for (int i = threadIdx.x; i < B_*4096; i += 1024){
    float v = g_pooled[i] * (1.f/256.f);
    mn = fminf(mn, v); mx = fmaxf(mx, v);
  }
#pragma unroll
  for (int o = 16; o > 0; o >>= 1){
    mn = fminf(mn, __shfl_xor_sync(0xffffffffu, mn, o));
    mx = fmaxf(mx, __shfl_xor_sync(0xffffffffu, mx, o));
  }
  __shared__ float smn[32], smx[32];
  if ((threadIdx.x & 31) == 0){ smn[threadIdx.x >> 5] = mn; smx[threadIdx.x >> 5] = mx; }
  __syncthreads();
  if (threadIdx.x < 32){
    mn = smn[threadIdx.x]; mx = smx[threadIdx.x];
#pragma unroll
    for (int o = 16; o > 0; o >>= 1){
      mn = fminf(mn, __shfl_xor_sync(0xffffffffu, mn, o));
      mx = fmaxf(mx, __shfl_xor_sync(0xffffffffu, mx, o));
    }
    if (threadIdx.x == 0){ g_minmax[0] = mn; g_minmax[1] = mx; }
  }
}

__global__ void k_gate(const float* __restrict__ w1, const float* __restrict__ w2){
  int b = blockIdx.x;
  __shared__ float y[4096];
  __shared__ float S[64];
  __shared__ float g0[64];
  __shared__ float hid[4];
  float mn = g_minmax[0];
  float inv = 1.f / (g_minmax[1] - mn);
  for (int i = threadIdx.x; i < 4096; i += 64)
    y[i] = (g_pooled[b*4096 + i] * (1.f/256.f) - mn) * inv;
  __syncthreads();
  {
    int i = threadIdx.x; float s = 0.f;
    for (int c = 0; c < 64; c++) s += y[c*64 + i];
    S[i] = s;
  }
  __syncthreads();
  {
    int c = threadIdx.x; float s = 0.f, sm2 = 0.f;
    for (int i = 0; i < 64; i++){
      s = fmaf(y[c*64 + i], S[i], s);
      sm2 += g_pooled[b*4096 + c*64 + i];
    }
    g0[c] = (s * (1.f/64.f)) * (sm2 * (1.f/16384.f));
  }
  __syncthreads();
  if (threadIdx.x < 4){
    int j = threadIdx.x; float h = 0.f;
    for (int c = 0; c < 64; c++) h = fmaf(g0[c], w1[c*4 + j], h);
    hid[j] = leaky(h);
  }
  __syncthreads();
  {
    int c = threadIdx.x; float o = 0.f;
#pragma unroll
    for (int j = 0; j < 4; j++) o = fmaf(hid[j], w2[j*64 + c], o);
    g_gate[b*64 + c] = 1.f / (1.f + expf(-o));
  }
}

__global__ void k_scale(float* __restrict__ out){
  size_t i = (size_t)blockIdx.x * 256 + threadIdx.x;
  out[i] *= g_gate[i >> 14];
}

// ================================ launch ========================================
extern "C" void kernel_launch(void* const* d_in, const int* in_sizes, int n_in,
                              void* d_out, int out_size){
  const float* x     = (const float*)d_in[0];
  const float* wq    = (const float*)d_in[1];
  const float* wk    = (const float*)d_in[2];
  const float* wv    = (const float*)d_in[3];
  const float* wproj = (const float*)d_in[4];
  const float* bproj = (const float*)d_in[5];
  const float* wpos  = (const float*)d_in[6];
  const float* ln_g  = (const float*)d_in[7];
  const float* ln_b  = (const float*)d_in[8];
  const float* wff   = (const float*)d_in[9];
  const float* bn1_g = (const float*)d_in[10];
  const float* bn1_b = (const float*)d_in[11];
  const float* wd    = (const float*)d_in[12];
  const float* bn2_g = (const float*)d_in[13];
  const float* bn2_b = (const float*)d_in[14];
  const float* sw1   = (const float*)d_in[15];
  const float* sw2   = (const float*)d_in[16];
  float* out = (float*)d_out;

  cudaFuncSetAttribute(k_gemm<0>,    cudaFuncAttributeMaxDynamicSharedMemorySize, SM_GEMM_BYTES);
  cudaFuncSetAttribute(k_gemm<3>,    cudaFuncAttributeMaxDynamicSharedMemorySize, SM_GEMM_BYTES);
  cudaFuncSetAttribute(k_fused12<0>, cudaFuncAttributeMaxDynamicSharedMemorySize, SM_F_BYTES);
  cudaFuncSetAttribute(k_fused12<1>, cudaFuncAttributeMaxDynamicSharedMemorySize, SM_F_BYTES);
  cudaFuncSetAttribute(k_attn_weff,  cudaFuncAttributeMaxDynamicSharedMemorySize, 100*1024);

  void *pC = nullptr, *pStats = nullptr, *pPooled = nullptr;
  cudaGetSymbolAddress(&pC, g_C);
  cudaGetSymbolAddress(&pStats, g_stats);
  cudaGetSymbolAddress(&pPooled, g_pooled);

  cudaMemsetAsync(pStats, 0, 256*sizeof(float));
  k_transpose_in<<<dim3(16, 256), 256>>>(x);
  for (int l = 0; l < 2; l++){
    cudaMemsetAsync(pC, 0, 16*4096*sizeof(float));
    k_gemm<0><<<dim3(16, 128), 256, SM_GEMM_BYTES>>>(wv + l*4096, nullptr, nullptr);
    k_attn_weff<<<16, 256, 6*4096*sizeof(float)>>>(wq + l*4096, wk + l*4096, wproj + l*4096);
    if (l == 0)
      k_fused12<0><<<dim3(16, 128), 256, SM_F_BYTES>>>(wff + l*4096, bproj + l*64, ln_g + l*64, ln_b + l*64, wpos + l*576);
    else
      k_fused12<1><<<dim3(16, 128), 256, SM_F_BYTES>>>(wff + l*4096, bproj + l*64, ln_g + l*64, ln_b + l*64, wpos + l*576);
  }
  k_gemm<3><<<dim3(16, 128), 256, SM_GEMM_BYTES>>>(wd, bn1_g, bn1_b);
  cudaMemsetAsync(pPooled, 0, 16*4096*sizeof(float));
  k_bn2_add_pool<<<dim3(16, 256), 256>>>(x, out, bn2_g, bn2_b);
  k_minmax<<<1, 1024>>>();
  k_gate<<<16, 64>>>(sw1, sw2);
  k_scale<<<65536, 256>>>(out);
}